// round 9
// baseline (speedup 1.0000x reference)
#include <cuda_runtime.h>
#include <cuda_fp16.h>
#include <math.h>
#include <stdint.h>

#define Bn 4096
#define Fdim 512
#define Hdim 1024
#define Nn 64
#define Dd 64
#define FLAT 4096
#define Ccls 1000
#define CAP 64
#define Pp 8

// ================= scratch (device globals) =================
__device__ float g_h1[Bn * Hdim];
__device__ float g_b2a[FLAT];
__device__ float g_sim[Bn * CAP];
__device__ float g_s1[Bn * Hdim];
__device__ float g_bhm[1024];
__device__ float g_adj[Nn * Nn];
__device__ float g_cf[Nn * Dd];
// fp16 hi/lo operand buffers
__device__ __half g_xh[Bn * Fdim],    g_xl[Bn * Fdim];
__device__ __half g_W1h[Hdim * Fdim], g_W1l[Hdim * Fdim];
__device__ __half g_h1h[Bn * Hdim],   g_h1l[Bn * Hdim];
__device__ __half g_W2h[FLAT * Hdim], g_W2l[FLAT * Hdim];
__device__ __half g_xah[(size_t)Bn * FLAT], g_xal[(size_t)Bn * FLAT];
__device__ __half g_xfh[(size_t)Bn * FLAT], g_xfl[(size_t)Bn * FLAT];
__device__ __half g_Whmh[1024 * FLAT], g_Whml[1024 * FLAT];
__device__ __half g_Ws1h[Hdim * FLAT], g_Ws1l[Hdim * FLAT];
__device__ __half g_memh[128 * FLAT], g_meml[128 * FLAT];
__device__ __half g_Wch[Nn * 256 * 64], g_Wcl[Nn * 256 * 64];  // cell weights [n][r][i], r: Wi'|Wf'|Wc|Wo'

__device__ __forceinline__ float sigmoidf_(float x) { return 1.f / (1.f + expf(-x)); }

__device__ __forceinline__ uint32_t pack2h(__half a, __half b) {
    return (uint32_t)__half_as_ushort(a) | ((uint32_t)__half_as_ushort(b) << 16);
}
__device__ __forceinline__ void cvt4(float4 v, uint2& hi, uint2& lo) {
    __half h0 = __float2half_rn(v.x), h1 = __float2half_rn(v.y);
    __half h2 = __float2half_rn(v.z), h3 = __float2half_rn(v.w);
    __half l0 = __float2half_rn(v.x - __half2float(h0));
    __half l1 = __float2half_rn(v.y - __half2float(h1));
    __half l2 = __float2half_rn(v.z - __half2float(h2));
    __half l3 = __float2half_rn(v.w - __half2float(h3));
    hi.x = pack2h(h0, h1); hi.y = pack2h(h2, h3);
    lo.x = pack2h(l0, l1); lo.y = pack2h(l2, l3);
}
__device__ __forceinline__ void cvt2(float a, float b, uint32_t& hi, uint32_t& lo) {
    __half h0 = __float2half_rn(a), h1 = __float2half_rn(b);
    __half l0 = __float2half_rn(a - __half2float(h0));
    __half l1 = __float2half_rn(b - __half2float(h1));
    hi = pack2h(h0, h1); lo = pack2h(l0, l1);
}

// ================= mma / cp.async / ldmatrix primitives =================
__device__ __forceinline__ uint32_t smem_u32(const void* p) {
    uint32_t a;
    asm("{ .reg .u64 t; cvta.to.shared.u64 t, %1; cvt.u32.u64 %0, t; }" : "=r"(a) : "l"(p));
    return a;
}
__device__ __forceinline__ void cp16(uint32_t s, const void* g) {
    asm volatile("cp.async.cg.shared.global [%0], [%1], 16;" :: "r"(s), "l"(g));
}
#define CP_COMMIT() asm volatile("cp.async.commit_group;")
#define CP_WAIT1() asm volatile("cp.async.wait_group 1;")

__device__ __forceinline__ void mma16816(float* d, const uint32_t* a, uint32_t b0, uint32_t b1) {
    asm volatile(
        "mma.sync.aligned.m16n8k16.row.col.f32.f16.f16.f32 "
        "{%0,%1,%2,%3}, {%4,%5,%6,%7}, {%8,%9}, {%0,%1,%2,%3};"
        : "+f"(d[0]), "+f"(d[1]), "+f"(d[2]), "+f"(d[3])
        : "r"(a[0]), "r"(a[1]), "r"(a[2]), "r"(a[3]), "r"(b0), "r"(b1));
}
__device__ __forceinline__ void ldsm_x4(uint32_t& r0, uint32_t& r1, uint32_t& r2, uint32_t& r3,
                                        uint32_t addr) {
    asm volatile("ldmatrix.sync.aligned.m8n8.x4.shared.b16 {%0,%1,%2,%3}, [%4];"
                 : "=r"(r0), "=r"(r1), "=r"(r2), "=r"(r3) : "r"(addr));
}

// ================= conversion kernels =================
__global__ void cvt_hilo(const float* __restrict__ src, uint2* __restrict__ hi,
                         uint2* __restrict__ lo, int n4) {
    int i = blockIdx.x * 256 + threadIdx.x;
    if (i < n4) {
        float4 v = ((const float4*)src)[i];
        uint2 h, l; cvt4(v, h, l);
        hi[i] = h; lo[i] = l;
    }
}
__global__ void cvt_mem_pad(const float* __restrict__ mem) {
    int i = blockIdx.x * 256 + threadIdx.x;
    if (i >= 128 * FLAT / 4) return;
    int row = i >> 10;
    uint2 h = make_uint2(0u, 0u), l = make_uint2(0u, 0u);
    if (row < CAP) {
        float4 v = ((const float4*)mem)[i];
        cvt4(v, h, l);
    }
    ((uint2*)g_memh)[i] = h; ((uint2*)g_meml)[i] = l;
}

// ================= prep kernels =================
__global__ void prep_adj(const float* __restrict__ edge_w, const float* __restrict__ mask) {
    __shared__ float t[64 * 64];
    int r = threadIdx.x;
    float sum = 0.f;
    for (int c = 0; c < 64; c++) {
        float v = sigmoidf_(edge_w[r * 64 + c] * 1.5f) * mask[r * 64 + c];
        t[r * 64 + c] = v; sum += v;
    }
    float inv = 1.f / fmaxf(sum, 1e-6f);
    for (int c = 0; c < 64; c++) g_adj[r * 64 + c] = t[r * 64 + c] * inv;
}

// fold adjacency into W2, emit fp16 hi/lo
__global__ void __launch_bounds__(256) fold_w2(const float* __restrict__ W2) {
    int kt = blockIdx.x;
    int d  = blockIdx.y;
    __shared__ float tile[64][128];
    __shared__ float adjT[64 * 64];
    int tid = threadIdx.x;
    for (int i = tid; i < 4096; i += 256) {
        int m = i >> 6, n = i & 63;
        adjT[i] = g_adj[n * 64 + m];
    }
    for (int i = tid; i < 64 * 32; i += 256) {
        int m = i >> 5, c4 = (i & 31) << 2;
        *(float4*)&tile[m][c4] = *(const float4*)(W2 + (size_t)(m * 64 + d) * Hdim + kt * 128 + c4);
    }
    __syncthreads();
    int n = tid & 63;
    int kq = tid >> 6;
    float4 acc[8];
#pragma unroll
    for (int q = 0; q < 8; q++) acc[q] = make_float4(0.f, 0.f, 0.f, 0.f);
    for (int m = 0; m < 64; m++) {
        float s = adjT[m * 64 + n];
        const float4* trow = (const float4*)&tile[m][kq * 32];
#pragma unroll
        for (int q = 0; q < 8; q++) {
            float4 t4 = trow[q];
            acc[q].x += s * t4.x; acc[q].y += s * t4.y;
            acc[q].z += s * t4.z; acc[q].w += s * t4.w;
        }
    }
    size_t off4 = ((size_t)(n * 64 + d) * Hdim + kt * 128 + kq * 32) >> 2;
#pragma unroll
    for (int q = 0; q < 8; q++) {
        uint2 h, l; cvt4(acc[q], h, l);
        ((uint2*)g_W2h)[off4 + q] = h;
        ((uint2*)g_W2l)[off4 + q] = l;
    }
}
__global__ void prep_b2a(const float* __restrict__ b2) {
    int nd = blockIdx.x * 64 + threadIdx.x;
    int n = nd >> 6, d = nd & 63;
    float acc = 0.f;
    for (int m = 0; m < 64; m++) acc += g_adj[n * 64 + m] * b2[m * 64 + d];
    g_b2a[nd] = acc;
}

// per-node: sigma, cf, and fp16 hi/lo cell weights in [o][i] B-layout, type-major rows:
// rows 0-63: Wi'[o][i]=Wi[i][o]; 64-127: Wf'[o][i]=Wf[i][o]; 128-191: Wc[o][i]; 192-255: Wo'[o][i]=Wo[i][o]
__global__ void prep_node(const float* __restrict__ Wslow, const float* __restrict__ u,
                          const float* __restrict__ Wfast, const float* __restrict__ Wf,
                          const float* __restrict__ bf, const float* __restrict__ hprev,
                          const float* __restrict__ Wi, const float* __restrict__ Wo) {
    int n = blockIdx.x;
    int t = threadIdx.x;
    __shared__ float us[64], v[64], red[64];
    const float* Ws = Wslow + (size_t)n * 4096;
    us[t] = u[n * 64 + t];
    __syncthreads();
    float acc = 0.f;
    for (int o = 0; o < 64; o++) acc += Ws[o * 64 + t] * us[o];
    v[t] = acc;
    __syncthreads();
    float wv = 0.f;
    for (int i = 0; i < 64; i++) wv += Ws[t * 64 + i] * v[i];
    red[t] = us[t] * wv;
    __syncthreads();
    for (int off = 32; off > 0; off >>= 1) {
        if (t < off) red[t] += red[t + off];
        __syncthreads();
    }
    float inv = 1.f / (red[0] + 1e-8f);
    const float* Wfa = Wfast + (size_t)n * 4096;
    const float* Wip = Wi + (size_t)n * 4096;
    const float* Wfp = Wf + (size_t)n * 8192;
    const float* Wop = Wo + (size_t)n * 4096;
    __half* wh = g_Wch + (size_t)n * 16384;
    __half* wl = g_Wcl + (size_t)n * 16384;
    for (int idx = t; idx < 16384; idx += 64) {
        int r = idx >> 6, i = idx & 63;
        float val;
        if (r < 64)       val = Wip[i * 64 + r];
        else if (r < 128) val = Wfp[i * 64 + (r - 64)];
        else if (r < 192) val = Ws[(r - 128) * 64 + i] * inv + Wfa[(r - 128) * 64 + i];
        else              val = Wop[i * 64 + (r - 192)];
        __half h = __float2half_rn(val);
        wh[idx] = h;
        wl[idx] = __float2half_rn(val - __half2float(h));
    }
    float c = bf[n * 64 + t];
    const float* Wf2 = Wfp + 4096;
    for (int i = 0; i < 64; i++) c += hprev[n * 64 + i] * Wf2[i * 64 + t];
    g_cf[n * 64 + t] = c;
}

__global__ void prep_whm_bf(const float* __restrict__ Wh) {
    int i = blockIdx.x * 256 + threadIdx.x;
    if (i >= (1024 * FLAT) / 4) return;
    int row = i >> 10;
    uint2 h, l;
    if (row < Ccls) {
        const size_t CF4 = (size_t)Ccls * FLAT / 4;
        const float4* W4 = (const float4*)Wh;
        float4 a = W4[i], b = W4[i + CF4], c = W4[i + 2 * CF4];
        float4 m = make_float4((a.x + b.x + c.x) * (1.f / 3.f), (a.y + b.y + c.y) * (1.f / 3.f),
                               (a.z + b.z + c.z) * (1.f / 3.f), (a.w + b.w + c.w) * (1.f / 3.f));
        cvt4(m, h, l);
    } else {
        h = make_uint2(0u, 0u); l = make_uint2(0u, 0u);
    }
    ((uint2*)g_Whmh)[i] = h; ((uint2*)g_Whml)[i] = l;
}
__global__ void prep_bhm(const float* __restrict__ bh) {
    int i = blockIdx.x * 256 + threadIdx.x;
    if (i < 1024) g_bhm[i] = (i < Ccls) ? (bh[i] + bh[i + Ccls] + bh[i + 2 * Ccls]) * (1.f / 3.f) : 0.f;
}
__global__ void zero_sim() {
    g_sim[blockIdx.x * 256 + threadIdx.x] = 0.f;
}

// ================= split-fp16 HMMA GEMM =================
#define TSTRIDE 40
#define ROWB (TSTRIDE * 2)
#define TILE_B (128 * ROWB)
#define STAGE_B (4 * TILE_B)
#define GSMEM_TOTAL (2 * STAGE_B)

template <int NI, bool THREE>
__global__ void __launch_bounds__(256, 2) gemm_mma(
    const __half* __restrict__ Ahi, const __half* __restrict__ Alo,
    const __half* __restrict__ Bhi, const __half* __restrict__ Blo,
    const float* __restrict__ bias, float* __restrict__ C,
    uint32_t* __restrict__ Ch, uint32_t* __restrict__ Cl,
    int K, int lda, int Nstore, int act, int atomicOut) {
    extern __shared__ char smem[];
    const int tid = threadIdx.x;
    const int wid = tid >> 5;
    const int lane = tid & 31;
    const int grp = lane >> 2;
    const int qp = lane & 3;
    const int wm = (wid >> 2) * 64;
    const int wn = (wid & 3) * (NI * 8);
    const int bm = blockIdx.y * 128;
    const int bn = blockIdx.x * 128;
    const int kbase = blockIdx.z * K;
    const uint32_t sb = smem_u32(smem);

    const int row = tid >> 2;
    const int c16 = tid & 3;

    const int aRowL = wm + (lane & 7) + ((lane >> 3) & 1) * 8;
    const int aKL = (lane >> 4) * 8;
    const int bRowL = wn + (lane & 7) + (lane >> 4) * 8;
    const int bKL = ((lane >> 3) & 1) * 8;

    float acc[4][NI][4];
#pragma unroll
    for (int mi = 0; mi < 4; mi++)
#pragma unroll
        for (int ni = 0; ni < NI; ni++)
#pragma unroll
            for (int j = 0; j < 4; j++) acc[mi][ni][j] = 0.f;

    const int nc = K >> 5;

    auto issue = [&](int c, int s) {
        const uint32_t ss = sb + s * STAGE_B;
        const int k0 = c << 5;
#pragma unroll
        for (int t = 0; t < 2; t++) {
            const int r = row + t * 64;
            const uint32_t so = (uint32_t)r * ROWB + c16 * 16;
            const size_t gAoff = ((size_t)(bm + r) * lda + kbase + k0) * 2 + c16 * 16;
            const size_t gBoff = ((size_t)(bn + r) * lda + kbase + k0) * 2 + c16 * 16;
            cp16(ss + 0 * TILE_B + so, (const char*)Ahi + gAoff);
            if (THREE) cp16(ss + 1 * TILE_B + so, (const char*)Alo + gAoff);
            cp16(ss + 2 * TILE_B + so, (const char*)Bhi + gBoff);
            cp16(ss + 3 * TILE_B + so, (const char*)Blo + gBoff);
        }
    };

    issue(0, 0); CP_COMMIT();
    if (nc > 1) issue(1, 1);
    CP_COMMIT();

    for (int c = 0; c < nc; c++) {
        const int s = c & 1;
        CP_WAIT1();
        __syncthreads();
        const uint32_t st = sb + s * STAGE_B;
#pragma unroll
        for (int ks = 0; ks < 2; ks++) {
            const int k0 = ks * 16;
            uint32_t ah[4][4], al[4][4];
#pragma unroll
            for (int mi = 0; mi < 4; mi++) {
                const uint32_t ad = st + (uint32_t)(aRowL + mi * 16) * ROWB + (k0 + aKL) * 2;
                ldsm_x4(ah[mi][0], ah[mi][1], ah[mi][2], ah[mi][3], ad);
                if (THREE) ldsm_x4(al[mi][0], al[mi][1], al[mi][2], al[mi][3], ad + TILE_B);
            }
            uint32_t bh[NI][2], bl[NI][2];
#pragma unroll
            for (int p = 0; p < NI / 2; p++) {
                const uint32_t bd = st + 2 * TILE_B + (uint32_t)(bRowL + p * 16) * ROWB + (k0 + bKL) * 2;
                uint32_t r0, r1, r2, r3;
                ldsm_x4(r0, r1, r2, r3, bd);
                bh[2 * p][0] = r0; bh[2 * p][1] = r1; bh[2 * p + 1][0] = r2; bh[2 * p + 1][1] = r3;
                ldsm_x4(r0, r1, r2, r3, bd + TILE_B);
                bl[2 * p][0] = r0; bl[2 * p][1] = r1; bl[2 * p + 1][0] = r2; bl[2 * p + 1][1] = r3;
            }
#pragma unroll
            for (int ni = 0; ni < NI; ni++) {
#pragma unroll
                for (int mi = 0; mi < 4; mi++) {
                    mma16816(acc[mi][ni], ah[mi], bh[ni][0], bh[ni][1]);
                    mma16816(acc[mi][ni], ah[mi], bl[ni][0], bl[ni][1]);
                    if (THREE) mma16816(acc[mi][ni], al[mi], bh[ni][0], bh[ni][1]);
                }
            }
        }
        __syncthreads();
        if (c + 2 < nc) issue(c + 2, s);
        CP_COMMIT();
    }

    // epilogue
#pragma unroll
    for (int mi = 0; mi < 4; mi++) {
#pragma unroll
        for (int ni = 0; ni < NI; ni++) {
            const int r0 = bm + wm + mi * 16 + grp;
            const int col = bn + wn + ni * 8 + qp * 2;
            float* a4 = acc[mi][ni];
            if (atomicOut) {
                if (col < Nstore) {
                    atomicAdd(&C[(size_t)r0 * Nstore + col], a4[0]);
                    atomicAdd(&C[(size_t)(r0 + 8) * Nstore + col], a4[2]);
                    if (col + 1 < Nstore) {
                        atomicAdd(&C[(size_t)r0 * Nstore + col + 1], a4[1]);
                        atomicAdd(&C[(size_t)(r0 + 8) * Nstore + col + 1], a4[3]);
                    }
                }
            } else if (Ch) {
                // fp16 hi/lo pair output (col even, full tiles only)
                float bb0 = bias ? bias[col] : 0.f;
                float bb1 = bias ? bias[col + 1] : 0.f;
                uint32_t h, l;
                cvt2(a4[0] + bb0, a4[1] + bb1, h, l);
                size_t i0 = ((size_t)r0 * Nstore + col) >> 1;
                Ch[i0] = h; Cl[i0] = l;
                cvt2(a4[2] + bb0, a4[3] + bb1, h, l);
                size_t i1 = ((size_t)(r0 + 8) * Nstore + col) >> 1;
                Ch[i1] = h; Cl[i1] = l;
            } else if (col + 1 < Nstore) {
                float2 v0, v1;
                float bb0 = bias ? bias[col] : 0.f;
                float bb1 = bias ? bias[col + 1] : 0.f;
                v0.x = a4[0] + bb0; v0.y = a4[1] + bb1;
                v1.x = a4[2] + bb0; v1.y = a4[3] + bb1;
                if (act == 1) {
                    v0.x = fmaxf(v0.x, 0.f); v0.y = fmaxf(v0.y, 0.f);
                    v1.x = fmaxf(v1.x, 0.f); v1.y = fmaxf(v1.y, 0.f);
                }
                *(float2*)(C + (size_t)r0 * Nstore + col) = v0;
                *(float2*)(C + (size_t)(r0 + 8) * Nstore + col) = v1;
            } else if (col < Nstore) {
                float bb0 = bias ? bias[col] : 0.f;
                float v0 = a4[0] + bb0, v1 = a4[2] + bb0;
                if (act == 1) { v0 = fmaxf(v0, 0.f); v1 = fmaxf(v1, 0.f); }
                C[(size_t)r0 * Nstore + col] = v0;
                C[(size_t)(r0 + 8) * Nstore + col] = v1;
            }
        }
    }
}

// ================= LayerNorm(H=1024) + GELU -> fp16 hi/lo =================
__global__ void __launch_bounds__(256) ln_gelu_kernel(const float* __restrict__ h,
                                                      const float* __restrict__ g,
                                                      const float* __restrict__ beta,
                                                      uint2* __restrict__ hi,
                                                      uint2* __restrict__ lo) {
    int row = blockIdx.x;
    const float* hr = h + (size_t)row * Hdim;
    int tid = threadIdx.x;
    float4 v = *(const float4*)(hr + tid * 4);
    float s = v.x + v.y + v.z + v.w;
    float ss = v.x * v.x + v.y * v.y + v.z * v.z + v.w * v.w;
    __shared__ float rs[8], rss[8];
    for (int o = 16; o > 0; o >>= 1) {
        s += __shfl_down_sync(0xffffffffu, s, o);
        ss += __shfl_down_sync(0xffffffffu, ss, o);
    }
    if ((tid & 31) == 0) { rs[tid >> 5] = s; rss[tid >> 5] = ss; }
    __syncthreads();
    if (tid < 32) {
        float a = tid < 8 ? rs[tid] : 0.f;
        float b = tid < 8 ? rss[tid] : 0.f;
        for (int o = 4; o > 0; o >>= 1) {
            a += __shfl_down_sync(0xffffffffu, a, o);
            b += __shfl_down_sync(0xffffffffu, b, o);
        }
        if (tid == 0) { rs[0] = a; rss[0] = b; }
    }
    __syncthreads();
    float mu = rs[0] * (1.f / Hdim);
    float var = rss[0] * (1.f / Hdim) - mu * mu;
    float inv = rsqrtf(var + 1e-5f);
    float4 gg = *(const float4*)(g + tid * 4);
    float4 bb = *(const float4*)(beta + tid * 4);
    float y;
    y = (v.x - mu) * inv * gg.x + bb.x; v.x = 0.5f * y * (1.f + erff(y * 0.70710678118654752f));
    y = (v.y - mu) * inv * gg.y + bb.y; v.y = 0.5f * y * (1.f + erff(y * 0.70710678118654752f));
    y = (v.z - mu) * inv * gg.z + bb.z; v.z = 0.5f * y * (1.f + erff(y * 0.70710678118654752f));
    y = (v.w - mu) * inv * gg.w + bb.w; v.w = 0.5f * y * (1.f + erff(y * 0.70710678118654752f));
    uint2 hh, ll; cvt4(v, hh, ll);
    hi[(size_t)row * 256 + tid] = hh;
    lo[(size_t)row * 256 + tid] = ll;
}

// ================= HMMA cell kernel =================
// grid (node=64, batchTile=64), 256 threads; 3-pass fp16 (residual ~2^-22)
// smem: WHh/WHl [256][72] | XSh/XSl [64][72] | PA [64][192] fp32 | vecs [7*64]
#define CW_STRIDE 72
#define CELL2_SMEM ((256 * 72 * 2 + 64 * 72 * 2) * 2 + (64 * 192 + 7 * 64) * 4)

__global__ void __launch_bounds__(256, 1) cell_hmma(const float* __restrict__ bi_g,
                                                    const float* __restrict__ bslow_g,
                                                    const float* __restrict__ bo_g,
                                                    const float* __restrict__ hprev_g,
                                                    const float* __restrict__ gln_g,
                                                    const float* __restrict__ bln_g,
                                                    float* __restrict__ xflat_out,
                                                    uint32_t* __restrict__ xfh,
                                                    uint32_t* __restrict__ xfl) {
    extern __shared__ char cs[];
    __half* WHh = (__half*)cs;
    __half* WHl = WHh + 256 * CW_STRIDE;
    __half* XSh = WHl + 256 * CW_STRIDE;
    __half* XSl = XSh + 64 * CW_STRIDE;
    float* PA   = (float*)(XSl + 64 * CW_STRIDE);
    float* vecs = PA + 64 * 192;

    const int n = blockIdx.x;
    const int b0 = blockIdx.y * 64;
    const int tid = threadIdx.x;
    const int wid = tid >> 5;
    const int lane = tid & 31;
    const int grp = lane >> 2;
    const int qp = lane & 3;

    // ---- loads ----
    const uint32_t* wsrcH = (const uint32_t*)(g_Wch + (size_t)n * 16384);
    const uint32_t* wsrcL = (const uint32_t*)(g_Wcl + (size_t)n * 16384);
    for (int idx = tid; idx < 8192; idx += 256) {     // 256 rows x 32 uint32
        int r = idx >> 5, c2 = idx & 31;
        *(uint32_t*)(WHh + r * CW_STRIDE + c2 * 2) = wsrcH[idx];
        *(uint32_t*)(WHl + r * CW_STRIDE + c2 * 2) = wsrcL[idx];
    }
    for (int idx = tid; idx < 2048; idx += 256) {     // 64 rows x 32 uint32
        int r = idx >> 5, c2 = idx & 31;
        size_t gi = (((size_t)(b0 + r) * 4096 + n * 64) >> 1) + c2;
        *(uint32_t*)(XSh + r * CW_STRIDE + c2 * 2) = ((const uint32_t*)g_xah)[gi];
        *(uint32_t*)(XSl + r * CW_STRIDE + c2 * 2) = ((const uint32_t*)g_xal)[gi];
    }
    if (tid < 64) {
        vecs[0 * 64 + tid] = bi_g[n * 64 + tid];
        vecs[1 * 64 + tid] = g_cf[n * 64 + tid];
        vecs[2 * 64 + tid] = bslow_g[n * 64 + tid];
        vecs[3 * 64 + tid] = bo_g[n * 64 + tid];
        vecs[4 * 64 + tid] = hprev_g[n * 64 + tid];
        vecs[5 * 64 + tid] = gln_g[n * 64 + tid];
        vecs[6 * 64 + tid] = bln_g[n * 64 + tid];
    }
    __syncthreads();

    const int aRowL = (lane & 7) + ((lane >> 3) & 1) * 8;   // + wm
    const int aKL = (lane >> 4) * 8;
    const int bRowL = (lane & 7) + (lane >> 4) * 8;         // + wn + p*16
    const int bKL = ((lane >> 3) & 1) * 8;

    // ---- loop1: [64 x 192] = XS[64x64] * Wgates[192x64]^T, 3-pass ----
    {
        const int wm = (wid >> 1) * 16;
        const int wn = (wid & 1) * 96;
        float acc[12][4];
#pragma unroll
        for (int f = 0; f < 12; f++)
#pragma unroll
            for (int j = 0; j < 4; j++) acc[f][j] = 0.f;

#pragma unroll
        for (int ks = 0; ks < 4; ks++) {
            const int k0 = ks * 16;
            uint32_t ah[4], al[4];
            {
                const uint32_t ad = smem_u32(XSh + (wm + aRowL) * CW_STRIDE + k0 + aKL);
                const uint32_t adl = smem_u32(XSl + (wm + aRowL) * CW_STRIDE + k0 + aKL);
                ldsm_x4(ah[0], ah[1], ah[2], ah[3], ad);
                ldsm_x4(al[0], al[1], al[2], al[3], adl);
            }
            uint32_t bh[12][2], bl[12][2];
#pragma unroll
            for (int p = 0; p < 6; p++) {
                const int brow = wn + p * 16 + bRowL;
                uint32_t r0, r1, r2, r3;
                ldsm_x4(r0, r1, r2, r3, smem_u32(WHh + brow * CW_STRIDE + k0 + bKL));
                bh[2 * p][0] = r0; bh[2 * p][1] = r1; bh[2 * p + 1][0] = r2; bh[2 * p + 1][1] = r3;
                ldsm_x4(r0, r1, r2, r3, smem_u32(WHl + brow * CW_STRIDE + k0 + bKL));
                bl[2 * p][0] = r0; bl[2 * p][1] = r1; bl[2 * p + 1][0] = r2; bl[2 * p + 1][1] = r3;
            }
#pragma unroll
            for (int f = 0; f < 12; f++) {
                mma16816(acc[f], ah, bh[f][0], bh[f][1]);
                mma16816(acc[f], ah, bl[f][0], bl[f][1]);
                mma16816(acc[f], al, bh[f][0], bh[f][1]);
            }
        }
        // stage preact to PA
#pragma unroll
        for (int f = 0; f < 12; f++) {
            const int r0 = wm + grp;
            const int col = wn + f * 8 + qp * 2;
            PA[r0 * 192 + col] = acc[f][0];
            PA[r0 * 192 + col + 1] = acc[f][1];
            PA[(r0 + 8) * 192 + col] = acc[f][2];
            PA[(r0 + 8) * 192 + col + 1] = acc[f][3];
        }
    }
    __syncthreads();

    // ---- gates: h_raw = sigmoid(i)*(hs) + sigmoid(f)*hp ----
    for (int idx = tid; idx < 4096; idx += 256) {
        int b = idx >> 6, o = idx & 63;
        float it = sigmoidf_(PA[b * 192 + o] + vecs[0 * 64 + o]);
        float ft = sigmoidf_(PA[b * 192 + 64 + o] + vecs[1 * 64 + o]);
        float hs = PA[b * 192 + 128 + o] + vecs[2 * 64 + o];
        float hr = it * hs + ft * vecs[4 * 64 + o];
        PA[b * 192 + o] = hr;                       // fp32 for tanh
        __half hh = __float2half_rn(hr);
        XSh[b * CW_STRIDE + o] = hh;                // hi/lo for loop2 (XS reuse)
        XSl[b * CW_STRIDE + o] = __float2half_rn(hr - __half2float(hh));
    }
    __syncthreads();

    // ---- loop2: [64 x 64] = hraw * Wo'[64x64]^T, 3-pass; epilogue o_t*tanh ----
    {
        const int wm = (wid & 3) * 16;
        const int wn = (wid >> 2) * 32;
        float acc[4][4];
#pragma unroll
        for (int f = 0; f < 4; f++)
#pragma unroll
            for (int j = 0; j < 4; j++) acc[f][j] = 0.f;

#pragma unroll
        for (int ks = 0; ks < 4; ks++) {
            const int k0 = ks * 16;
            uint32_t ah[4], al[4];
            ldsm_x4(ah[0], ah[1], ah[2], ah[3], smem_u32(XSh + (wm + aRowL) * CW_STRIDE + k0 + aKL));
            ldsm_x4(al[0], al[1], al[2], al[3], smem_u32(XSl + (wm + aRowL) * CW_STRIDE + k0 + aKL));
            uint32_t bh[4][2], bl[4][2];
#pragma unroll
            for (int p = 0; p < 2; p++) {
                const int brow = 192 + wn + p * 16 + bRowL;
                uint32_t r0, r1, r2, r3;
                ldsm_x4(r0, r1, r2, r3, smem_u32(WHh + brow * CW_STRIDE + k0 + bKL));
                bh[2 * p][0] = r0; bh[2 * p][1] = r1; bh[2 * p + 1][0] = r2; bh[2 * p + 1][1] = r3;
                ldsm_x4(r0, r1, r2, r3, smem_u32(WHl + brow * CW_STRIDE + k0 + bKL));
                bl[2 * p][0] = r0; bl[2 * p][1] = r1; bl[2 * p + 1][0] = r2; bl[2 * p + 1][1] = r3;
            }
#pragma unroll
            for (int f = 0; f < 4; f++) {
                mma16816(acc[f], ah, bh[f][0], bh[f][1]);
                mma16816(acc[f], ah, bl[f][0], bl[f][1]);
                mma16816(acc[f], al, bh[f][0], bh[f][1]);
            }
        }
        // y = sigmoid(opre+bo) * tanh(hraw) -> PA cols 64..127
#pragma unroll
        for (int f = 0; f < 4; f++) {
            const int r0 = wm + grp;
            const int col = wn + f * 8 + qp * 2;
#pragma unroll
            for (int half_ = 0; half_ < 2; half_++) {
                const int r = r0 + half_ * 8;
                float o0 = sigmoidf_(acc[f][2 * half_ + 0] + vecs[3 * 64 + col]);
                float o1 = sigmoidf_(acc[f][2 * half_ + 1] + vecs[3 * 64 + col + 1]);
                PA[r * 192 + 64 + col]     = o0 * tanhf(PA[r * 192 + col]);
                PA[r * 192 + 64 + col + 1] = o1 * tanhf(PA[r * 192 + col + 1]);
            }
        }
    }
    __syncthreads();

    // ---- LayerNorm over D=64, warp per row ----
    for (int rr = 0; rr < 8; rr++) {
        int row = wid * 8 + rr;
        float v0 = PA[row * 192 + 64 + 2 * lane];
        float v1 = PA[row * 192 + 64 + 2 * lane + 1];
        float s = v0 + v1;
        float ss = v0 * v0 + v1 * v1;
        for (int o = 16; o > 0; o >>= 1) {
            s += __shfl_xor_sync(0xffffffffu, s, o);
            ss += __shfl_xor_sync(0xffffffffu, ss, o);
        }
        float mu = s * (1.f / 64.f);
        float var = ss * (1.f / 64.f) - mu * mu;
        float inv = rsqrtf(var + 1e-5f);
        float y0 = (v0 - mu) * inv * vecs[5 * 64 + 2 * lane] + vecs[6 * 64 + 2 * lane];
        float y1 = (v1 - mu) * inv * vecs[5 * 64 + 2 * lane + 1] + vecs[6 * 64 + 2 * lane + 1];
        size_t base = (size_t)(b0 + row) * 4096 + n * 64;
        *(float2*)(xflat_out + base + 2 * lane) = make_float2(y0, y1);
        uint32_t hh, ll; cvt2(y0, y1, hh, ll);
        xfh[(base >> 1) + lane] = hh;
        xfl[(base >> 1) + lane] = ll;
    }
}

// ================= top-5 retrieval + update + fp16 re-emit =================
__global__ void __launch_bounds__(256) retrieve_kernel(const float* __restrict__ mem,
                                                       float* __restrict__ xflat,
                                                       uint2* __restrict__ xfh,
                                                       uint2* __restrict__ xfl) {
    int b = blockIdx.x;
    __shared__ float s[64];
    __shared__ int top[5];
    int tid = threadIdx.x;
    if (tid < 64) s[tid] = g_sim[b * 64 + tid];
    __syncthreads();
    if (tid < 32) {
        for (int k = 0; k < 5; k++) {
            float v = s[tid]; int idx = tid;
            float v2 = s[tid + 32];
            if (v2 > v) { v = v2; idx = tid + 32; }
            for (int o = 16; o > 0; o >>= 1) {
                float ov = __shfl_down_sync(0xffffffffu, v, o);
                int oi = __shfl_down_sync(0xffffffffu, idx, o);
                if (ov > v || (ov == v && oi < idx)) { v = ov; idx = oi; }
            }
            idx = __shfl_sync(0xffffffffu, idx, 0);
            if (tid == 0) top[k] = idx;
            if (tid == 0) s[idx] = -INFINITY;
            __syncwarp();
        }
    }
    __syncthreads();
    const float4* m4 = (const float4*)mem;
    float4* x4 = (float4*)(xflat + (size_t)b * 4096);
    int t0 = top[0] * 1024, t1 = top[1] * 1024, t2 = top[2] * 1024, t3 = top[3] * 1024, t4 = top[4] * 1024;
#pragma unroll
    for (int j = 0; j < 4; j++) {
        int idx = tid + j * 256;
        float4 xv = x4[idx];
        float4 a = m4[t0 + idx], bb = m4[t1 + idx], c = m4[t2 + idx], d = m4[t3 + idx], e = m4[t4 + idx];
        xv.x += 0.02f * (a.x + bb.x + c.x + d.x + e.x);
        xv.y += 0.02f * (a.y + bb.y + c.y + d.y + e.y);
        xv.z += 0.02f * (a.z + bb.z + c.z + d.z + e.z);
        xv.w += 0.02f * (a.w + bb.w + c.w + d.w + e.w);
        x4[idx] = xv;
        uint2 h, l; cvt4(xv, h, l);
        xfh[(size_t)b * 1024 + idx] = h;
        xfl[(size_t)b * 1024 + idx] = l;
    }
}

// ================= proj2: proj[b, 0:8] = relu_s1[b,:] @ Ws2^T + bs2 =================
__global__ void __launch_bounds__(256) proj2_kernel(const float* __restrict__ s1,
                                                    const float* __restrict__ Ws2,
                                                    const float* __restrict__ bs2,
                                                    float* __restrict__ proj) {
    __shared__ float w2s[8 * 1024];
    __shared__ float bss[8];
    int tid = threadIdx.x;
    for (int i = tid; i < 8192; i += 256) w2s[i] = Ws2[i];
    if (tid < 8) bss[tid] = bs2[tid];
    __syncthreads();
    int w = tid >> 5, lane = tid & 31;
    int b = blockIdx.x * 8 + w;
    const float4* row = (const float4*)(s1 + (size_t)b * 1024);
    float4 xv[8];
#pragma unroll
    for (int j = 0; j < 8; j++) xv[j] = row[lane + j * 32];
#pragma unroll
    for (int p = 0; p < 8; p++) {
        const float4* wr = (const float4*)(w2s + p * 1024);
        float acc = 0.f;
#pragma unroll
        for (int j = 0; j < 8; j++) {
            float4 wv = wr[lane + j * 32];
            acc += xv[j].x * wv.x + xv[j].y * wv.y + xv[j].z * wv.z + xv[j].w * wv.w;
        }
        for (int o = 16; o > 0; o >>= 1) acc += __shfl_xor_sync(0xffffffffu, acc, o);
        if (lane == 0) proj[(size_t)b * 8 + p] = acc + bss[p];
    }
}

// ================= launch =================
extern "C" void kernel_launch(void* const* d_in, const int* in_sizes, int n_in,
                              void* d_out, int out_size) {
    const float* x      = (const float*)d_in[0];
    const float* W1     = (const float*)d_in[1];
    const float* b1     = (const float*)d_in[2];
    const float* g1     = (const float*)d_in[3];
    const float* beta1  = (const float*)d_in[4];
    const float* W2     = (const float*)d_in[5];
    const float* b2     = (const float*)d_in[6];
    const float* edge_w = (const float*)d_in[7];
    const float* mask   = (const float*)d_in[8];
    const float* Wi     = (const float*)d_in[9];
    const float* bi     = (const float*)d_in[10];
    const float* Wf     = (const float*)d_in[11];
    const float* bf     = (const float*)d_in[12];
    const float* Wslow  = (const float*)d_in[13];
    const float* bslow  = (const float*)d_in[14];
    const float* u      = (const float*)d_in[15];
    const float* Wfast  = (const float*)d_in[16];
    const float* Wo     = (const float*)d_in[17];
    const float* bo     = (const float*)d_in[18];
    const float* gln    = (const float*)d_in[19];
    const float* bln    = (const float*)d_in[20];
    const float* h_prev = (const float*)d_in[21];
    const float* memory = (const float*)d_in[22];
    const float* Wh     = (const float*)d_in[23];
    const float* bh     = (const float*)d_in[24];
    const float* Ws1    = (const float*)d_in[25];
    const float* bs1    = (const float*)d_in[26];
    const float* Ws2    = (const float*)d_in[27];
    const float* bs2    = (const float*)d_in[28];

    float* out    = (float*)d_out;
    float* logits = out;
    float* proj   = out + (size_t)Bn * Ccls;
    float* xflat  = proj + (size_t)Bn * Pp;

    float *p_h1, *p_b2a, *p_sim, *p_s1, *p_bhm;
    cudaGetSymbolAddress((void**)&p_h1, g_h1);
    cudaGetSymbolAddress((void**)&p_b2a, g_b2a);
    cudaGetSymbolAddress((void**)&p_sim, g_sim);
    cudaGetSymbolAddress((void**)&p_s1, g_s1);
    cudaGetSymbolAddress((void**)&p_bhm, g_bhm);
    void *p_xh, *p_xl, *p_W1h, *p_W1l, *p_h1h, *p_h1l, *p_W2h, *p_W2l;
    void *p_xah, *p_xal, *p_xfh, *p_xfl, *p_Whmh, *p_Whml, *p_Ws1h, *p_Ws1l, *p_memh, *p_meml;
    cudaGetSymbolAddress(&p_xh, g_xh);   cudaGetSymbolAddress(&p_xl, g_xl);
    cudaGetSymbolAddress(&p_W1h, g_W1h); cudaGetSymbolAddress(&p_W1l, g_W1l);
    cudaGetSymbolAddress(&p_h1h, g_h1h); cudaGetSymbolAddress(&p_h1l, g_h1l);
    cudaGetSymbolAddress(&p_W2h, g_W2h); cudaGetSymbolAddress(&p_W2l, g_W2l);
    cudaGetSymbolAddress(&p_xah, g_xah); cudaGetSymbolAddress(&p_xal, g_xal);
    cudaGetSymbolAddress(&p_xfh, g_xfh); cudaGetSymbolAddress(&p_xfl, g_xfl);
    cudaGetSymbolAddress(&p_Whmh, g_Whmh); cudaGetSymbolAddress(&p_Whml, g_Whml);
    cudaGetSymbolAddress(&p_Ws1h, g_Ws1h); cudaGetSymbolAddress(&p_Ws1l, g_Ws1l);
    cudaGetSymbolAddress(&p_memh, g_memh); cudaGetSymbolAddress(&p_meml, g_meml);

    cudaFuncSetAttribute(cell_hmma, cudaFuncAttributeMaxDynamicSharedMemorySize, CELL2_SMEM);
    cudaFuncSetAttribute(gemm_mma<4, true>,  cudaFuncAttributeMaxDynamicSharedMemorySize, GSMEM_TOTAL);
    cudaFuncSetAttribute(gemm_mma<4, false>, cudaFuncAttributeMaxDynamicSharedMemorySize, GSMEM_TOTAL);
    cudaFuncSetAttribute(gemm_mma<2, true>,  cudaFuncAttributeMaxDynamicSharedMemorySize, GSMEM_TOTAL);

    // prep + conversions
    prep_adj<<<1, 64>>>(edge_w, mask);
    fold_w2<<<dim3(8, 64), 256>>>(W2);
    prep_b2a<<<64, 64>>>(b2);
    prep_node<<<64, 64>>>(Wslow, u, Wfast, Wf, bf, h_prev, Wi, Wo);
    prep_whm_bf<<<(1024 * FLAT / 4 + 255) / 256, 256>>>(Wh);
    prep_bhm<<<4, 256>>>(bh);
    cvt_hilo<<<(Bn * Fdim / 4 + 255) / 256, 256>>>(x, (uint2*)p_xh, (uint2*)p_xl, Bn * Fdim / 4);
    cvt_hilo<<<(Hdim * Fdim / 4 + 255) / 256, 256>>>(W1, (uint2*)p_W1h, (uint2*)p_W1l, Hdim * Fdim / 4);
    cvt_hilo<<<(Hdim * FLAT / 4 + 255) / 256, 256>>>(Ws1, (uint2*)p_Ws1h, (uint2*)p_Ws1l, Hdim * FLAT / 4);
    cvt_mem_pad<<<(128 * FLAT / 4 + 255) / 256, 256>>>(memory);

    // stage 1: input projection; G2 emits x_agg as fp16 hi/lo (adj folded)
    gemm_mma<4, true><<<dim3(Hdim / 128, Bn / 128), 256, GSMEM_TOTAL>>>(
        (const __half*)p_xh, (const __half*)p_xl,
        (const __half*)p_W1h, (const __half*)p_W1l, b1, p_h1, nullptr, nullptr,
        Fdim, Fdim, Hdim, 0, 0);
    ln_gelu_kernel<<<Bn, 256>>>(p_h1, g1, beta1, (uint2*)p_h1h, (uint2*)p_h1l);
    gemm_mma<4, true><<<dim3(FLAT / 128, Bn / 128), 256, GSMEM_TOTAL>>>(
        (const __half*)p_h1h, (const __half*)p_h1l,
        (const __half*)p_W2h, (const __half*)p_W2l, p_b2a, nullptr,
        (uint32_t*)p_xah, (uint32_t*)p_xal,
        Hdim, Hdim, FLAT, 0, 0);

    // stage 2: cells (HMMA, 3-pass fp16)
    cell_hmma<<<dim3(Nn, Bn / 64), 256, CELL2_SMEM>>>(bi, bslow, bo, h_prev, gln, bln,
                                                      xflat, (uint32_t*)p_xfh, (uint32_t*)p_xfl);

    // stage 3: retrieval (split-K sim GEMM, atomic accumulate)
    zero_sim<<<Bn * CAP / 256, 256>>>();
    gemm_mma<2, true><<<dim3(1, Bn / 128, 4), 256, GSMEM_TOTAL>>>(
        (const __half*)p_xfh, (const __half*)p_xfl,
        (const __half*)p_memh, (const __half*)p_meml, nullptr, p_sim, nullptr, nullptr,
        FLAT / 4, FLAT, CAP, 0, 1);
    retrieve_kernel<<<Bn, 256>>>(memory, xflat, (uint2*)p_xfh, (uint2*)p_xfl);

    // stage 4: heads (2-pass fp16)
    gemm_mma<4, false><<<dim3(1024 / 128, Bn / 128), 256, GSMEM_TOTAL>>>(
        (const __half*)p_xfh, nullptr,
        (const __half*)p_Whmh, (const __half*)p_Whml, p_bhm, logits, nullptr, nullptr,
        FLAT, FLAT, Ccls, 0, 0);
    gemm_mma<4, false><<<dim3(Hdim / 128, Bn / 128), 256, GSMEM_TOTAL>>>(
        (const __half*)p_xfh, nullptr,
        (const __half*)p_Ws1h, (const __half*)p_Ws1l, bs1, p_s1, nullptr, nullptr,
        FLAT, FLAT, Hdim, 1, 0);
    proj2_kernel<<<Bn / 8, 256>>>(p_s1, Ws2, bs2, proj);
}

// round 10
// speedup vs baseline: 1.1650x; 1.1650x over previous
#include <cuda_runtime.h>
#include <cuda_fp16.h>
#include <math.h>
#include <stdint.h>

#define Bn 4096
#define Fdim 512
#define Hdim 1024
#define Nn 64
#define Dd 64
#define FLAT 4096
#define Ccls 1000
#define CAP 64
#define Pp 8

// ================= scratch (device globals) =================
__device__ float g_h1[Bn * Hdim];
__device__ float g_b2a[FLAT];
__device__ float g_xagg[(size_t)Bn * FLAT];
__device__ float g_sim[Bn * CAP];
__device__ float g_s1[Bn * Hdim];
__device__ float g_bhm[1024];
__device__ float g_adj[Nn * Nn];
__device__ float g_WcT[Nn * Dd * Dd];
__device__ float g_cf[Nn * Dd];
// fp16 hi/lo operand buffers
__device__ __half g_xh[Bn * Fdim],    g_xl[Bn * Fdim];
__device__ __half g_W1h[Hdim * Fdim], g_W1l[Hdim * Fdim];
__device__ __half g_h1h[Bn * Hdim],   g_h1l[Bn * Hdim];
__device__ __half g_W2h[FLAT * Hdim], g_W2l[FLAT * Hdim];
__device__ __half g_xfh[(size_t)Bn * FLAT], g_xfl[(size_t)Bn * FLAT];
__device__ __half g_Whmh[1024 * FLAT], g_Whml[1024 * FLAT];
__device__ __half g_Ws1h[Hdim * FLAT], g_Ws1l[Hdim * FLAT];
__device__ __half g_memh[128 * FLAT], g_meml[128 * FLAT];

__device__ __forceinline__ float sigmoidf_(float x) { return 1.f / (1.f + expf(-x)); }

__device__ __forceinline__ uint32_t pack2h(__half a, __half b) {
    return (uint32_t)__half_as_ushort(a) | ((uint32_t)__half_as_ushort(b) << 16);
}
__device__ __forceinline__ void cvt4(float4 v, uint2& hi, uint2& lo) {
    __half h0 = __float2half_rn(v.x), h1 = __float2half_rn(v.y);
    __half h2 = __float2half_rn(v.z), h3 = __float2half_rn(v.w);
    __half l0 = __float2half_rn(v.x - __half2float(h0));
    __half l1 = __float2half_rn(v.y - __half2float(h1));
    __half l2 = __float2half_rn(v.z - __half2float(h2));
    __half l3 = __float2half_rn(v.w - __half2float(h3));
    hi.x = pack2h(h0, h1); hi.y = pack2h(h2, h3);
    lo.x = pack2h(l0, l1); lo.y = pack2h(l2, l3);
}
__device__ __forceinline__ void cvt2(float a, float b, uint32_t& hi, uint32_t& lo) {
    __half h0 = __float2half_rn(a), h1 = __float2half_rn(b);
    __half l0 = __float2half_rn(a - __half2float(h0));
    __half l1 = __float2half_rn(b - __half2float(h1));
    hi = pack2h(h0, h1); lo = pack2h(l0, l1);
}

// ================= mma / cp.async / ldmatrix primitives =================
__device__ __forceinline__ uint32_t smem_u32(const void* p) {
    uint32_t a;
    asm("{ .reg .u64 t; cvta.to.shared.u64 t, %1; cvt.u32.u64 %0, t; }" : "=r"(a) : "l"(p));
    return a;
}
__device__ __forceinline__ void cp16(uint32_t s, const void* g) {
    asm volatile("cp.async.cg.shared.global [%0], [%1], 16;" :: "r"(s), "l"(g));
}
#define CP_COMMIT() asm volatile("cp.async.commit_group;")
#define CP_WAIT1() asm volatile("cp.async.wait_group 1;")

__device__ __forceinline__ void mma16816(float* d, const uint32_t* a, uint32_t b0, uint32_t b1) {
    asm volatile(
        "mma.sync.aligned.m16n8k16.row.col.f32.f16.f16.f32 "
        "{%0,%1,%2,%3}, {%4,%5,%6,%7}, {%8,%9}, {%0,%1,%2,%3};"
        : "+f"(d[0]), "+f"(d[1]), "+f"(d[2]), "+f"(d[3])
        : "r"(a[0]), "r"(a[1]), "r"(a[2]), "r"(a[3]), "r"(b0), "r"(b1));
}
__device__ __forceinline__ void ldsm_x4(uint32_t& r0, uint32_t& r1, uint32_t& r2, uint32_t& r3,
                                        uint32_t addr) {
    asm volatile("ldmatrix.sync.aligned.m8n8.x4.shared.b16 {%0,%1,%2,%3}, [%4];"
                 : "=r"(r0), "=r"(r1), "=r"(r2), "=r"(r3) : "r"(addr));
}

// ================= conversion kernels =================
__global__ void cvt_hilo(const float* __restrict__ src, uint2* __restrict__ hi,
                         uint2* __restrict__ lo, int n4) {
    int i = blockIdx.x * 256 + threadIdx.x;
    if (i < n4) {
        float4 v = ((const float4*)src)[i];
        uint2 h, l; cvt4(v, h, l);
        hi[i] = h; lo[i] = l;
    }
}
__global__ void cvt_mem_pad(const float* __restrict__ mem) {
    int i = blockIdx.x * 256 + threadIdx.x;
    if (i >= 128 * FLAT / 4) return;
    int row = i >> 10;
    uint2 h = make_uint2(0u, 0u), l = make_uint2(0u, 0u);
    if (row < CAP) {
        float4 v = ((const float4*)mem)[i];
        cvt4(v, h, l);
    }
    ((uint2*)g_memh)[i] = h; ((uint2*)g_meml)[i] = l;
}

// ================= prep kernels =================
__global__ void prep_adj(const float* __restrict__ edge_w, const float* __restrict__ mask) {
    __shared__ float t[64 * 64];
    int r = threadIdx.x;
    float sum = 0.f;
    for (int c = 0; c < 64; c++) {
        float v = sigmoidf_(edge_w[r * 64 + c] * 1.5f) * mask[r * 64 + c];
        t[r * 64 + c] = v; sum += v;
    }
    float inv = 1.f / fmaxf(sum, 1e-6f);
    for (int c = 0; c < 64; c++) g_adj[r * 64 + c] = t[r * 64 + c] * inv;
}

// fold adjacency into W2, emit fp16 hi/lo
__global__ void __launch_bounds__(256) fold_w2(const float* __restrict__ W2) {
    int kt = blockIdx.x;
    int d  = blockIdx.y;
    __shared__ float tile[64][128];
    __shared__ float adjT[64 * 64];
    int tid = threadIdx.x;
    for (int i = tid; i < 4096; i += 256) {
        int m = i >> 6, n = i & 63;
        adjT[i] = g_adj[n * 64 + m];
    }
    for (int i = tid; i < 64 * 32; i += 256) {
        int m = i >> 5, c4 = (i & 31) << 2;
        *(float4*)&tile[m][c4] = *(const float4*)(W2 + (size_t)(m * 64 + d) * Hdim + kt * 128 + c4);
    }
    __syncthreads();
    int n = tid & 63;
    int kq = tid >> 6;
    float4 acc[8];
#pragma unroll
    for (int q = 0; q < 8; q++) acc[q] = make_float4(0.f, 0.f, 0.f, 0.f);
    for (int m = 0; m < 64; m++) {
        float s = adjT[m * 64 + n];
        const float4* trow = (const float4*)&tile[m][kq * 32];
#pragma unroll
        for (int q = 0; q < 8; q++) {
            float4 t4 = trow[q];
            acc[q].x += s * t4.x; acc[q].y += s * t4.y;
            acc[q].z += s * t4.z; acc[q].w += s * t4.w;
        }
    }
    size_t off4 = ((size_t)(n * 64 + d) * Hdim + kt * 128 + kq * 32) >> 2;
#pragma unroll
    for (int q = 0; q < 8; q++) {
        uint2 h, l; cvt4(acc[q], h, l);
        ((uint2*)g_W2h)[off4 + q] = h;
        ((uint2*)g_W2l)[off4 + q] = l;
    }
}
__global__ void prep_b2a(const float* __restrict__ b2) {
    int nd = blockIdx.x * 64 + threadIdx.x;
    int n = nd >> 6, d = nd & 63;
    float acc = 0.f;
    for (int m = 0; m < 64; m++) acc += g_adj[n * 64 + m] * b2[m * 64 + d];
    g_b2a[nd] = acc;
}

__global__ void prep_node(const float* __restrict__ Wslow, const float* __restrict__ u,
                          const float* __restrict__ Wfast, const float* __restrict__ Wf,
                          const float* __restrict__ bf, const float* __restrict__ hprev) {
    int n = blockIdx.x;
    int t = threadIdx.x;
    __shared__ float us[64], v[64], red[64];
    const float* Ws = Wslow + (size_t)n * 4096;
    us[t] = u[n * 64 + t];
    __syncthreads();
    float acc = 0.f;
    for (int o = 0; o < 64; o++) acc += Ws[o * 64 + t] * us[o];
    v[t] = acc;
    __syncthreads();
    float wv = 0.f;
    for (int i = 0; i < 64; i++) wv += Ws[t * 64 + i] * v[i];
    red[t] = us[t] * wv;
    __syncthreads();
    for (int off = 32; off > 0; off >>= 1) {
        if (t < off) red[t] += red[t + off];
        __syncthreads();
    }
    float inv = 1.f / (red[0] + 1e-8f);
    const float* Wfa = Wfast + (size_t)n * 4096;
    float* out = g_WcT + (size_t)n * 4096;
    for (int idx = t; idx < 4096; idx += 64) {
        int i = idx >> 6, o = idx & 63;
        out[idx] = Ws[o * 64 + i] * inv + Wfa[o * 64 + i];
    }
    float c = bf[n * 64 + t];
    const float* Wf2 = Wf + (size_t)n * 8192 + 4096;
    for (int i = 0; i < 64; i++) c += hprev[n * 64 + i] * Wf2[i * 64 + t];
    g_cf[n * 64 + t] = c;
}

__global__ void prep_whm_bf(const float* __restrict__ Wh) {
    int i = blockIdx.x * 256 + threadIdx.x;
    if (i >= (1024 * FLAT) / 4) return;
    int row = i >> 10;
    uint2 h, l;
    if (row < Ccls) {
        const size_t CF4 = (size_t)Ccls * FLAT / 4;
        const float4* W4 = (const float4*)Wh;
        float4 a = W4[i], b = W4[i + CF4], c = W4[i + 2 * CF4];
        float4 m = make_float4((a.x + b.x + c.x) * (1.f / 3.f), (a.y + b.y + c.y) * (1.f / 3.f),
                               (a.z + b.z + c.z) * (1.f / 3.f), (a.w + b.w + c.w) * (1.f / 3.f));
        cvt4(m, h, l);
    } else {
        h = make_uint2(0u, 0u); l = make_uint2(0u, 0u);
    }
    ((uint2*)g_Whmh)[i] = h; ((uint2*)g_Whml)[i] = l;
}
__global__ void prep_bhm(const float* __restrict__ bh) {
    int i = blockIdx.x * 256 + threadIdx.x;
    if (i < 1024) g_bhm[i] = (i < Ccls) ? (bh[i] + bh[i + Ccls] + bh[i + 2 * Ccls]) * (1.f / 3.f) : 0.f;
}
__global__ void zero_sim() {
    g_sim[blockIdx.x * 256 + threadIdx.x] = 0.f;
}

// ================= split-fp16 HMMA GEMM =================
#define TSTRIDE 40
#define ROWB (TSTRIDE * 2)
#define TILE_B (128 * ROWB)
#define STAGE_B (4 * TILE_B)
#define GSMEM_TOTAL (2 * STAGE_B)

template <int NI, bool THREE>
__global__ void __launch_bounds__(256, 2) gemm_mma(
    const __half* __restrict__ Ahi, const __half* __restrict__ Alo,
    const __half* __restrict__ Bhi, const __half* __restrict__ Blo,
    const float* __restrict__ bias, float* __restrict__ C,
    int K, int lda, int Nstore, int act, int atomicOut) {
    extern __shared__ char smem[];
    const int tid = threadIdx.x;
    const int wid = tid >> 5;
    const int lane = tid & 31;
    const int grp = lane >> 2;
    const int qp = lane & 3;
    const int wm = (wid >> 2) * 64;
    const int wn = (wid & 3) * (NI * 8);
    const int bm = blockIdx.y * 128;
    const int bn = blockIdx.x * 128;
    const int kbase = blockIdx.z * K;
    const uint32_t sb = smem_u32(smem);

    const int row = tid >> 2;
    const int c16 = tid & 3;

    const int aRowL = wm + (lane & 7) + ((lane >> 3) & 1) * 8;
    const int aKL = (lane >> 4) * 8;
    const int bRowL = wn + (lane & 7) + (lane >> 4) * 8;
    const int bKL = ((lane >> 3) & 1) * 8;

    float acc[4][NI][4];
#pragma unroll
    for (int mi = 0; mi < 4; mi++)
#pragma unroll
        for (int ni = 0; ni < NI; ni++)
#pragma unroll
            for (int j = 0; j < 4; j++) acc[mi][ni][j] = 0.f;

    const int nc = K >> 5;

    auto issue = [&](int c, int s) {
        const uint32_t ss = sb + s * STAGE_B;
        const int k0 = c << 5;
#pragma unroll
        for (int t = 0; t < 2; t++) {
            const int r = row + t * 64;
            const uint32_t so = (uint32_t)r * ROWB + c16 * 16;
            const size_t gAoff = ((size_t)(bm + r) * lda + kbase + k0) * 2 + c16 * 16;
            const size_t gBoff = ((size_t)(bn + r) * lda + kbase + k0) * 2 + c16 * 16;
            cp16(ss + 0 * TILE_B + so, (const char*)Ahi + gAoff);
            if (THREE) cp16(ss + 1 * TILE_B + so, (const char*)Alo + gAoff);
            cp16(ss + 2 * TILE_B + so, (const char*)Bhi + gBoff);
            cp16(ss + 3 * TILE_B + so, (const char*)Blo + gBoff);
        }
    };

    issue(0, 0); CP_COMMIT();
    if (nc > 1) issue(1, 1);
    CP_COMMIT();

    for (int c = 0; c < nc; c++) {
        const int s = c & 1;
        CP_WAIT1();
        __syncthreads();
        const uint32_t st = sb + s * STAGE_B;
#pragma unroll
        for (int ks = 0; ks < 2; ks++) {
            const int k0 = ks * 16;
            uint32_t ah[4][4], al[4][4];
#pragma unroll
            for (int mi = 0; mi < 4; mi++) {
                const uint32_t ad = st + (uint32_t)(aRowL + mi * 16) * ROWB + (k0 + aKL) * 2;
                ldsm_x4(ah[mi][0], ah[mi][1], ah[mi][2], ah[mi][3], ad);
                if (THREE) ldsm_x4(al[mi][0], al[mi][1], al[mi][2], al[mi][3], ad + TILE_B);
            }
            uint32_t bh[NI][2], bl[NI][2];
#pragma unroll
            for (int p = 0; p < NI / 2; p++) {
                const uint32_t bd = st + 2 * TILE_B + (uint32_t)(bRowL + p * 16) * ROWB + (k0 + bKL) * 2;
                uint32_t r0, r1, r2, r3;
                ldsm_x4(r0, r1, r2, r3, bd);
                bh[2 * p][0] = r0; bh[2 * p][1] = r1; bh[2 * p + 1][0] = r2; bh[2 * p + 1][1] = r3;
                ldsm_x4(r0, r1, r2, r3, bd + TILE_B);
                bl[2 * p][0] = r0; bl[2 * p][1] = r1; bl[2 * p + 1][0] = r2; bl[2 * p + 1][1] = r3;
            }
#pragma unroll
            for (int ni = 0; ni < NI; ni++) {
#pragma unroll
                for (int mi = 0; mi < 4; mi++) {
                    mma16816(acc[mi][ni], ah[mi], bh[ni][0], bh[ni][1]);
                    mma16816(acc[mi][ni], ah[mi], bl[ni][0], bl[ni][1]);
                    if (THREE) mma16816(acc[mi][ni], al[mi], bh[ni][0], bh[ni][1]);
                }
            }
        }
        __syncthreads();
        if (c + 2 < nc) issue(c + 2, s);
        CP_COMMIT();
    }

    // epilogue
#pragma unroll
    for (int mi = 0; mi < 4; mi++) {
#pragma unroll
        for (int ni = 0; ni < NI; ni++) {
            const int r0 = bm + wm + mi * 16 + grp;
            const int col = bn + wn + ni * 8 + qp * 2;
            float* a4 = acc[mi][ni];
            if (atomicOut) {
                if (col < Nstore) {
                    atomicAdd(&C[(size_t)r0 * Nstore + col], a4[0]);
                    atomicAdd(&C[(size_t)(r0 + 8) * Nstore + col], a4[2]);
                    if (col + 1 < Nstore) {
                        atomicAdd(&C[(size_t)r0 * Nstore + col + 1], a4[1]);
                        atomicAdd(&C[(size_t)(r0 + 8) * Nstore + col + 1], a4[3]);
                    }
                }
            } else if (col + 1 < Nstore) {
                float2 v0, v1;
                float bb0 = bias ? bias[col] : 0.f;
                float bb1 = bias ? bias[col + 1] : 0.f;
                v0.x = a4[0] + bb0; v0.y = a4[1] + bb1;
                v1.x = a4[2] + bb0; v1.y = a4[3] + bb1;
                if (act == 1) {
                    v0.x = fmaxf(v0.x, 0.f); v0.y = fmaxf(v0.y, 0.f);
                    v1.x = fmaxf(v1.x, 0.f); v1.y = fmaxf(v1.y, 0.f);
                }
                *(float2*)(C + (size_t)r0 * Nstore + col) = v0;
                *(float2*)(C + (size_t)(r0 + 8) * Nstore + col) = v1;
            } else if (col < Nstore) {
                float bb0 = bias ? bias[col] : 0.f;
                float v0 = a4[0] + bb0, v1 = a4[2] + bb0;
                if (act == 1) { v0 = fmaxf(v0, 0.f); v1 = fmaxf(v1, 0.f); }
                C[(size_t)r0 * Nstore + col] = v0;
                C[(size_t)(r0 + 8) * Nstore + col] = v1;
            }
        }
    }
}

// ================= LayerNorm(H=1024) + GELU -> fp16 hi/lo =================
__global__ void __launch_bounds__(256) ln_gelu_kernel(const float* __restrict__ h,
                                                      const float* __restrict__ g,
                                                      const float* __restrict__ beta,
                                                      uint2* __restrict__ hi,
                                                      uint2* __restrict__ lo) {
    int row = blockIdx.x;
    const float* hr = h + (size_t)row * Hdim;
    int tid = threadIdx.x;
    float4 v = *(const float4*)(hr + tid * 4);
    float s = v.x + v.y + v.z + v.w;
    float ss = v.x * v.x + v.y * v.y + v.z * v.z + v.w * v.w;
    __shared__ float rs[8], rss[8];
    for (int o = 16; o > 0; o >>= 1) {
        s += __shfl_down_sync(0xffffffffu, s, o);
        ss += __shfl_down_sync(0xffffffffu, ss, o);
    }
    if ((tid & 31) == 0) { rs[tid >> 5] = s; rss[tid >> 5] = ss; }
    __syncthreads();
    if (tid < 32) {
        float a = tid < 8 ? rs[tid] : 0.f;
        float b = tid < 8 ? rss[tid] : 0.f;
        for (int o = 4; o > 0; o >>= 1) {
            a += __shfl_down_sync(0xffffffffu, a, o);
            b += __shfl_down_sync(0xffffffffu, b, o);
        }
        if (tid == 0) { rs[0] = a; rss[0] = b; }
    }
    __syncthreads();
    float mu = rs[0] * (1.f / Hdim);
    float var = rss[0] * (1.f / Hdim) - mu * mu;
    float inv = rsqrtf(var + 1e-5f);
    float4 gg = *(const float4*)(g + tid * 4);
    float4 bb = *(const float4*)(beta + tid * 4);
    float y;
    y = (v.x - mu) * inv * gg.x + bb.x; v.x = 0.5f * y * (1.f + erff(y * 0.70710678118654752f));
    y = (v.y - mu) * inv * gg.y + bb.y; v.y = 0.5f * y * (1.f + erff(y * 0.70710678118654752f));
    y = (v.z - mu) * inv * gg.z + bb.z; v.z = 0.5f * y * (1.f + erff(y * 0.70710678118654752f));
    y = (v.w - mu) * inv * gg.w + bb.w; v.w = 0.5f * y * (1.f + erff(y * 0.70710678118654752f));
    uint2 hh, ll; cvt4(v, hh, ll);
    hi[(size_t)row * 256 + tid] = hh;
    lo[(size_t)row * 256 + tid] = ll;
}

// ================= fused cell kernel (emits fp16 hi/lo of xflat) =================
#define CELL_SMEM ((64 * 68 * 2 + 4096 * 4 + 7 * 64) * sizeof(float))
__global__ void __launch_bounds__(256) cell_kernel(const float* __restrict__ Wi,
                                                   const float* __restrict__ Wf,
                                                   const float* __restrict__ Wo,
                                                   const float* __restrict__ bi_g,
                                                   const float* __restrict__ bslow_g,
                                                   const float* __restrict__ bo_g,
                                                   const float* __restrict__ hprev_g,
                                                   const float* __restrict__ gln_g,
                                                   const float* __restrict__ bln_g,
                                                   float* __restrict__ xflat_out,
                                                   uint32_t* __restrict__ xfh,
                                                   uint32_t* __restrict__ xfl) {
    extern __shared__ float sf[];
    float* xs = sf;
    float* wi = xs + 64 * 68;
    float* wf = wi + 4096;
    float* wc = wf + 4096;
    float* wo = wc + 4096;
    float* hr = wo + 4096;
    float* vecs = hr + 64 * 68;

    int n = blockIdx.x;
    int b0 = blockIdx.y * 64;
    int tid = threadIdx.x;

#pragma unroll
    for (int j = 0; j < 4; j++) {
        int idx = tid + j * 256;
        int row = idx >> 4, c4 = (idx & 15) << 2;
        *(float4*)(xs + row * 68 + c4) =
            *(const float4*)(g_xagg + (((size_t)(b0 + row) * 64 + n) << 6) + c4);
        ((float4*)wi)[idx] = ((const float4*)(Wi + (size_t)n * 4096))[idx];
        ((float4*)wf)[idx] = ((const float4*)(Wf + (size_t)n * 8192))[idx];
        ((float4*)wc)[idx] = ((const float4*)(g_WcT + (size_t)n * 4096))[idx];
        ((float4*)wo)[idx] = ((const float4*)(Wo + (size_t)n * 4096))[idx];
    }
    if (tid < 64) {
        vecs[0 * 64 + tid] = bi_g[n * 64 + tid];
        vecs[1 * 64 + tid] = g_cf[n * 64 + tid];
        vecs[2 * 64 + tid] = bslow_g[n * 64 + tid];
        vecs[3 * 64 + tid] = bo_g[n * 64 + tid];
        vecs[4 * 64 + tid] = hprev_g[n * 64 + tid];
        vecs[5 * 64 + tid] = gln_g[n * 64 + tid];
        vecs[6 * 64 + tid] = bln_g[n * 64 + tid];
    }
    __syncthreads();

    const int r0 = (tid >> 4) * 4;
    const int c0 = (tid & 15) * 4;

    float ai[4][4], af[4][4], ac[4][4];
#pragma unroll
    for (int r = 0; r < 4; r++)
#pragma unroll
        for (int c = 0; c < 4; c++) { ai[r][c] = 0.f; af[r][c] = 0.f; ac[r][c] = 0.f; }

    for (int i = 0; i < 64; i++) {
        float xv[4];
#pragma unroll
        for (int r = 0; r < 4; r++) xv[r] = xs[(r0 + r) * 68 + i];
        float4 w1 = *(const float4*)(wi + i * 64 + c0);
        float4 w2 = *(const float4*)(wf + i * 64 + c0);
        float4 w3 = *(const float4*)(wc + i * 64 + c0);
#pragma unroll
        for (int r = 0; r < 4; r++) {
            ai[r][0] += xv[r] * w1.x; ai[r][1] += xv[r] * w1.y; ai[r][2] += xv[r] * w1.z; ai[r][3] += xv[r] * w1.w;
            af[r][0] += xv[r] * w2.x; af[r][1] += xv[r] * w2.y; af[r][2] += xv[r] * w2.z; af[r][3] += xv[r] * w2.w;
            ac[r][0] += xv[r] * w3.x; ac[r][1] += xv[r] * w3.y; ac[r][2] += xv[r] * w3.z; ac[r][3] += xv[r] * w3.w;
        }
    }
#pragma unroll
    for (int r = 0; r < 4; r++)
#pragma unroll
        for (int c = 0; c < 4; c++) {
            int o = c0 + c;
            float it = sigmoidf_(ai[r][c] + vecs[0 * 64 + o]);
            float ft = sigmoidf_(af[r][c] + vecs[1 * 64 + o]);
            float hs = ac[r][c] + vecs[2 * 64 + o];
            hr[(r0 + r) * 68 + o] = it * hs + ft * vecs[4 * 64 + o];
        }
    __syncthreads();

    float ao[4][4];
#pragma unroll
    for (int r = 0; r < 4; r++)
#pragma unroll
        for (int c = 0; c < 4; c++) ao[r][c] = 0.f;
    for (int i = 0; i < 64; i++) {
        float xv[4];
#pragma unroll
        for (int r = 0; r < 4; r++) xv[r] = hr[(r0 + r) * 68 + i];
        float4 w = *(const float4*)(wo + i * 64 + c0);
#pragma unroll
        for (int r = 0; r < 4; r++) {
            ao[r][0] += xv[r] * w.x; ao[r][1] += xv[r] * w.y;
            ao[r][2] += xv[r] * w.z; ao[r][3] += xv[r] * w.w;
        }
    }
    float* ys = xs;
#pragma unroll
    for (int r = 0; r < 4; r++)
#pragma unroll
        for (int c = 0; c < 4; c++) {
            int o = c0 + c;
            float ot = sigmoidf_(ao[r][c] + vecs[3 * 64 + o]);
            ys[(r0 + r) * 68 + o] = ot * tanhf(hr[(r0 + r) * 68 + o]);
        }
    __syncthreads();

    int w = tid >> 5, lane = tid & 31;
    for (int rr = 0; rr < 8; rr++) {
        int row = w * 8 + rr;
        float v0 = ys[row * 68 + 2 * lane];
        float v1 = ys[row * 68 + 2 * lane + 1];
        float s = v0 + v1;
        float ss = v0 * v0 + v1 * v1;
        for (int o = 16; o > 0; o >>= 1) {
            s += __shfl_xor_sync(0xffffffffu, s, o);
            ss += __shfl_xor_sync(0xffffffffu, ss, o);
        }
        float mu = s * (1.f / 64.f);
        float var = ss * (1.f / 64.f) - mu * mu;
        float inv = rsqrtf(var + 1e-5f);
        float y0 = (v0 - mu) * inv * vecs[5 * 64 + 2 * lane] + vecs[6 * 64 + 2 * lane];
        float y1 = (v1 - mu) * inv * vecs[5 * 64 + 2 * lane + 1] + vecs[6 * 64 + 2 * lane + 1];
        size_t base = (size_t)(b0 + row) * 4096 + n * 64;
        *(float2*)(xflat_out + base + 2 * lane) = make_float2(y0, y1);
        uint32_t hh, ll; cvt2(y0, y1, hh, ll);
        xfh[(base >> 1) + lane] = hh;
        xfl[(base >> 1) + lane] = ll;
    }
}

// ================= top-5 retrieval + update + fp16 re-emit =================
__global__ void __launch_bounds__(256) retrieve_kernel(const float* __restrict__ mem,
                                                       float* __restrict__ xflat,
                                                       uint2* __restrict__ xfh,
                                                       uint2* __restrict__ xfl) {
    int b = blockIdx.x;
    __shared__ float s[64];
    __shared__ int top[5];
    int tid = threadIdx.x;
    if (tid < 64) s[tid] = g_sim[b * 64 + tid];
    __syncthreads();
    if (tid < 32) {
        for (int k = 0; k < 5; k++) {
            float v = s[tid]; int idx = tid;
            float v2 = s[tid + 32];
            if (v2 > v) { v = v2; idx = tid + 32; }
            for (int o = 16; o > 0; o >>= 1) {
                float ov = __shfl_down_sync(0xffffffffu, v, o);
                int oi = __shfl_down_sync(0xffffffffu, idx, o);
                if (ov > v || (ov == v && oi < idx)) { v = ov; idx = oi; }
            }
            idx = __shfl_sync(0xffffffffu, idx, 0);
            if (tid == 0) top[k] = idx;
            if (tid == 0) s[idx] = -INFINITY;
            __syncwarp();
        }
    }
    __syncthreads();
    const float4* m4 = (const float4*)mem;
    float4* x4 = (float4*)(xflat + (size_t)b * 4096);
    int t0 = top[0] * 1024, t1 = top[1] * 1024, t2 = top[2] * 1024, t3 = top[3] * 1024, t4 = top[4] * 1024;
#pragma unroll
    for (int j = 0; j < 4; j++) {
        int idx = tid + j * 256;
        float4 xv = x4[idx];
        float4 a = m4[t0 + idx], bb = m4[t1 + idx], c = m4[t2 + idx], d = m4[t3 + idx], e = m4[t4 + idx];
        xv.x += 0.02f * (a.x + bb.x + c.x + d.x + e.x);
        xv.y += 0.02f * (a.y + bb.y + c.y + d.y + e.y);
        xv.z += 0.02f * (a.z + bb.z + c.z + d.z + e.z);
        xv.w += 0.02f * (a.w + bb.w + c.w + d.w + e.w);
        x4[idx] = xv;
        uint2 h, l; cvt4(xv, h, l);
        xfh[(size_t)b * 1024 + idx] = h;
        xfl[(size_t)b * 1024 + idx] = l;
    }
}

// ================= proj2: proj[b, 0:8] = relu_s1[b,:] @ Ws2^T + bs2 =================
__global__ void __launch_bounds__(256) proj2_kernel(const float* __restrict__ s1,
                                                    const float* __restrict__ Ws2,
                                                    const float* __restrict__ bs2,
                                                    float* __restrict__ proj) {
    __shared__ float w2s[8 * 1024];
    __shared__ float bss[8];
    int tid = threadIdx.x;
    for (int i = tid; i < 8192; i += 256) w2s[i] = Ws2[i];
    if (tid < 8) bss[tid] = bs2[tid];
    __syncthreads();
    int w = tid >> 5, lane = tid & 31;
    int b = blockIdx.x * 8 + w;
    const float4* row = (const float4*)(s1 + (size_t)b * 1024);
    float4 xv[8];
#pragma unroll
    for (int j = 0; j < 8; j++) xv[j] = row[lane + j * 32];
#pragma unroll
    for (int p = 0; p < 8; p++) {
        const float4* wr = (const float4*)(w2s + p * 1024);
        float acc = 0.f;
#pragma unroll
        for (int j = 0; j < 8; j++) {
            float4 wv = wr[lane + j * 32];
            acc += xv[j].x * wv.x + xv[j].y * wv.y + xv[j].z * wv.z + xv[j].w * wv.w;
        }
        for (int o = 16; o > 0; o >>= 1) acc += __shfl_xor_sync(0xffffffffu, acc, o);
        if (lane == 0) proj[(size_t)b * 8 + p] = acc + bss[p];
    }
}

// ================= launch =================
extern "C" void kernel_launch(void* const* d_in, const int* in_sizes, int n_in,
                              void* d_out, int out_size) {
    const float* x      = (const float*)d_in[0];
    const float* W1     = (const float*)d_in[1];
    const float* b1     = (const float*)d_in[2];
    const float* g1     = (const float*)d_in[3];
    const float* beta1  = (const float*)d_in[4];
    const float* W2     = (const float*)d_in[5];
    const float* b2     = (const float*)d_in[6];
    const float* edge_w = (const float*)d_in[7];
    const float* mask   = (const float*)d_in[8];
    const float* Wi     = (const float*)d_in[9];
    const float* bi     = (const float*)d_in[10];
    const float* Wf     = (const float*)d_in[11];
    const float* bf     = (const float*)d_in[12];
    const float* Wslow  = (const float*)d_in[13];
    const float* bslow  = (const float*)d_in[14];
    const float* u      = (const float*)d_in[15];
    const float* Wfast  = (const float*)d_in[16];
    const float* Wo     = (const float*)d_in[17];
    const float* bo     = (const float*)d_in[18];
    const float* gln    = (const float*)d_in[19];
    const float* bln    = (const float*)d_in[20];
    const float* h_prev = (const float*)d_in[21];
    const float* memory = (const float*)d_in[22];
    const float* Wh     = (const float*)d_in[23];
    const float* bh     = (const float*)d_in[24];
    const float* Ws1    = (const float*)d_in[25];
    const float* bs1    = (const float*)d_in[26];
    const float* Ws2    = (const float*)d_in[27];
    const float* bs2    = (const float*)d_in[28];

    float* out    = (float*)d_out;
    float* logits = out;
    float* proj   = out + (size_t)Bn * Ccls;
    float* xflat  = proj + (size_t)Bn * Pp;

    float *p_h1, *p_b2a, *p_xagg, *p_sim, *p_s1, *p_bhm;
    cudaGetSymbolAddress((void**)&p_h1, g_h1);
    cudaGetSymbolAddress((void**)&p_b2a, g_b2a);
    cudaGetSymbolAddress((void**)&p_xagg, g_xagg);
    cudaGetSymbolAddress((void**)&p_sim, g_sim);
    cudaGetSymbolAddress((void**)&p_s1, g_s1);
    cudaGetSymbolAddress((void**)&p_bhm, g_bhm);
    void *p_xh, *p_xl, *p_W1h, *p_W1l, *p_h1h, *p_h1l, *p_W2h, *p_W2l;
    void *p_xfh, *p_xfl, *p_Whmh, *p_Whml, *p_Ws1h, *p_Ws1l, *p_memh, *p_meml;
    cudaGetSymbolAddress(&p_xh, g_xh);   cudaGetSymbolAddress(&p_xl, g_xl);
    cudaGetSymbolAddress(&p_W1h, g_W1h); cudaGetSymbolAddress(&p_W1l, g_W1l);
    cudaGetSymbolAddress(&p_h1h, g_h1h); cudaGetSymbolAddress(&p_h1l, g_h1l);
    cudaGetSymbolAddress(&p_W2h, g_W2h); cudaGetSymbolAddress(&p_W2l, g_W2l);
    cudaGetSymbolAddress(&p_xfh, g_xfh); cudaGetSymbolAddress(&p_xfl, g_xfl);
    cudaGetSymbolAddress(&p_Whmh, g_Whmh); cudaGetSymbolAddress(&p_Whml, g_Whml);
    cudaGetSymbolAddress(&p_Ws1h, g_Ws1h); cudaGetSymbolAddress(&p_Ws1l, g_Ws1l);
    cudaGetSymbolAddress(&p_memh, g_memh); cudaGetSymbolAddress(&p_meml, g_meml);

    cudaFuncSetAttribute(cell_kernel, cudaFuncAttributeMaxDynamicSharedMemorySize, CELL_SMEM);
    cudaFuncSetAttribute(gemm_mma<4, true>,  cudaFuncAttributeMaxDynamicSharedMemorySize, GSMEM_TOTAL);
    cudaFuncSetAttribute(gemm_mma<4, false>, cudaFuncAttributeMaxDynamicSharedMemorySize, GSMEM_TOTAL);
    cudaFuncSetAttribute(gemm_mma<2, true>,  cudaFuncAttributeMaxDynamicSharedMemorySize, GSMEM_TOTAL);

    // prep + conversions
    prep_adj<<<1, 64>>>(edge_w, mask);
    fold_w2<<<dim3(8, 64), 256>>>(W2);
    prep_b2a<<<64, 64>>>(b2);
    prep_node<<<64, 64>>>(Wslow, u, Wfast, Wf, bf, h_prev);
    prep_whm_bf<<<(1024 * FLAT / 4 + 255) / 256, 256>>>(Wh);
    prep_bhm<<<4, 256>>>(bh);
    cvt_hilo<<<(Bn * Fdim / 4 + 255) / 256, 256>>>(x, (uint2*)p_xh, (uint2*)p_xl, Bn * Fdim / 4);
    cvt_hilo<<<(Hdim * Fdim / 4 + 255) / 256, 256>>>(W1, (uint2*)p_W1h, (uint2*)p_W1l, Hdim * Fdim / 4);
    cvt_hilo<<<(Hdim * FLAT / 4 + 255) / 256, 256>>>(Ws1, (uint2*)p_Ws1h, (uint2*)p_Ws1l, Hdim * FLAT / 4);
    cvt_mem_pad<<<(128 * FLAT / 4 + 255) / 256, 256>>>(memory);

    // stage 1: input projection; gemm2 emits x_agg directly (adj folded)
    gemm_mma<4, true><<<dim3(Hdim / 128, Bn / 128), 256, GSMEM_TOTAL>>>(
        (const __half*)p_xh, (const __half*)p_xl,
        (const __half*)p_W1h, (const __half*)p_W1l, b1, p_h1,
        Fdim, Fdim, Hdim, 0, 0);
    ln_gelu_kernel<<<Bn, 256>>>(p_h1, g1, beta1, (uint2*)p_h1h, (uint2*)p_h1l);
    gemm_mma<4, true><<<dim3(FLAT / 128, Bn / 128), 256, GSMEM_TOTAL>>>(
        (const __half*)p_h1h, (const __half*)p_h1l,
        (const __half*)p_W2h, (const __half*)p_W2l, p_b2a, p_xagg,
        Hdim, Hdim, FLAT, 0, 0);

    // stage 2: cells
    cell_kernel<<<dim3(Nn, Bn / 64), 256, CELL_SMEM>>>(Wi, Wf, Wo, bi, bslow, bo,
                                                       h_prev, gln, bln, xflat,
                                                       (uint32_t*)p_xfh, (uint32_t*)p_xfl);

    // stage 3: retrieval (split-K sim GEMM, atomic accumulate)
    zero_sim<<<Bn * CAP / 256, 256>>>();
    gemm_mma<2, true><<<dim3(1, Bn / 128, 4), 256, GSMEM_TOTAL>>>(
        (const __half*)p_xfh, (const __half*)p_xfl,
        (const __half*)p_memh, (const __half*)p_meml, nullptr, p_sim,
        FLAT / 4, FLAT, CAP, 0, 1);
    retrieve_kernel<<<Bn, 256>>>(memory, xflat, (uint2*)p_xfh, (uint2*)p_xfl);

    // stage 4: heads (2-pass fp16)
    gemm_mma<4, false><<<dim3(1024 / 128, Bn / 128), 256, GSMEM_TOTAL>>>(
        (const __half*)p_xfh, nullptr,
        (const __half*)p_Whmh, (const __half*)p_Whml, p_bhm, logits,
        FLAT, FLAT, Ccls, 0, 0);
    gemm_mma<4, false><<<dim3(Hdim / 128, Bn / 128), 256, GSMEM_TOTAL>>>(
        (const __half*)p_xfh, nullptr,
        (const __half*)p_Ws1h, (const __half*)p_Ws1l, bs1, p_s1,
        FLAT, FLAT, Hdim, 1, 0);
    proj2_kernel<<<Bn / 8, 256>>>(p_s1, Ws2, bs2, proj);
}

// round 11
// speedup vs baseline: 1.3497x; 1.1585x over previous
#include <cuda_runtime.h>
#include <cuda_fp16.h>
#include <math.h>
#include <stdint.h>

#define Bn 4096
#define Fdim 512
#define Hdim 1024
#define Nn 64
#define Dd 64
#define FLAT 4096
#define Ccls 1000
#define CAP 64
#define Pp 8

// ================= scratch (device globals) =================
__device__ float g_h1[Bn * Hdim];
__device__ float g_b2a[FLAT];
__device__ float g_xagg[(size_t)Bn * FLAT];
__device__ float g_sim[Bn * CAP];
__device__ float g_s1[Bn * Hdim];
__device__ float g_bhm[1024];
__device__ float g_adj[Nn * Nn];
__device__ float g_WcT[Nn * Dd * Dd];
__device__ float g_cf[Nn * Dd];
// fp16 hi/lo operand buffers
__device__ __half g_xh[Bn * Fdim],    g_xl[Bn * Fdim];
__device__ __half g_W1h[Hdim * Fdim], g_W1l[Hdim * Fdim];
__device__ __half g_h1h[Bn * Hdim],   g_h1l[Bn * Hdim];
__device__ __half g_W2h[FLAT * Hdim], g_W2l[FLAT * Hdim];
__device__ __half g_xfh[(size_t)Bn * FLAT], g_xfl[(size_t)Bn * FLAT];
__device__ __half g_Whmh[1024 * FLAT], g_Whml[1024 * FLAT];
__device__ __half g_Ws1h[Hdim * FLAT], g_Ws1l[Hdim * FLAT];
__device__ __half g_memh[128 * FLAT], g_meml[128 * FLAT];

__device__ __forceinline__ float sigmoidf_(float x) { return 1.f / (1.f + expf(-x)); }

__device__ __forceinline__ uint32_t pack2h(__half a, __half b) {
    return (uint32_t)__half_as_ushort(a) | ((uint32_t)__half_as_ushort(b) << 16);
}
__device__ __forceinline__ void cvt4(float4 v, uint2& hi, uint2& lo) {
    __half h0 = __float2half_rn(v.x), h1 = __float2half_rn(v.y);
    __half h2 = __float2half_rn(v.z), h3 = __float2half_rn(v.w);
    __half l0 = __float2half_rn(v.x - __half2float(h0));
    __half l1 = __float2half_rn(v.y - __half2float(h1));
    __half l2 = __float2half_rn(v.z - __half2float(h2));
    __half l3 = __float2half_rn(v.w - __half2float(h3));
    hi.x = pack2h(h0, h1); hi.y = pack2h(h2, h3);
    lo.x = pack2h(l0, l1); lo.y = pack2h(l2, l3);
}
__device__ __forceinline__ void cvt2(float a, float b, uint32_t& hi, uint32_t& lo) {
    __half h0 = __float2half_rn(a), h1 = __float2half_rn(b);
    __half l0 = __float2half_rn(a - __half2float(h0));
    __half l1 = __float2half_rn(b - __half2float(h1));
    hi = pack2h(h0, h1); lo = pack2h(l0, l1);
}

// ================= mma / cp.async / ldmatrix primitives =================
__device__ __forceinline__ uint32_t smem_u32(const void* p) {
    uint32_t a;
    asm("{ .reg .u64 t; cvta.to.shared.u64 t, %1; cvt.u32.u64 %0, t; }" : "=r"(a) : "l"(p));
    return a;
}
__device__ __forceinline__ void cp16(uint32_t s, const void* g) {
    asm volatile("cp.async.cg.shared.global [%0], [%1], 16;" :: "r"(s), "l"(g));
}
#define CP_COMMIT() asm volatile("cp.async.commit_group;")
#define CP_WAIT1() asm volatile("cp.async.wait_group 1;")

__device__ __forceinline__ void mma16816(float* d, const uint32_t* a, uint32_t b0, uint32_t b1) {
    asm volatile(
        "mma.sync.aligned.m16n8k16.row.col.f32.f16.f16.f32 "
        "{%0,%1,%2,%3}, {%4,%5,%6,%7}, {%8,%9}, {%0,%1,%2,%3};"
        : "+f"(d[0]), "+f"(d[1]), "+f"(d[2]), "+f"(d[3])
        : "r"(a[0]), "r"(a[1]), "r"(a[2]), "r"(a[3]), "r"(b0), "r"(b1));
}
__device__ __forceinline__ void ldsm_x4(uint32_t& r0, uint32_t& r1, uint32_t& r2, uint32_t& r3,
                                        uint32_t addr) {
    asm volatile("ldmatrix.sync.aligned.m8n8.x4.shared.b16 {%0,%1,%2,%3}, [%4];"
                 : "=r"(r0), "=r"(r1), "=r"(r2), "=r"(r3) : "r"(addr));
}

// ================= conversion kernels =================
__global__ void cvt_hilo(const float* __restrict__ src, uint2* __restrict__ hi,
                         uint2* __restrict__ lo, int n4) {
    int i = blockIdx.x * 256 + threadIdx.x;
    if (i < n4) {
        float4 v = ((const float4*)src)[i];
        uint2 h, l; cvt4(v, h, l);
        hi[i] = h; lo[i] = l;
    }
}
__global__ void cvt_mem_pad(const float* __restrict__ mem) {
    int i = blockIdx.x * 256 + threadIdx.x;
    if (i >= 128 * FLAT / 4) return;
    int row = i >> 10;
    uint2 h = make_uint2(0u, 0u), l = make_uint2(0u, 0u);
    if (row < CAP) {
        float4 v = ((const float4*)mem)[i];
        cvt4(v, h, l);
    }
    ((uint2*)g_memh)[i] = h; ((uint2*)g_meml)[i] = l;
}

// ================= prep kernels =================
__global__ void prep_adj(const float* __restrict__ edge_w, const float* __restrict__ mask) {
    __shared__ float t[64 * 64];
    int r = threadIdx.x;
    float sum = 0.f;
    for (int c = 0; c < 64; c++) {
        float v = sigmoidf_(edge_w[r * 64 + c] * 1.5f) * mask[r * 64 + c];
        t[r * 64 + c] = v; sum += v;
    }
    float inv = 1.f / fmaxf(sum, 1e-6f);
    for (int c = 0; c < 64; c++) g_adj[r * 64 + c] = t[r * 64 + c] * inv;
}

// fold adjacency into W2, emit fp16 hi/lo
__global__ void __launch_bounds__(256) fold_w2(const float* __restrict__ W2) {
    int kt = blockIdx.x;
    int d  = blockIdx.y;
    __shared__ float tile[64][128];
    __shared__ float adjT[64 * 64];
    int tid = threadIdx.x;
    for (int i = tid; i < 4096; i += 256) {
        int m = i >> 6, n = i & 63;
        adjT[i] = g_adj[n * 64 + m];
    }
    for (int i = tid; i < 64 * 32; i += 256) {
        int m = i >> 5, c4 = (i & 31) << 2;
        *(float4*)&tile[m][c4] = *(const float4*)(W2 + (size_t)(m * 64 + d) * Hdim + kt * 128 + c4);
    }
    __syncthreads();
    int n = tid & 63;
    int kq = tid >> 6;
    float4 acc[8];
#pragma unroll
    for (int q = 0; q < 8; q++) acc[q] = make_float4(0.f, 0.f, 0.f, 0.f);
    for (int m = 0; m < 64; m++) {
        float s = adjT[m * 64 + n];
        const float4* trow = (const float4*)&tile[m][kq * 32];
#pragma unroll
        for (int q = 0; q < 8; q++) {
            float4 t4 = trow[q];
            acc[q].x += s * t4.x; acc[q].y += s * t4.y;
            acc[q].z += s * t4.z; acc[q].w += s * t4.w;
        }
    }
    size_t off4 = ((size_t)(n * 64 + d) * Hdim + kt * 128 + kq * 32) >> 2;
#pragma unroll
    for (int q = 0; q < 8; q++) {
        uint2 h, l; cvt4(acc[q], h, l);
        ((uint2*)g_W2h)[off4 + q] = h;
        ((uint2*)g_W2l)[off4 + q] = l;
    }
}
__global__ void prep_b2a(const float* __restrict__ b2) {
    int nd = blockIdx.x * 64 + threadIdx.x;
    int n = nd >> 6, d = nd & 63;
    float acc = 0.f;
    for (int m = 0; m < 64; m++) acc += g_adj[n * 64 + m] * b2[m * 64 + d];
    g_b2a[nd] = acc;
}

__global__ void prep_node(const float* __restrict__ Wslow, const float* __restrict__ u,
                          const float* __restrict__ Wfast, const float* __restrict__ Wf,
                          const float* __restrict__ bf, const float* __restrict__ hprev) {
    int n = blockIdx.x;
    int t = threadIdx.x;
    __shared__ float us[64], v[64], red[64];
    const float* Ws = Wslow + (size_t)n * 4096;
    us[t] = u[n * 64 + t];
    __syncthreads();
    float acc = 0.f;
    for (int o = 0; o < 64; o++) acc += Ws[o * 64 + t] * us[o];
    v[t] = acc;
    __syncthreads();
    float wv = 0.f;
    for (int i = 0; i < 64; i++) wv += Ws[t * 64 + i] * v[i];
    red[t] = us[t] * wv;
    __syncthreads();
    for (int off = 32; off > 0; off >>= 1) {
        if (t < off) red[t] += red[t + off];
        __syncthreads();
    }
    float inv = 1.f / (red[0] + 1e-8f);
    const float* Wfa = Wfast + (size_t)n * 4096;
    float* out = g_WcT + (size_t)n * 4096;
    for (int idx = t; idx < 4096; idx += 64) {
        int i = idx >> 6, o = idx & 63;
        out[idx] = Ws[o * 64 + i] * inv + Wfa[o * 64 + i];
    }
    float c = bf[n * 64 + t];
    const float* Wf2 = Wf + (size_t)n * 8192 + 4096;
    for (int i = 0; i < 64; i++) c += hprev[n * 64 + i] * Wf2[i * 64 + t];
    g_cf[n * 64 + t] = c;
}

__global__ void prep_whm_bf(const float* __restrict__ Wh) {
    int i = blockIdx.x * 256 + threadIdx.x;
    if (i >= (1024 * FLAT) / 4) return;
    int row = i >> 10;
    uint2 h, l;
    if (row < Ccls) {
        const size_t CF4 = (size_t)Ccls * FLAT / 4;
        const float4* W4 = (const float4*)Wh;
        float4 a = W4[i], b = W4[i + CF4], c = W4[i + 2 * CF4];
        float4 m = make_float4((a.x + b.x + c.x) * (1.f / 3.f), (a.y + b.y + c.y) * (1.f / 3.f),
                               (a.z + b.z + c.z) * (1.f / 3.f), (a.w + b.w + c.w) * (1.f / 3.f));
        cvt4(m, h, l);
    } else {
        h = make_uint2(0u, 0u); l = make_uint2(0u, 0u);
    }
    ((uint2*)g_Whmh)[i] = h; ((uint2*)g_Whml)[i] = l;
}
__global__ void prep_bhm(const float* __restrict__ bh) {
    int i = blockIdx.x * 256 + threadIdx.x;
    if (i < 1024) g_bhm[i] = (i < Ccls) ? (bh[i] + bh[i + Ccls] + bh[i + 2 * Ccls]) * (1.f / 3.f) : 0.f;
}
__global__ void zero_sim() {
    g_sim[blockIdx.x * 256 + threadIdx.x] = 0.f;
}

// ================= split-fp16 HMMA GEMM =================
// PASSES: 3 = Ah*Bh + Ah*Bl + Al*Bh; 2 = Ah*Bh + Ah*Bl; 1 = Ah*Bh only.
#define TSTRIDE 40
#define ROWB (TSTRIDE * 2)
#define TILE_B (128 * ROWB)
#define STAGE_B (4 * TILE_B)
#define GSMEM_TOTAL (2 * STAGE_B)

template <int NI, int PASSES>
__global__ void __launch_bounds__(256, 2) gemm_mma(
    const __half* __restrict__ Ahi, const __half* __restrict__ Alo,
    const __half* __restrict__ Bhi, const __half* __restrict__ Blo,
    const float* __restrict__ bias, float* __restrict__ C,
    int K, int lda, int Nstore, int act, int atomicOut) {
    extern __shared__ char smem[];
    const int tid = threadIdx.x;
    const int wid = tid >> 5;
    const int lane = tid & 31;
    const int grp = lane >> 2;
    const int qp = lane & 3;
    const int wm = (wid >> 2) * 64;
    const int wn = (wid & 3) * (NI * 8);
    const int bm = blockIdx.y * 128;
    const int bn = blockIdx.x * 128;
    const int kbase = blockIdx.z * K;
    const uint32_t sb = smem_u32(smem);

    const int row = tid >> 2;
    const int c16 = tid & 3;

    const int aRowL = wm + (lane & 7) + ((lane >> 3) & 1) * 8;
    const int aKL = (lane >> 4) * 8;
    const int bRowL = wn + (lane & 7) + (lane >> 4) * 8;
    const int bKL = ((lane >> 3) & 1) * 8;

    float acc[4][NI][4];
#pragma unroll
    for (int mi = 0; mi < 4; mi++)
#pragma unroll
        for (int ni = 0; ni < NI; ni++)
#pragma unroll
            for (int j = 0; j < 4; j++) acc[mi][ni][j] = 0.f;

    const int nc = K >> 5;

    auto issue = [&](int c, int s) {
        const uint32_t ss = sb + s * STAGE_B;
        const int k0 = c << 5;
#pragma unroll
        for (int t = 0; t < 2; t++) {
            const int r = row + t * 64;
            const uint32_t so = (uint32_t)r * ROWB + c16 * 16;
            const size_t gAoff = ((size_t)(bm + r) * lda + kbase + k0) * 2 + c16 * 16;
            const size_t gBoff = ((size_t)(bn + r) * lda + kbase + k0) * 2 + c16 * 16;
            cp16(ss + 0 * TILE_B + so, (const char*)Ahi + gAoff);
            if (PASSES == 3) cp16(ss + 1 * TILE_B + so, (const char*)Alo + gAoff);
            cp16(ss + 2 * TILE_B + so, (const char*)Bhi + gBoff);
            if (PASSES >= 2) cp16(ss + 3 * TILE_B + so, (const char*)Blo + gBoff);
        }
    };

    issue(0, 0); CP_COMMIT();
    if (nc > 1) issue(1, 1);
    CP_COMMIT();

    for (int c = 0; c < nc; c++) {
        const int s = c & 1;
        CP_WAIT1();
        __syncthreads();
        const uint32_t st = sb + s * STAGE_B;
#pragma unroll
        for (int ks = 0; ks < 2; ks++) {
            const int k0 = ks * 16;
            uint32_t ah[4][4], al[4][4];
#pragma unroll
            for (int mi = 0; mi < 4; mi++) {
                const uint32_t ad = st + (uint32_t)(aRowL + mi * 16) * ROWB + (k0 + aKL) * 2;
                ldsm_x4(ah[mi][0], ah[mi][1], ah[mi][2], ah[mi][3], ad);
                if (PASSES == 3) ldsm_x4(al[mi][0], al[mi][1], al[mi][2], al[mi][3], ad + TILE_B);
            }
            uint32_t bh[NI][2], bl[NI][2];
#pragma unroll
            for (int p = 0; p < NI / 2; p++) {
                const uint32_t bd = st + 2 * TILE_B + (uint32_t)(bRowL + p * 16) * ROWB + (k0 + bKL) * 2;
                uint32_t r0, r1, r2, r3;
                ldsm_x4(r0, r1, r2, r3, bd);
                bh[2 * p][0] = r0; bh[2 * p][1] = r1; bh[2 * p + 1][0] = r2; bh[2 * p + 1][1] = r3;
                if (PASSES >= 2) {
                    ldsm_x4(r0, r1, r2, r3, bd + TILE_B);
                    bl[2 * p][0] = r0; bl[2 * p][1] = r1; bl[2 * p + 1][0] = r2; bl[2 * p + 1][1] = r3;
                }
            }
#pragma unroll
            for (int ni = 0; ni < NI; ni++) {
#pragma unroll
                for (int mi = 0; mi < 4; mi++) {
                    mma16816(acc[mi][ni], ah[mi], bh[ni][0], bh[ni][1]);
                    if (PASSES >= 2) mma16816(acc[mi][ni], ah[mi], bl[ni][0], bl[ni][1]);
                    if (PASSES == 3) mma16816(acc[mi][ni], al[mi], bh[ni][0], bh[ni][1]);
                }
            }
        }
        __syncthreads();
        if (c + 2 < nc) issue(c + 2, s);
        CP_COMMIT();
    }

    // epilogue
#pragma unroll
    for (int mi = 0; mi < 4; mi++) {
#pragma unroll
        for (int ni = 0; ni < NI; ni++) {
            const int r0 = bm + wm + mi * 16 + grp;
            const int col = bn + wn + ni * 8 + qp * 2;
            float* a4 = acc[mi][ni];
            if (atomicOut) {
                if (col < Nstore) {
                    atomicAdd(&C[(size_t)r0 * Nstore + col], a4[0]);
                    atomicAdd(&C[(size_t)(r0 + 8) * Nstore + col], a4[2]);
                    if (col + 1 < Nstore) {
                        atomicAdd(&C[(size_t)r0 * Nstore + col + 1], a4[1]);
                        atomicAdd(&C[(size_t)(r0 + 8) * Nstore + col + 1], a4[3]);
                    }
                }
            } else if (col + 1 < Nstore) {
                float2 v0, v1;
                float bb0 = bias ? bias[col] : 0.f;
                float bb1 = bias ? bias[col + 1] : 0.f;
                v0.x = a4[0] + bb0; v0.y = a4[1] + bb1;
                v1.x = a4[2] + bb0; v1.y = a4[3] + bb1;
                if (act == 1) {
                    v0.x = fmaxf(v0.x, 0.f); v0.y = fmaxf(v0.y, 0.f);
                    v1.x = fmaxf(v1.x, 0.f); v1.y = fmaxf(v1.y, 0.f);
                }
                *(float2*)(C + (size_t)r0 * Nstore + col) = v0;
                *(float2*)(C + (size_t)(r0 + 8) * Nstore + col) = v1;
            } else if (col < Nstore) {
                float bb0 = bias ? bias[col] : 0.f;
                float v0 = a4[0] + bb0, v1 = a4[2] + bb0;
                if (act == 1) { v0 = fmaxf(v0, 0.f); v1 = fmaxf(v1, 0.f); }
                C[(size_t)r0 * Nstore + col] = v0;
                C[(size_t)(r0 + 8) * Nstore + col] = v1;
            }
        }
    }
}

// ================= LayerNorm(H=1024) + GELU -> fp16 hi/lo =================
__global__ void __launch_bounds__(256) ln_gelu_kernel(const float* __restrict__ h,
                                                      const float* __restrict__ g,
                                                      const float* __restrict__ beta,
                                                      uint2* __restrict__ hi,
                                                      uint2* __restrict__ lo) {
    int row = blockIdx.x;
    const float* hr = h + (size_t)row * Hdim;
    int tid = threadIdx.x;
    float4 v = *(const float4*)(hr + tid * 4);
    float s = v.x + v.y + v.z + v.w;
    float ss = v.x * v.x + v.y * v.y + v.z * v.z + v.w * v.w;
    __shared__ float rs[8], rss[8];
    for (int o = 16; o > 0; o >>= 1) {
        s += __shfl_down_sync(0xffffffffu, s, o);
        ss += __shfl_down_sync(0xffffffffu, ss, o);
    }
    if ((tid & 31) == 0) { rs[tid >> 5] = s; rss[tid >> 5] = ss; }
    __syncthreads();
    if (tid < 32) {
        float a = tid < 8 ? rs[tid] : 0.f;
        float b = tid < 8 ? rss[tid] : 0.f;
        for (int o = 4; o > 0; o >>= 1) {
            a += __shfl_down_sync(0xffffffffu, a, o);
            b += __shfl_down_sync(0xffffffffu, b, o);
        }
        if (tid == 0) { rs[0] = a; rss[0] = b; }
    }
    __syncthreads();
    float mu = rs[0] * (1.f / Hdim);
    float var = rss[0] * (1.f / Hdim) - mu * mu;
    float inv = rsqrtf(var + 1e-5f);
    float4 gg = *(const float4*)(g + tid * 4);
    float4 bb = *(const float4*)(beta + tid * 4);
    float y;
    y = (v.x - mu) * inv * gg.x + bb.x; v.x = 0.5f * y * (1.f + erff(y * 0.70710678118654752f));
    y = (v.y - mu) * inv * gg.y + bb.y; v.y = 0.5f * y * (1.f + erff(y * 0.70710678118654752f));
    y = (v.z - mu) * inv * gg.z + bb.z; v.z = 0.5f * y * (1.f + erff(y * 0.70710678118654752f));
    y = (v.w - mu) * inv * gg.w + bb.w; v.w = 0.5f * y * (1.f + erff(y * 0.70710678118654752f));
    uint2 hh, ll; cvt4(v, hh, ll);
    hi[(size_t)row * 256 + tid] = hh;
    lo[(size_t)row * 256 + tid] = ll;
}

// ================= fused cell kernel (emits fp16 hi/lo of xflat) =================
#define CELL_SMEM ((64 * 68 * 2 + 4096 * 4 + 7 * 64) * sizeof(float))
__global__ void __launch_bounds__(256) cell_kernel(const float* __restrict__ Wi,
                                                   const float* __restrict__ Wf,
                                                   const float* __restrict__ Wo,
                                                   const float* __restrict__ bi_g,
                                                   const float* __restrict__ bslow_g,
                                                   const float* __restrict__ bo_g,
                                                   const float* __restrict__ hprev_g,
                                                   const float* __restrict__ gln_g,
                                                   const float* __restrict__ bln_g,
                                                   float* __restrict__ xflat_out,
                                                   uint32_t* __restrict__ xfh,
                                                   uint32_t* __restrict__ xfl) {
    extern __shared__ float sf[];
    float* xs = sf;
    float* wi = xs + 64 * 68;
    float* wf = wi + 4096;
    float* wc = wf + 4096;
    float* wo = wc + 4096;
    float* hr = wo + 4096;
    float* vecs = hr + 64 * 68;

    int n = blockIdx.x;
    int b0 = blockIdx.y * 64;
    int tid = threadIdx.x;

#pragma unroll
    for (int j = 0; j < 4; j++) {
        int idx = tid + j * 256;
        int row = idx >> 4, c4 = (idx & 15) << 2;
        *(float4*)(xs + row * 68 + c4) =
            *(const float4*)(g_xagg + (((size_t)(b0 + row) * 64 + n) << 6) + c4);
        ((float4*)wi)[idx] = ((const float4*)(Wi + (size_t)n * 4096))[idx];
        ((float4*)wf)[idx] = ((const float4*)(Wf + (size_t)n * 8192))[idx];
        ((float4*)wc)[idx] = ((const float4*)(g_WcT + (size_t)n * 4096))[idx];
        ((float4*)wo)[idx] = ((const float4*)(Wo + (size_t)n * 4096))[idx];
    }
    if (tid < 64) {
        vecs[0 * 64 + tid] = bi_g[n * 64 + tid];
        vecs[1 * 64 + tid] = g_cf[n * 64 + tid];
        vecs[2 * 64 + tid] = bslow_g[n * 64 + tid];
        vecs[3 * 64 + tid] = bo_g[n * 64 + tid];
        vecs[4 * 64 + tid] = hprev_g[n * 64 + tid];
        vecs[5 * 64 + tid] = gln_g[n * 64 + tid];
        vecs[6 * 64 + tid] = bln_g[n * 64 + tid];
    }
    __syncthreads();

    const int r0 = (tid >> 4) * 4;
    const int c0 = (tid & 15) * 4;

    float ai[4][4], af[4][4], ac[4][4];
#pragma unroll
    for (int r = 0; r < 4; r++)
#pragma unroll
        for (int c = 0; c < 4; c++) { ai[r][c] = 0.f; af[r][c] = 0.f; ac[r][c] = 0.f; }

    for (int i = 0; i < 64; i++) {
        float xv[4];
#pragma unroll
        for (int r = 0; r < 4; r++) xv[r] = xs[(r0 + r) * 68 + i];
        float4 w1 = *(const float4*)(wi + i * 64 + c0);
        float4 w2 = *(const float4*)(wf + i * 64 + c0);
        float4 w3 = *(const float4*)(wc + i * 64 + c0);
#pragma unroll
        for (int r = 0; r < 4; r++) {
            ai[r][0] += xv[r] * w1.x; ai[r][1] += xv[r] * w1.y; ai[r][2] += xv[r] * w1.z; ai[r][3] += xv[r] * w1.w;
            af[r][0] += xv[r] * w2.x; af[r][1] += xv[r] * w2.y; af[r][2] += xv[r] * w2.z; af[r][3] += xv[r] * w2.w;
            ac[r][0] += xv[r] * w3.x; ac[r][1] += xv[r] * w3.y; ac[r][2] += xv[r] * w3.z; ac[r][3] += xv[r] * w3.w;
        }
    }
#pragma unroll
    for (int r = 0; r < 4; r++)
#pragma unroll
        for (int c = 0; c < 4; c++) {
            int o = c0 + c;
            float it = sigmoidf_(ai[r][c] + vecs[0 * 64 + o]);
            float ft = sigmoidf_(af[r][c] + vecs[1 * 64 + o]);
            float hs = ac[r][c] + vecs[2 * 64 + o];
            hr[(r0 + r) * 68 + o] = it * hs + ft * vecs[4 * 64 + o];
        }
    __syncthreads();

    float ao[4][4];
#pragma unroll
    for (int r = 0; r < 4; r++)
#pragma unroll
        for (int c = 0; c < 4; c++) ao[r][c] = 0.f;
    for (int i = 0; i < 64; i++) {
        float xv[4];
#pragma unroll
        for (int r = 0; r < 4; r++) xv[r] = hr[(r0 + r) * 68 + i];
        float4 w = *(const float4*)(wo + i * 64 + c0);
#pragma unroll
        for (int r = 0; r < 4; r++) {
            ao[r][0] += xv[r] * w.x; ao[r][1] += xv[r] * w.y;
            ao[r][2] += xv[r] * w.z; ao[r][3] += xv[r] * w.w;
        }
    }
    float* ys = xs;
#pragma unroll
    for (int r = 0; r < 4; r++)
#pragma unroll
        for (int c = 0; c < 4; c++) {
            int o = c0 + c;
            float ot = sigmoidf_(ao[r][c] + vecs[3 * 64 + o]);
            ys[(r0 + r) * 68 + o] = ot * tanhf(hr[(r0 + r) * 68 + o]);
        }
    __syncthreads();

    int w = tid >> 5, lane = tid & 31;
    for (int rr = 0; rr < 8; rr++) {
        int row = w * 8 + rr;
        float v0 = ys[row * 68 + 2 * lane];
        float v1 = ys[row * 68 + 2 * lane + 1];
        float s = v0 + v1;
        float ss = v0 * v0 + v1 * v1;
        for (int o = 16; o > 0; o >>= 1) {
            s += __shfl_xor_sync(0xffffffffu, s, o);
            ss += __shfl_xor_sync(0xffffffffu, ss, o);
        }
        float mu = s * (1.f / 64.f);
        float var = ss * (1.f / 64.f) - mu * mu;
        float inv = rsqrtf(var + 1e-5f);
        float y0 = (v0 - mu) * inv * vecs[5 * 64 + 2 * lane] + vecs[6 * 64 + 2 * lane];
        float y1 = (v1 - mu) * inv * vecs[5 * 64 + 2 * lane + 1] + vecs[6 * 64 + 2 * lane + 1];
        size_t base = (size_t)(b0 + row) * 4096 + n * 64;
        *(float2*)(xflat_out + base + 2 * lane) = make_float2(y0, y1);
        uint32_t hh, ll; cvt2(y0, y1, hh, ll);
        xfh[(base >> 1) + lane] = hh;
        xfl[(base >> 1) + lane] = ll;
    }
}

// ================= top-5 retrieval + update + fp16 re-emit =================
__global__ void __launch_bounds__(256) retrieve_kernel(const float* __restrict__ mem,
                                                       float* __restrict__ xflat,
                                                       uint2* __restrict__ xfh,
                                                       uint2* __restrict__ xfl) {
    int b = blockIdx.x;
    __shared__ float s[64];
    __shared__ int top[5];
    int tid = threadIdx.x;
    if (tid < 64) s[tid] = g_sim[b * 64 + tid];
    __syncthreads();
    if (tid < 32) {
        for (int k = 0; k < 5; k++) {
            float v = s[tid]; int idx = tid;
            float v2 = s[tid + 32];
            if (v2 > v) { v = v2; idx = tid + 32; }
            for (int o = 16; o > 0; o >>= 1) {
                float ov = __shfl_down_sync(0xffffffffu, v, o);
                int oi = __shfl_down_sync(0xffffffffu, idx, o);
                if (ov > v || (ov == v && oi < idx)) { v = ov; idx = oi; }
            }
            idx = __shfl_sync(0xffffffffu, idx, 0);
            if (tid == 0) top[k] = idx;
            if (tid == 0) s[idx] = -INFINITY;
            __syncwarp();
        }
    }
    __syncthreads();
    const float4* m4 = (const float4*)mem;
    float4* x4 = (float4*)(xflat + (size_t)b * 4096);
    int t0 = top[0] * 1024, t1 = top[1] * 1024, t2 = top[2] * 1024, t3 = top[3] * 1024, t4 = top[4] * 1024;
#pragma unroll
    for (int j = 0; j < 4; j++) {
        int idx = tid + j * 256;
        float4 xv = x4[idx];
        float4 a = m4[t0 + idx], bb = m4[t1 + idx], c = m4[t2 + idx], d = m4[t3 + idx], e = m4[t4 + idx];
        xv.x += 0.02f * (a.x + bb.x + c.x + d.x + e.x);
        xv.y += 0.02f * (a.y + bb.y + c.y + d.y + e.y);
        xv.z += 0.02f * (a.z + bb.z + c.z + d.z + e.z);
        xv.w += 0.02f * (a.w + bb.w + c.w + d.w + e.w);
        x4[idx] = xv;
        uint2 h, l; cvt4(xv, h, l);
        xfh[(size_t)b * 1024 + idx] = h;
        xfl[(size_t)b * 1024 + idx] = l;
    }
}

// ================= proj2: proj[b, 0:8] = relu_s1[b,:] @ Ws2^T + bs2 =================
__global__ void __launch_bounds__(256) proj2_kernel(const float* __restrict__ s1,
                                                    const float* __restrict__ Ws2,
                                                    const float* __restrict__ bs2,
                                                    float* __restrict__ proj) {
    __shared__ float w2s[8 * 1024];
    __shared__ float bss[8];
    int tid = threadIdx.x;
    for (int i = tid; i < 8192; i += 256) w2s[i] = Ws2[i];
    if (tid < 8) bss[tid] = bs2[tid];
    __syncthreads();
    int w = tid >> 5, lane = tid & 31;
    int b = blockIdx.x * 8 + w;
    const float4* row = (const float4*)(s1 + (size_t)b * 1024);
    float4 xv[8];
#pragma unroll
    for (int j = 0; j < 8; j++) xv[j] = row[lane + j * 32];
#pragma unroll
    for (int p = 0; p < 8; p++) {
        const float4* wr = (const float4*)(w2s + p * 1024);
        float acc = 0.f;
#pragma unroll
        for (int j = 0; j < 8; j++) {
            float4 wv = wr[lane + j * 32];
            acc += xv[j].x * wv.x + xv[j].y * wv.y + xv[j].z * wv.z + xv[j].w * wv.w;
        }
        for (int o = 16; o > 0; o >>= 1) acc += __shfl_xor_sync(0xffffffffu, acc, o);
        if (lane == 0) proj[(size_t)b * 8 + p] = acc + bss[p];
    }
}

// ================= launch =================
extern "C" void kernel_launch(void* const* d_in, const int* in_sizes, int n_in,
                              void* d_out, int out_size) {
    const float* x      = (const float*)d_in[0];
    const float* W1     = (const float*)d_in[1];
    const float* b1     = (const float*)d_in[2];
    const float* g1     = (const float*)d_in[3];
    const float* beta1  = (const float*)d_in[4];
    const float* W2     = (const float*)d_in[5];
    const float* b2     = (const float*)d_in[6];
    const float* edge_w = (const float*)d_in[7];
    const float* mask   = (const float*)d_in[8];
    const float* Wi     = (const float*)d_in[9];
    const float* bi     = (const float*)d_in[10];
    const float* Wf     = (const float*)d_in[11];
    const float* bf     = (const float*)d_in[12];
    const float* Wslow  = (const float*)d_in[13];
    const float* bslow  = (const float*)d_in[14];
    const float* u      = (const float*)d_in[15];
    const float* Wfast  = (const float*)d_in[16];
    const float* Wo     = (const float*)d_in[17];
    const float* bo     = (const float*)d_in[18];
    const float* gln    = (const float*)d_in[19];
    const float* bln    = (const float*)d_in[20];
    const float* h_prev = (const float*)d_in[21];
    const float* memory = (const float*)d_in[22];
    const float* Wh     = (const float*)d_in[23];
    const float* bh     = (const float*)d_in[24];
    const float* Ws1    = (const float*)d_in[25];
    const float* bs1    = (const float*)d_in[26];
    const float* Ws2    = (const float*)d_in[27];
    const float* bs2    = (const float*)d_in[28];

    float* out    = (float*)d_out;
    float* logits = out;
    float* proj   = out + (size_t)Bn * Ccls;
    float* xflat  = proj + (size_t)Bn * Pp;

    float *p_h1, *p_b2a, *p_xagg, *p_sim, *p_s1, *p_bhm;
    cudaGetSymbolAddress((void**)&p_h1, g_h1);
    cudaGetSymbolAddress((void**)&p_b2a, g_b2a);
    cudaGetSymbolAddress((void**)&p_xagg, g_xagg);
    cudaGetSymbolAddress((void**)&p_sim, g_sim);
    cudaGetSymbolAddress((void**)&p_s1, g_s1);
    cudaGetSymbolAddress((void**)&p_bhm, g_bhm);
    void *p_xh, *p_xl, *p_W1h, *p_W1l, *p_h1h, *p_h1l, *p_W2h, *p_W2l;
    void *p_xfh, *p_xfl, *p_Whmh, *p_Whml, *p_Ws1h, *p_Ws1l, *p_memh, *p_meml;
    cudaGetSymbolAddress(&p_xh, g_xh);   cudaGetSymbolAddress(&p_xl, g_xl);
    cudaGetSymbolAddress(&p_W1h, g_W1h); cudaGetSymbolAddress(&p_W1l, g_W1l);
    cudaGetSymbolAddress(&p_h1h, g_h1h); cudaGetSymbolAddress(&p_h1l, g_h1l);
    cudaGetSymbolAddress(&p_W2h, g_W2h); cudaGetSymbolAddress(&p_W2l, g_W2l);
    cudaGetSymbolAddress(&p_xfh, g_xfh); cudaGetSymbolAddress(&p_xfl, g_xfl);
    cudaGetSymbolAddress(&p_Whmh, g_Whmh); cudaGetSymbolAddress(&p_Whml, g_Whml);
    cudaGetSymbolAddress(&p_Ws1h, g_Ws1h); cudaGetSymbolAddress(&p_Ws1l, g_Ws1l);
    cudaGetSymbolAddress(&p_memh, g_memh); cudaGetSymbolAddress(&p_meml, g_meml);

    cudaFuncSetAttribute(cell_kernel, cudaFuncAttributeMaxDynamicSharedMemorySize, CELL_SMEM);
    cudaFuncSetAttribute(gemm_mma<4, 3>, cudaFuncAttributeMaxDynamicSharedMemorySize, GSMEM_TOTAL);
    cudaFuncSetAttribute(gemm_mma<4, 1>, cudaFuncAttributeMaxDynamicSharedMemorySize, GSMEM_TOTAL);
    cudaFuncSetAttribute(gemm_mma<2, 3>, cudaFuncAttributeMaxDynamicSharedMemorySize, GSMEM_TOTAL);

    // prep + conversions
    prep_adj<<<1, 64>>>(edge_w, mask);
    fold_w2<<<dim3(8, 64), 256>>>(W2);
    prep_b2a<<<64, 64>>>(b2);
    prep_node<<<64, 64>>>(Wslow, u, Wfast, Wf, bf, h_prev);
    prep_whm_bf<<<(1024 * FLAT / 4 + 255) / 256, 256>>>(Wh);
    prep_bhm<<<4, 256>>>(bh);
    cvt_hilo<<<(Bn * Fdim / 4 + 255) / 256, 256>>>(x, (uint2*)p_xh, (uint2*)p_xl, Bn * Fdim / 4);
    cvt_hilo<<<(Hdim * Fdim / 4 + 255) / 256, 256>>>(W1, (uint2*)p_W1h, (uint2*)p_W1l, Hdim * Fdim / 4);
    cvt_hilo<<<(Hdim * FLAT / 4 + 255) / 256, 256>>>(Ws1, (uint2*)p_Ws1h, (uint2*)p_Ws1l, Hdim * FLAT / 4);
    cvt_mem_pad<<<(128 * FLAT / 4 + 255) / 256, 256>>>(memory);

    // stage 1: input projection; gemm2 emits x_agg directly (adj folded)
    gemm_mma<4, 3><<<dim3(Hdim / 128, Bn / 128), 256, GSMEM_TOTAL>>>(
        (const __half*)p_xh, (const __half*)p_xl,
        (const __half*)p_W1h, (const __half*)p_W1l, b1, p_h1,
        Fdim, Fdim, Hdim, 0, 0);
    ln_gelu_kernel<<<Bn, 256>>>(p_h1, g1, beta1, (uint2*)p_h1h, (uint2*)p_h1l);
    gemm_mma<4, 3><<<dim3(FLAT / 128, Bn / 128), 256, GSMEM_TOTAL>>>(
        (const __half*)p_h1h, (const __half*)p_h1l,
        (const __half*)p_W2h, (const __half*)p_W2l, p_b2a, p_xagg,
        Hdim, Hdim, FLAT, 0, 0);

    // stage 2: cells
    cell_kernel<<<dim3(Nn, Bn / 64), 256, CELL_SMEM>>>(Wi, Wf, Wo, bi, bslow, bo,
                                                       h_prev, gln, bln, xflat,
                                                       (uint32_t*)p_xfh, (uint32_t*)p_xfl);

    // stage 3: retrieval (split-K sim GEMM, atomic accumulate; 3-pass keeps top-k tight)
    zero_sim<<<Bn * CAP / 256, 256>>>();
    gemm_mma<2, 3><<<dim3(1, Bn / 128, 4), 256, GSMEM_TOTAL>>>(
        (const __half*)p_xfh, (const __half*)p_xfl,
        (const __half*)p_memh, (const __half*)p_meml, nullptr, p_sim,
        FLAT / 4, FLAT, CAP, 0, 1);
    retrieve_kernel<<<Bn, 256>>>(memory, xflat, (uint2*)p_xfh, (uint2*)p_xfl);

    // stage 4: heads (1-pass fp16: smooth error ~4.5e-4, no top-k dependence)
    gemm_mma<4, 1><<<dim3(1024 / 128, Bn / 128), 256, GSMEM_TOTAL>>>(
        (const __half*)p_xfh, nullptr,
        (const __half*)p_Whmh, nullptr, p_bhm, logits,
        FLAT, FLAT, Ccls, 0, 0);
    gemm_mma<4, 1><<<dim3(Hdim / 128, Bn / 128), 256, GSMEM_TOTAL>>>(
        (const __half*)p_xfh, nullptr,
        (const __half*)p_Ws1h, nullptr, bs1, p_s1,
        FLAT, FLAT, Hdim, 1, 0);
    proj2_kernel<<<Bn / 8, 256>>>(p_s1, Ws2, bs2, proj);
}

// round 12
// speedup vs baseline: 1.4653x; 1.0857x over previous
#include <cuda_runtime.h>
#include <cuda_fp16.h>
#include <math.h>
#include <stdint.h>

#define Bn 4096
#define Fdim 512
#define Hdim 1024
#define Nn 64
#define Dd 64
#define FLAT 4096
#define Ccls 1000
#define CAP 64
#define Pp 8

// ================= scratch (device globals) =================
__device__ float g_h1[Bn * Hdim];
__device__ float g_b2a[FLAT];
__device__ float g_xagg[(size_t)Bn * FLAT];
__device__ float g_sim[Bn * CAP];
__device__ float g_s1[Bn * Hdim];
__device__ float g_bhm[1024];
__device__ float g_adj[Nn * Nn];
__device__ float g_WcT[Nn * Dd * Dd];
__device__ float g_cf[Nn * Dd];
// fp16 hi/lo operand buffers
__device__ __half g_xh[Bn * Fdim],    g_xl[Bn * Fdim];
__device__ __half g_W1h[Hdim * Fdim], g_W1l[Hdim * Fdim];
__device__ __half g_h1h[Bn * Hdim],   g_h1l[Bn * Hdim];
__device__ __half g_W2h[FLAT * Hdim], g_W2l[FLAT * Hdim];
__device__ __half g_xfh[(size_t)Bn * FLAT], g_xfl[(size_t)Bn * FLAT];
__device__ __half g_Whmh[1024 * FLAT], g_Whml[1024 * FLAT];
__device__ __half g_Ws1h[Hdim * FLAT], g_Ws1l[Hdim * FLAT];
__device__ __half g_memh[128 * FLAT], g_meml[128 * FLAT];

__device__ __forceinline__ float sigmoidf_(float x) { return 1.f / (1.f + expf(-x)); }

__device__ __forceinline__ uint32_t pack2h(__half a, __half b) {
    return (uint32_t)__half_as_ushort(a) | ((uint32_t)__half_as_ushort(b) << 16);
}
__device__ __forceinline__ void cvt4(float4 v, uint2& hi, uint2& lo) {
    __half h0 = __float2half_rn(v.x), h1 = __float2half_rn(v.y);
    __half h2 = __float2half_rn(v.z), h3 = __float2half_rn(v.w);
    __half l0 = __float2half_rn(v.x - __half2float(h0));
    __half l1 = __float2half_rn(v.y - __half2float(h1));
    __half l2 = __float2half_rn(v.z - __half2float(h2));
    __half l3 = __float2half_rn(v.w - __half2float(h3));
    hi.x = pack2h(h0, h1); hi.y = pack2h(h2, h3);
    lo.x = pack2h(l0, l1); lo.y = pack2h(l2, l3);
}
__device__ __forceinline__ void cvt2(float a, float b, uint32_t& hi, uint32_t& lo) {
    __half h0 = __float2half_rn(a), h1 = __float2half_rn(b);
    __half l0 = __float2half_rn(a - __half2float(h0));
    __half l1 = __float2half_rn(b - __half2float(h1));
    hi = pack2h(h0, h1); lo = pack2h(l0, l1);
}

// ================= mma / cp.async / ldmatrix primitives =================
__device__ __forceinline__ uint32_t smem_u32(const void* p) {
    uint32_t a;
    asm("{ .reg .u64 t; cvta.to.shared.u64 t, %1; cvt.u32.u64 %0, t; }" : "=r"(a) : "l"(p));
    return a;
}
__device__ __forceinline__ void cp16(uint32_t s, const void* g) {
    asm volatile("cp.async.cg.shared.global [%0], [%1], 16;" :: "r"(s), "l"(g));
}
#define CP_COMMIT() asm volatile("cp.async.commit_group;")
#define CP_WAIT1() asm volatile("cp.async.wait_group 1;")

__device__ __forceinline__ void mma16816(float* d, const uint32_t* a, uint32_t b0, uint32_t b1) {
    asm volatile(
        "mma.sync.aligned.m16n8k16.row.col.f32.f16.f16.f32 "
        "{%0,%1,%2,%3}, {%4,%5,%6,%7}, {%8,%9}, {%0,%1,%2,%3};"
        : "+f"(d[0]), "+f"(d[1]), "+f"(d[2]), "+f"(d[3])
        : "r"(a[0]), "r"(a[1]), "r"(a[2]), "r"(a[3]), "r"(b0), "r"(b1));
}
__device__ __forceinline__ void ldsm_x4(uint32_t& r0, uint32_t& r1, uint32_t& r2, uint32_t& r3,
                                        uint32_t addr) {
    asm volatile("ldmatrix.sync.aligned.m8n8.x4.shared.b16 {%0,%1,%2,%3}, [%4];"
                 : "=r"(r0), "=r"(r1), "=r"(r2), "=r"(r3) : "r"(addr));
}

// ================= conversion kernels =================
__global__ void cvt_hilo(const float* __restrict__ src, uint2* __restrict__ hi,
                         uint2* __restrict__ lo, int n4) {
    int i = blockIdx.x * 256 + threadIdx.x;
    if (i < n4) {
        float4 v = ((const float4*)src)[i];
        uint2 h, l; cvt4(v, h, l);
        hi[i] = h; lo[i] = l;
    }
}
__global__ void cvt_mem_pad(const float* __restrict__ mem) {
    int i = blockIdx.x * 256 + threadIdx.x;
    if (i >= 128 * FLAT / 4) return;
    int row = i >> 10;
    uint2 h = make_uint2(0u, 0u), l = make_uint2(0u, 0u);
    if (row < CAP) {
        float4 v = ((const float4*)mem)[i];
        cvt4(v, h, l);
    }
    ((uint2*)g_memh)[i] = h; ((uint2*)g_meml)[i] = l;
}

// ================= prep kernels =================
__global__ void prep_adj(const float* __restrict__ edge_w, const float* __restrict__ mask) {
    __shared__ float t[64 * 64];
    int r = threadIdx.x;
    float sum = 0.f;
    for (int c = 0; c < 64; c++) {
        float v = sigmoidf_(edge_w[r * 64 + c] * 1.5f) * mask[r * 64 + c];
        t[r * 64 + c] = v; sum += v;
    }
    float inv = 1.f / fmaxf(sum, 1e-6f);
    for (int c = 0; c < 64; c++) g_adj[r * 64 + c] = t[r * 64 + c] * inv;
}

// fold adjacency into W2, emit fp16 hi/lo
__global__ void __launch_bounds__(256) fold_w2(const float* __restrict__ W2) {
    int kt = blockIdx.x;
    int d  = blockIdx.y;
    __shared__ float tile[64][128];
    __shared__ float adjT[64 * 64];
    int tid = threadIdx.x;
    for (int i = tid; i < 4096; i += 256) {
        int m = i >> 6, n = i & 63;
        adjT[i] = g_adj[n * 64 + m];
    }
    for (int i = tid; i < 64 * 32; i += 256) {
        int m = i >> 5, c4 = (i & 31) << 2;
        *(float4*)&tile[m][c4] = *(const float4*)(W2 + (size_t)(m * 64 + d) * Hdim + kt * 128 + c4);
    }
    __syncthreads();
    int n = tid & 63;
    int kq = tid >> 6;
    float4 acc[8];
#pragma unroll
    for (int q = 0; q < 8; q++) acc[q] = make_float4(0.f, 0.f, 0.f, 0.f);
    for (int m = 0; m < 64; m++) {
        float s = adjT[m * 64 + n];
        const float4* trow = (const float4*)&tile[m][kq * 32];
#pragma unroll
        for (int q = 0; q < 8; q++) {
            float4 t4 = trow[q];
            acc[q].x += s * t4.x; acc[q].y += s * t4.y;
            acc[q].z += s * t4.z; acc[q].w += s * t4.w;
        }
    }
    size_t off4 = ((size_t)(n * 64 + d) * Hdim + kt * 128 + kq * 32) >> 2;
#pragma unroll
    for (int q = 0; q < 8; q++) {
        uint2 h, l; cvt4(acc[q], h, l);
        ((uint2*)g_W2h)[off4 + q] = h;
        ((uint2*)g_W2l)[off4 + q] = l;
    }
}
__global__ void prep_b2a(const float* __restrict__ b2) {
    int nd = blockIdx.x * 64 + threadIdx.x;
    int n = nd >> 6, d = nd & 63;
    float acc = 0.f;
    for (int m = 0; m < 64; m++) acc += g_adj[n * 64 + m] * b2[m * 64 + d];
    g_b2a[nd] = acc;
}

__global__ void prep_node(const float* __restrict__ Wslow, const float* __restrict__ u,
                          const float* __restrict__ Wfast, const float* __restrict__ Wf,
                          const float* __restrict__ bf, const float* __restrict__ hprev) {
    int n = blockIdx.x;
    int t = threadIdx.x;
    __shared__ float us[64], v[64], red[64];
    const float* Ws = Wslow + (size_t)n * 4096;
    us[t] = u[n * 64 + t];
    __syncthreads();
    float acc = 0.f;
    for (int o = 0; o < 64; o++) acc += Ws[o * 64 + t] * us[o];
    v[t] = acc;
    __syncthreads();
    float wv = 0.f;
    for (int i = 0; i < 64; i++) wv += Ws[t * 64 + i] * v[i];
    red[t] = us[t] * wv;
    __syncthreads();
    for (int off = 32; off > 0; off >>= 1) {
        if (t < off) red[t] += red[t + off];
        __syncthreads();
    }
    float inv = 1.f / (red[0] + 1e-8f);
    const float* Wfa = Wfast + (size_t)n * 4096;
    float* out = g_WcT + (size_t)n * 4096;
    for (int idx = t; idx < 4096; idx += 64) {
        int i = idx >> 6, o = idx & 63;
        out[idx] = Ws[o * 64 + i] * inv + Wfa[o * 64 + i];
    }
    float c = bf[n * 64 + t];
    const float* Wf2 = Wf + (size_t)n * 8192 + 4096;
    for (int i = 0; i < 64; i++) c += hprev[n * 64 + i] * Wf2[i * 64 + t];
    g_cf[n * 64 + t] = c;
}

__global__ void prep_whm_bf(const float* __restrict__ Wh) {
    int i = blockIdx.x * 256 + threadIdx.x;
    if (i >= (1024 * FLAT) / 4) return;
    int row = i >> 10;
    uint2 h, l;
    if (row < Ccls) {
        const size_t CF4 = (size_t)Ccls * FLAT / 4;
        const float4* W4 = (const float4*)Wh;
        float4 a = W4[i], b = W4[i + CF4], c = W4[i + 2 * CF4];
        float4 m = make_float4((a.x + b.x + c.x) * (1.f / 3.f), (a.y + b.y + c.y) * (1.f / 3.f),
                               (a.z + b.z + c.z) * (1.f / 3.f), (a.w + b.w + c.w) * (1.f / 3.f));
        cvt4(m, h, l);
    } else {
        h = make_uint2(0u, 0u); l = make_uint2(0u, 0u);
    }
    ((uint2*)g_Whmh)[i] = h; ((uint2*)g_Whml)[i] = l;
}
__global__ void prep_bhm(const float* __restrict__ bh) {
    int i = blockIdx.x * 256 + threadIdx.x;
    if (i < 1024) g_bhm[i] = (i < Ccls) ? (bh[i] + bh[i + Ccls] + bh[i + 2 * Ccls]) * (1.f / 3.f) : 0.f;
}
__global__ void zero_sim() {
    g_sim[blockIdx.x * 256 + threadIdx.x] = 0.f;
}

// ================= split-fp16 HMMA GEMM =================
// PASSES: 3 = Ah*Bh + Ah*Bl + Al*Bh; 2 = Ah*Bh + Ah*Bl; 1 = Ah*Bh only.
#define TSTRIDE 40
#define ROWB (TSTRIDE * 2)
#define TILE_B (128 * ROWB)
#define STAGE_B (4 * TILE_B)
#define GSMEM_TOTAL (2 * STAGE_B)

template <int NI, int PASSES>
__global__ void __launch_bounds__(256, 2) gemm_mma(
    const __half* __restrict__ Ahi, const __half* __restrict__ Alo,
    const __half* __restrict__ Bhi, const __half* __restrict__ Blo,
    const float* __restrict__ bias, float* __restrict__ C,
    int K, int lda, int Nstore, int act, int atomicOut) {
    extern __shared__ char smem[];
    const int tid = threadIdx.x;
    const int wid = tid >> 5;
    const int lane = tid & 31;
    const int grp = lane >> 2;
    const int qp = lane & 3;
    const int wm = (wid >> 2) * 64;
    const int wn = (wid & 3) * (NI * 8);
    const int bm = blockIdx.y * 128;
    const int bn = blockIdx.x * 128;
    const int kbase = blockIdx.z * K;
    const uint32_t sb = smem_u32(smem);

    const int row = tid >> 2;
    const int c16 = tid & 3;

    const int aRowL = wm + (lane & 7) + ((lane >> 3) & 1) * 8;
    const int aKL = (lane >> 4) * 8;
    const int bRowL = wn + (lane & 7) + (lane >> 4) * 8;
    const int bKL = ((lane >> 3) & 1) * 8;

    float acc[4][NI][4];
#pragma unroll
    for (int mi = 0; mi < 4; mi++)
#pragma unroll
        for (int ni = 0; ni < NI; ni++)
#pragma unroll
            for (int j = 0; j < 4; j++) acc[mi][ni][j] = 0.f;

    const int nc = K >> 5;

    auto issue = [&](int c, int s) {
        const uint32_t ss = sb + s * STAGE_B;
        const int k0 = c << 5;
#pragma unroll
        for (int t = 0; t < 2; t++) {
            const int r = row + t * 64;
            const uint32_t so = (uint32_t)r * ROWB + c16 * 16;
            const size_t gAoff = ((size_t)(bm + r) * lda + kbase + k0) * 2 + c16 * 16;
            const size_t gBoff = ((size_t)(bn + r) * lda + kbase + k0) * 2 + c16 * 16;
            cp16(ss + 0 * TILE_B + so, (const char*)Ahi + gAoff);
            if (PASSES == 3) cp16(ss + 1 * TILE_B + so, (const char*)Alo + gAoff);
            cp16(ss + 2 * TILE_B + so, (const char*)Bhi + gBoff);
            if (PASSES >= 2) cp16(ss + 3 * TILE_B + so, (const char*)Blo + gBoff);
        }
    };

    issue(0, 0); CP_COMMIT();
    if (nc > 1) issue(1, 1);
    CP_COMMIT();

    for (int c = 0; c < nc; c++) {
        const int s = c & 1;
        CP_WAIT1();
        __syncthreads();
        const uint32_t st = sb + s * STAGE_B;
#pragma unroll
        for (int ks = 0; ks < 2; ks++) {
            const int k0 = ks * 16;
            uint32_t ah[4][4], al[4][4];
#pragma unroll
            for (int mi = 0; mi < 4; mi++) {
                const uint32_t ad = st + (uint32_t)(aRowL + mi * 16) * ROWB + (k0 + aKL) * 2;
                ldsm_x4(ah[mi][0], ah[mi][1], ah[mi][2], ah[mi][3], ad);
                if (PASSES == 3) ldsm_x4(al[mi][0], al[mi][1], al[mi][2], al[mi][3], ad + TILE_B);
            }
            uint32_t bh[NI][2], bl[NI][2];
#pragma unroll
            for (int p = 0; p < NI / 2; p++) {
                const uint32_t bd = st + 2 * TILE_B + (uint32_t)(bRowL + p * 16) * ROWB + (k0 + bKL) * 2;
                uint32_t r0, r1, r2, r3;
                ldsm_x4(r0, r1, r2, r3, bd);
                bh[2 * p][0] = r0; bh[2 * p][1] = r1; bh[2 * p + 1][0] = r2; bh[2 * p + 1][1] = r3;
                if (PASSES >= 2) {
                    ldsm_x4(r0, r1, r2, r3, bd + TILE_B);
                    bl[2 * p][0] = r0; bl[2 * p][1] = r1; bl[2 * p + 1][0] = r2; bl[2 * p + 1][1] = r3;
                }
            }
#pragma unroll
            for (int ni = 0; ni < NI; ni++) {
#pragma unroll
                for (int mi = 0; mi < 4; mi++) {
                    mma16816(acc[mi][ni], ah[mi], bh[ni][0], bh[ni][1]);
                    if (PASSES >= 2) mma16816(acc[mi][ni], ah[mi], bl[ni][0], bl[ni][1]);
                    if (PASSES == 3) mma16816(acc[mi][ni], al[mi], bh[ni][0], bh[ni][1]);
                }
            }
        }
        __syncthreads();
        if (c + 2 < nc) issue(c + 2, s);
        CP_COMMIT();
    }

    // epilogue
#pragma unroll
    for (int mi = 0; mi < 4; mi++) {
#pragma unroll
        for (int ni = 0; ni < NI; ni++) {
            const int r0 = bm + wm + mi * 16 + grp;
            const int col = bn + wn + ni * 8 + qp * 2;
            float* a4 = acc[mi][ni];
            if (atomicOut) {
                if (col < Nstore) {
                    atomicAdd(&C[(size_t)r0 * Nstore + col], a4[0]);
                    atomicAdd(&C[(size_t)(r0 + 8) * Nstore + col], a4[2]);
                    if (col + 1 < Nstore) {
                        atomicAdd(&C[(size_t)r0 * Nstore + col + 1], a4[1]);
                        atomicAdd(&C[(size_t)(r0 + 8) * Nstore + col + 1], a4[3]);
                    }
                }
            } else if (col + 1 < Nstore) {
                float2 v0, v1;
                float bb0 = bias ? bias[col] : 0.f;
                float bb1 = bias ? bias[col + 1] : 0.f;
                v0.x = a4[0] + bb0; v0.y = a4[1] + bb1;
                v1.x = a4[2] + bb0; v1.y = a4[3] + bb1;
                if (act == 1) {
                    v0.x = fmaxf(v0.x, 0.f); v0.y = fmaxf(v0.y, 0.f);
                    v1.x = fmaxf(v1.x, 0.f); v1.y = fmaxf(v1.y, 0.f);
                }
                *(float2*)(C + (size_t)r0 * Nstore + col) = v0;
                *(float2*)(C + (size_t)(r0 + 8) * Nstore + col) = v1;
            } else if (col < Nstore) {
                float bb0 = bias ? bias[col] : 0.f;
                float v0 = a4[0] + bb0, v1 = a4[2] + bb0;
                if (act == 1) { v0 = fmaxf(v0, 0.f); v1 = fmaxf(v1, 0.f); }
                C[(size_t)r0 * Nstore + col] = v0;
                C[(size_t)(r0 + 8) * Nstore + col] = v1;
            }
        }
    }
}

// ================= LayerNorm(H=1024) + GELU -> fp16 hi/lo =================
__global__ void __launch_bounds__(256) ln_gelu_kernel(const float* __restrict__ h,
                                                      const float* __restrict__ g,
                                                      const float* __restrict__ beta,
                                                      uint2* __restrict__ hi,
                                                      uint2* __restrict__ lo) {
    int row = blockIdx.x;
    const float* hr = h + (size_t)row * Hdim;
    int tid = threadIdx.x;
    float4 v = *(const float4*)(hr + tid * 4);
    float s = v.x + v.y + v.z + v.w;
    float ss = v.x * v.x + v.y * v.y + v.z * v.z + v.w * v.w;
    __shared__ float rs[8], rss[8];
    for (int o = 16; o > 0; o >>= 1) {
        s += __shfl_down_sync(0xffffffffu, s, o);
        ss += __shfl_down_sync(0xffffffffu, ss, o);
    }
    if ((tid & 31) == 0) { rs[tid >> 5] = s; rss[tid >> 5] = ss; }
    __syncthreads();
    if (tid < 32) {
        float a = tid < 8 ? rs[tid] : 0.f;
        float b = tid < 8 ? rss[tid] : 0.f;
        for (int o = 4; o > 0; o >>= 1) {
            a += __shfl_down_sync(0xffffffffu, a, o);
            b += __shfl_down_sync(0xffffffffu, b, o);
        }
        if (tid == 0) { rs[0] = a; rss[0] = b; }
    }
    __syncthreads();
    float mu = rs[0] * (1.f / Hdim);
    float var = rss[0] * (1.f / Hdim) - mu * mu;
    float inv = rsqrtf(var + 1e-5f);
    float4 gg = *(const float4*)(g + tid * 4);
    float4 bb = *(const float4*)(beta + tid * 4);
    float y;
    y = (v.x - mu) * inv * gg.x + bb.x; v.x = 0.5f * y * (1.f + erff(y * 0.70710678118654752f));
    y = (v.y - mu) * inv * gg.y + bb.y; v.y = 0.5f * y * (1.f + erff(y * 0.70710678118654752f));
    y = (v.z - mu) * inv * gg.z + bb.z; v.z = 0.5f * y * (1.f + erff(y * 0.70710678118654752f));
    y = (v.w - mu) * inv * gg.w + bb.w; v.w = 0.5f * y * (1.f + erff(y * 0.70710678118654752f));
    uint2 hh, ll; cvt4(v, hh, ll);
    hi[(size_t)row * 256 + tid] = hh;
    lo[(size_t)row * 256 + tid] = ll;
}

// ================= fused cell kernel (emits fp16 hi/lo of xflat) =================
#define CELL_SMEM ((64 * 68 * 2 + 4096 * 4 + 7 * 64) * sizeof(float))
__global__ void __launch_bounds__(256) cell_kernel(const float* __restrict__ Wi,
                                                   const float* __restrict__ Wf,
                                                   const float* __restrict__ Wo,
                                                   const float* __restrict__ bi_g,
                                                   const float* __restrict__ bslow_g,
                                                   const float* __restrict__ bo_g,
                                                   const float* __restrict__ hprev_g,
                                                   const float* __restrict__ gln_g,
                                                   const float* __restrict__ bln_g,
                                                   float* __restrict__ xflat_out,
                                                   uint32_t* __restrict__ xfh,
                                                   uint32_t* __restrict__ xfl) {
    extern __shared__ float sf[];
    float* xs = sf;
    float* wi = xs + 64 * 68;
    float* wf = wi + 4096;
    float* wc = wf + 4096;
    float* wo = wc + 4096;
    float* hr = wo + 4096;
    float* vecs = hr + 64 * 68;

    int n = blockIdx.x;
    int b0 = blockIdx.y * 64;
    int tid = threadIdx.x;

#pragma unroll
    for (int j = 0; j < 4; j++) {
        int idx = tid + j * 256;
        int row = idx >> 4, c4 = (idx & 15) << 2;
        *(float4*)(xs + row * 68 + c4) =
            *(const float4*)(g_xagg + (((size_t)(b0 + row) * 64 + n) << 6) + c4);
        ((float4*)wi)[idx] = ((const float4*)(Wi + (size_t)n * 4096))[idx];
        ((float4*)wf)[idx] = ((const float4*)(Wf + (size_t)n * 8192))[idx];
        ((float4*)wc)[idx] = ((const float4*)(g_WcT + (size_t)n * 4096))[idx];
        ((float4*)wo)[idx] = ((const float4*)(Wo + (size_t)n * 4096))[idx];
    }
    if (tid < 64) {
        vecs[0 * 64 + tid] = bi_g[n * 64 + tid];
        vecs[1 * 64 + tid] = g_cf[n * 64 + tid];
        vecs[2 * 64 + tid] = bslow_g[n * 64 + tid];
        vecs[3 * 64 + tid] = bo_g[n * 64 + tid];
        vecs[4 * 64 + tid] = hprev_g[n * 64 + tid];
        vecs[5 * 64 + tid] = gln_g[n * 64 + tid];
        vecs[6 * 64 + tid] = bln_g[n * 64 + tid];
    }
    __syncthreads();

    const int r0 = (tid >> 4) * 4;
    const int c0 = (tid & 15) * 4;

    float ai[4][4], af[4][4], ac[4][4];
#pragma unroll
    for (int r = 0; r < 4; r++)
#pragma unroll
        for (int c = 0; c < 4; c++) { ai[r][c] = 0.f; af[r][c] = 0.f; ac[r][c] = 0.f; }

    for (int i = 0; i < 64; i++) {
        float xv[4];
#pragma unroll
        for (int r = 0; r < 4; r++) xv[r] = xs[(r0 + r) * 68 + i];
        float4 w1 = *(const float4*)(wi + i * 64 + c0);
        float4 w2 = *(const float4*)(wf + i * 64 + c0);
        float4 w3 = *(const float4*)(wc + i * 64 + c0);
#pragma unroll
        for (int r = 0; r < 4; r++) {
            ai[r][0] += xv[r] * w1.x; ai[r][1] += xv[r] * w1.y; ai[r][2] += xv[r] * w1.z; ai[r][3] += xv[r] * w1.w;
            af[r][0] += xv[r] * w2.x; af[r][1] += xv[r] * w2.y; af[r][2] += xv[r] * w2.z; af[r][3] += xv[r] * w2.w;
            ac[r][0] += xv[r] * w3.x; ac[r][1] += xv[r] * w3.y; ac[r][2] += xv[r] * w3.z; ac[r][3] += xv[r] * w3.w;
        }
    }
#pragma unroll
    for (int r = 0; r < 4; r++)
#pragma unroll
        for (int c = 0; c < 4; c++) {
            int o = c0 + c;
            float it = sigmoidf_(ai[r][c] + vecs[0 * 64 + o]);
            float ft = sigmoidf_(af[r][c] + vecs[1 * 64 + o]);
            float hs = ac[r][c] + vecs[2 * 64 + o];
            hr[(r0 + r) * 68 + o] = it * hs + ft * vecs[4 * 64 + o];
        }
    __syncthreads();

    float ao[4][4];
#pragma unroll
    for (int r = 0; r < 4; r++)
#pragma unroll
        for (int c = 0; c < 4; c++) ao[r][c] = 0.f;
    for (int i = 0; i < 64; i++) {
        float xv[4];
#pragma unroll
        for (int r = 0; r < 4; r++) xv[r] = hr[(r0 + r) * 68 + i];
        float4 w = *(const float4*)(wo + i * 64 + c0);
#pragma unroll
        for (int r = 0; r < 4; r++) {
            ao[r][0] += xv[r] * w.x; ao[r][1] += xv[r] * w.y;
            ao[r][2] += xv[r] * w.z; ao[r][3] += xv[r] * w.w;
        }
    }
    float* ys = xs;
#pragma unroll
    for (int r = 0; r < 4; r++)
#pragma unroll
        for (int c = 0; c < 4; c++) {
            int o = c0 + c;
            float ot = sigmoidf_(ao[r][c] + vecs[3 * 64 + o]);
            ys[(r0 + r) * 68 + o] = ot * tanhf(hr[(r0 + r) * 68 + o]);
        }
    __syncthreads();

    int w = tid >> 5, lane = tid & 31;
    for (int rr = 0; rr < 8; rr++) {
        int row = w * 8 + rr;
        float v0 = ys[row * 68 + 2 * lane];
        float v1 = ys[row * 68 + 2 * lane + 1];
        float s = v0 + v1;
        float ss = v0 * v0 + v1 * v1;
        for (int o = 16; o > 0; o >>= 1) {
            s += __shfl_xor_sync(0xffffffffu, s, o);
            ss += __shfl_xor_sync(0xffffffffu, ss, o);
        }
        float mu = s * (1.f / 64.f);
        float var = ss * (1.f / 64.f) - mu * mu;
        float inv = rsqrtf(var + 1e-5f);
        float y0 = (v0 - mu) * inv * vecs[5 * 64 + 2 * lane] + vecs[6 * 64 + 2 * lane];
        float y1 = (v1 - mu) * inv * vecs[5 * 64 + 2 * lane + 1] + vecs[6 * 64 + 2 * lane + 1];
        size_t base = (size_t)(b0 + row) * 4096 + n * 64;
        *(float2*)(xflat_out + base + 2 * lane) = make_float2(y0, y1);
        uint32_t hh, ll; cvt2(y0, y1, hh, ll);
        xfh[(base >> 1) + lane] = hh;
        xfl[(base >> 1) + lane] = ll;
    }
}

// ================= top-5 retrieval + update + fp16 re-emit =================
__global__ void __launch_bounds__(256) retrieve_kernel(const float* __restrict__ mem,
                                                       float* __restrict__ xflat,
                                                       uint2* __restrict__ xfh,
                                                       uint2* __restrict__ xfl) {
    int b = blockIdx.x;
    __shared__ float s[64];
    __shared__ int top[5];
    int tid = threadIdx.x;
    if (tid < 64) s[tid] = g_sim[b * 64 + tid];
    __syncthreads();
    if (tid < 32) {
        for (int k = 0; k < 5; k++) {
            float v = s[tid]; int idx = tid;
            float v2 = s[tid + 32];
            if (v2 > v) { v = v2; idx = tid + 32; }
            for (int o = 16; o > 0; o >>= 1) {
                float ov = __shfl_down_sync(0xffffffffu, v, o);
                int oi = __shfl_down_sync(0xffffffffu, idx, o);
                if (ov > v || (ov == v && oi < idx)) { v = ov; idx = oi; }
            }
            idx = __shfl_sync(0xffffffffu, idx, 0);
            if (tid == 0) top[k] = idx;
            if (tid == 0) s[idx] = -INFINITY;
            __syncwarp();
        }
    }
    __syncthreads();
    const float4* m4 = (const float4*)mem;
    float4* x4 = (float4*)(xflat + (size_t)b * 4096);
    int t0 = top[0] * 1024, t1 = top[1] * 1024, t2 = top[2] * 1024, t3 = top[3] * 1024, t4 = top[4] * 1024;
#pragma unroll
    for (int j = 0; j < 4; j++) {
        int idx = tid + j * 256;
        float4 xv = x4[idx];
        float4 a = m4[t0 + idx], bb = m4[t1 + idx], c = m4[t2 + idx], d = m4[t3 + idx], e = m4[t4 + idx];
        xv.x += 0.02f * (a.x + bb.x + c.x + d.x + e.x);
        xv.y += 0.02f * (a.y + bb.y + c.y + d.y + e.y);
        xv.z += 0.02f * (a.z + bb.z + c.z + d.z + e.z);
        xv.w += 0.02f * (a.w + bb.w + c.w + d.w + e.w);
        x4[idx] = xv;
        uint2 h, l; cvt4(xv, h, l);
        xfh[(size_t)b * 1024 + idx] = h;
        xfl[(size_t)b * 1024 + idx] = l;
    }
}

// ================= proj2: proj[b, 0:8] = relu_s1[b,:] @ Ws2^T + bs2 =================
__global__ void __launch_bounds__(256) proj2_kernel(const float* __restrict__ s1,
                                                    const float* __restrict__ Ws2,
                                                    const float* __restrict__ bs2,
                                                    float* __restrict__ proj) {
    __shared__ float w2s[8 * 1024];
    __shared__ float bss[8];
    int tid = threadIdx.x;
    for (int i = tid; i < 8192; i += 256) w2s[i] = Ws2[i];
    if (tid < 8) bss[tid] = bs2[tid];
    __syncthreads();
    int w = tid >> 5, lane = tid & 31;
    int b = blockIdx.x * 8 + w;
    const float4* row = (const float4*)(s1 + (size_t)b * 1024);
    float4 xv[8];
#pragma unroll
    for (int j = 0; j < 8; j++) xv[j] = row[lane + j * 32];
#pragma unroll
    for (int p = 0; p < 8; p++) {
        const float4* wr = (const float4*)(w2s + p * 1024);
        float acc = 0.f;
#pragma unroll
        for (int j = 0; j < 8; j++) {
            float4 wv = wr[lane + j * 32];
            acc += xv[j].x * wv.x + xv[j].y * wv.y + xv[j].z * wv.z + xv[j].w * wv.w;
        }
        for (int o = 16; o > 0; o >>= 1) acc += __shfl_xor_sync(0xffffffffu, acc, o);
        if (lane == 0) proj[(size_t)b * 8 + p] = acc + bss[p];
    }
}

// ================= launch =================
extern "C" void kernel_launch(void* const* d_in, const int* in_sizes, int n_in,
                              void* d_out, int out_size) {
    const float* x      = (const float*)d_in[0];
    const float* W1     = (const float*)d_in[1];
    const float* b1     = (const float*)d_in[2];
    const float* g1     = (const float*)d_in[3];
    const float* beta1  = (const float*)d_in[4];
    const float* W2     = (const float*)d_in[5];
    const float* b2     = (const float*)d_in[6];
    const float* edge_w = (const float*)d_in[7];
    const float* mask   = (const float*)d_in[8];
    const float* Wi     = (const float*)d_in[9];
    const float* bi     = (const float*)d_in[10];
    const float* Wf     = (const float*)d_in[11];
    const float* bf     = (const float*)d_in[12];
    const float* Wslow  = (const float*)d_in[13];
    const float* bslow  = (const float*)d_in[14];
    const float* u      = (const float*)d_in[15];
    const float* Wfast  = (const float*)d_in[16];
    const float* Wo     = (const float*)d_in[17];
    const float* bo     = (const float*)d_in[18];
    const float* gln    = (const float*)d_in[19];
    const float* bln    = (const float*)d_in[20];
    const float* h_prev = (const float*)d_in[21];
    const float* memory = (const float*)d_in[22];
    const float* Wh     = (const float*)d_in[23];
    const float* bh     = (const float*)d_in[24];
    const float* Ws1    = (const float*)d_in[25];
    const float* bs1    = (const float*)d_in[26];
    const float* Ws2    = (const float*)d_in[27];
    const float* bs2    = (const float*)d_in[28];

    float* out    = (float*)d_out;
    float* logits = out;
    float* proj   = out + (size_t)Bn * Ccls;
    float* xflat  = proj + (size_t)Bn * Pp;

    float *p_h1, *p_b2a, *p_xagg, *p_sim, *p_s1, *p_bhm;
    cudaGetSymbolAddress((void**)&p_h1, g_h1);
    cudaGetSymbolAddress((void**)&p_b2a, g_b2a);
    cudaGetSymbolAddress((void**)&p_xagg, g_xagg);
    cudaGetSymbolAddress((void**)&p_sim, g_sim);
    cudaGetSymbolAddress((void**)&p_s1, g_s1);
    cudaGetSymbolAddress((void**)&p_bhm, g_bhm);
    void *p_xh, *p_xl, *p_W1h, *p_W1l, *p_h1h, *p_h1l, *p_W2h, *p_W2l;
    void *p_xfh, *p_xfl, *p_Whmh, *p_Whml, *p_Ws1h, *p_Ws1l, *p_memh, *p_meml;
    cudaGetSymbolAddress(&p_xh, g_xh);   cudaGetSymbolAddress(&p_xl, g_xl);
    cudaGetSymbolAddress(&p_W1h, g_W1h); cudaGetSymbolAddress(&p_W1l, g_W1l);
    cudaGetSymbolAddress(&p_h1h, g_h1h); cudaGetSymbolAddress(&p_h1l, g_h1l);
    cudaGetSymbolAddress(&p_W2h, g_W2h); cudaGetSymbolAddress(&p_W2l, g_W2l);
    cudaGetSymbolAddress(&p_xfh, g_xfh); cudaGetSymbolAddress(&p_xfl, g_xfl);
    cudaGetSymbolAddress(&p_Whmh, g_Whmh); cudaGetSymbolAddress(&p_Whml, g_Whml);
    cudaGetSymbolAddress(&p_Ws1h, g_Ws1h); cudaGetSymbolAddress(&p_Ws1l, g_Ws1l);
    cudaGetSymbolAddress(&p_memh, g_memh); cudaGetSymbolAddress(&p_meml, g_meml);

    cudaFuncSetAttribute(cell_kernel, cudaFuncAttributeMaxDynamicSharedMemorySize, CELL_SMEM);
    cudaFuncSetAttribute(gemm_mma<4, 3>, cudaFuncAttributeMaxDynamicSharedMemorySize, GSMEM_TOTAL);
    cudaFuncSetAttribute(gemm_mma<4, 2>, cudaFuncAttributeMaxDynamicSharedMemorySize, GSMEM_TOTAL);
    cudaFuncSetAttribute(gemm_mma<4, 1>, cudaFuncAttributeMaxDynamicSharedMemorySize, GSMEM_TOTAL);
    cudaFuncSetAttribute(gemm_mma<2, 3>, cudaFuncAttributeMaxDynamicSharedMemorySize, GSMEM_TOTAL);

    // prep + conversions
    prep_adj<<<1, 64>>>(edge_w, mask);
    fold_w2<<<dim3(8, 64), 256>>>(W2);
    prep_b2a<<<64, 64>>>(b2);
    prep_node<<<64, 64>>>(Wslow, u, Wfast, Wf, bf, h_prev);
    prep_whm_bf<<<(1024 * FLAT / 4 + 255) / 256, 256>>>(Wh);
    prep_bhm<<<4, 256>>>(bh);
    cvt_hilo<<<(Bn * Fdim / 4 + 255) / 256, 256>>>(x, (uint2*)p_xh, (uint2*)p_xl, Bn * Fdim / 4);
    cvt_hilo<<<(Hdim * Fdim / 4 + 255) / 256, 256>>>(W1, (uint2*)p_W1h, (uint2*)p_W1l, Hdim * Fdim / 4);
    cvt_hilo<<<(Hdim * FLAT / 4 + 255) / 256, 256>>>(Ws1, (uint2*)p_Ws1h, (uint2*)p_Ws1l, Hdim * FLAT / 4);
    cvt_mem_pad<<<(128 * FLAT / 4 + 255) / 256, 256>>>(memory);

    // stage 1: input projection (3-pass); G2 -> x_agg (2-pass: error ~2^-12 into smooth cell path)
    gemm_mma<4, 3><<<dim3(Hdim / 128, Bn / 128), 256, GSMEM_TOTAL>>>(
        (const __half*)p_xh, (const __half*)p_xl,
        (const __half*)p_W1h, (const __half*)p_W1l, b1, p_h1,
        Fdim, Fdim, Hdim, 0, 0);
    ln_gelu_kernel<<<Bn, 256>>>(p_h1, g1, beta1, (uint2*)p_h1h, (uint2*)p_h1l);
    gemm_mma<4, 2><<<dim3(FLAT / 128, Bn / 128), 256, GSMEM_TOTAL>>>(
        (const __half*)p_h1h, nullptr,
        (const __half*)p_W2h, (const __half*)p_W2l, p_b2a, p_xagg,
        Hdim, Hdim, FLAT, 0, 0);

    // stage 2: cells
    cell_kernel<<<dim3(Nn, Bn / 64), 256, CELL_SMEM>>>(Wi, Wf, Wo, bi, bslow, bo,
                                                       h_prev, gln, bln, xflat,
                                                       (uint32_t*)p_xfh, (uint32_t*)p_xfl);

    // stage 3: retrieval (split-K sim GEMM, atomic accumulate; 3-pass keeps top-k tight)
    zero_sim<<<Bn * CAP / 256, 256>>>();
    gemm_mma<2, 3><<<dim3(1, Bn / 128, 4), 256, GSMEM_TOTAL>>>(
        (const __half*)p_xfh, (const __half*)p_xfl,
        (const __half*)p_memh, (const __half*)p_meml, nullptr, p_sim,
        FLAT / 4, FLAT, CAP, 0, 1);
    retrieve_kernel<<<Bn, 256>>>(memory, xflat, (uint2*)p_xfh, (uint2*)p_xfl);

    // stage 4: heads (1-pass fp16: smooth error, no top-k dependence)
    gemm_mma<4, 1><<<dim3(1024 / 128, Bn / 128), 256, GSMEM_TOTAL>>>(
        (const __half*)p_xfh, nullptr,
        (const __half*)p_Whmh, nullptr, p_bhm, logits,
        FLAT, FLAT, Ccls, 0, 0);
    gemm_mma<4, 1><<<dim3(Hdim / 128, Bn / 128), 256, GSMEM_TOTAL>>>(
        (const __half*)p_xfh, nullptr,
        (const __half*)p_Ws1h, nullptr, bs1, p_s1,
        FLAT, FLAT, Hdim, 1, 0);
    proj2_kernel<<<Bn / 8, 256>>>(p_s1, Ws2, bs2, proj);
}

// round 13
// speedup vs baseline: 1.4853x; 1.0136x over previous
#include <cuda_runtime.h>
#include <cuda_fp16.h>
#include <math.h>
#include <stdint.h>

#define Bn 4096
#define Fdim 512
#define Hdim 1024
#define Nn 64
#define Dd 64
#define FLAT 4096
#define Ccls 1000
#define CAP 64
#define Pp 8

// ================= scratch (device globals) =================
__device__ float g_h1[Bn * Hdim];
__device__ float g_b2a[FLAT];
__device__ float g_xagg[(size_t)Bn * FLAT];
__device__ float g_sim[Bn * CAP];
__device__ float g_s1[Bn * Hdim];
__device__ float g_bhm[1024];
__device__ float g_adj[Nn * Nn];
__device__ float g_WcT[Nn * Dd * Dd];
__device__ float g_cf[Nn * Dd];
// fp16 hi/lo operand buffers
__device__ __half g_xh[Bn * Fdim],    g_xl[Bn * Fdim];
__device__ __half g_W1h[Hdim * Fdim], g_W1l[Hdim * Fdim];
__device__ __half g_h1h[Bn * Hdim],   g_h1l[Bn * Hdim];
__device__ __half g_W2h[FLAT * Hdim], g_W2l[FLAT * Hdim];
__device__ __half g_xfh[(size_t)Bn * FLAT], g_xfl[(size_t)Bn * FLAT];
__device__ __half g_Whmh[1024 * FLAT], g_Whml[1024 * FLAT];
__device__ __half g_Ws1h[Hdim * FLAT], g_Ws1l[Hdim * FLAT];
__device__ __half g_memh[128 * FLAT], g_meml[128 * FLAT];

__device__ __forceinline__ float sigmoidf_(float x) { return 1.f / (1.f + expf(-x)); }

__device__ __forceinline__ uint32_t pack2h(__half a, __half b) {
    return (uint32_t)__half_as_ushort(a) | ((uint32_t)__half_as_ushort(b) << 16);
}
__device__ __forceinline__ void cvt4(float4 v, uint2& hi, uint2& lo) {
    __half h0 = __float2half_rn(v.x), h1 = __float2half_rn(v.y);
    __half h2 = __float2half_rn(v.z), h3 = __float2half_rn(v.w);
    __half l0 = __float2half_rn(v.x - __half2float(h0));
    __half l1 = __float2half_rn(v.y - __half2float(h1));
    __half l2 = __float2half_rn(v.z - __half2float(h2));
    __half l3 = __float2half_rn(v.w - __half2float(h3));
    hi.x = pack2h(h0, h1); hi.y = pack2h(h2, h3);
    lo.x = pack2h(l0, l1); lo.y = pack2h(l2, l3);
}
__device__ __forceinline__ void cvt2(float a, float b, uint32_t& hi, uint32_t& lo) {
    __half h0 = __float2half_rn(a), h1 = __float2half_rn(b);
    __half l0 = __float2half_rn(a - __half2float(h0));
    __half l1 = __float2half_rn(b - __half2float(h1));
    hi = pack2h(h0, h1); lo = pack2h(l0, l1);
}

// ================= packed f32x2 FMA (Blackwell; two independent fma.rn.f32) =================
#define FMA_F32X2(d, a, b) \
    asm("fma.rn.f32x2 %0, %1, %2, %0;" : "+l"(d) : "l"(a), "l"(b))
#define PACKF2(out, a, b) \
    asm("mov.b64 %0, {%1, %2};" : "=l"(out) : "f"(a), "f"(b))
#define UNPACKF2(a, b, in) \
    asm("mov.b64 {%0, %1}, %2;" : "=f"(a), "=f"(b) : "l"(in))

// ================= mma / cp.async / ldmatrix primitives =================
__device__ __forceinline__ uint32_t smem_u32(const void* p) {
    uint32_t a;
    asm("{ .reg .u64 t; cvta.to.shared.u64 t, %1; cvt.u32.u64 %0, t; }" : "=r"(a) : "l"(p));
    return a;
}
__device__ __forceinline__ void cp16(uint32_t s, const void* g) {
    asm volatile("cp.async.cg.shared.global [%0], [%1], 16;" :: "r"(s), "l"(g));
}
#define CP_COMMIT() asm volatile("cp.async.commit_group;")
#define CP_WAIT1() asm volatile("cp.async.wait_group 1;")

__device__ __forceinline__ void mma16816(float* d, const uint32_t* a, uint32_t b0, uint32_t b1) {
    asm volatile(
        "mma.sync.aligned.m16n8k16.row.col.f32.f16.f16.f32 "
        "{%0,%1,%2,%3}, {%4,%5,%6,%7}, {%8,%9}, {%0,%1,%2,%3};"
        : "+f"(d[0]), "+f"(d[1]), "+f"(d[2]), "+f"(d[3])
        : "r"(a[0]), "r"(a[1]), "r"(a[2]), "r"(a[3]), "r"(b0), "r"(b1));
}
__device__ __forceinline__ void ldsm_x4(uint32_t& r0, uint32_t& r1, uint32_t& r2, uint32_t& r3,
                                        uint32_t addr) {
    asm volatile("ldmatrix.sync.aligned.m8n8.x4.shared.b16 {%0,%1,%2,%3}, [%4];"
                 : "=r"(r0), "=r"(r1), "=r"(r2), "=r"(r3) : "r"(addr));
}

// ================= conversion kernels =================
__global__ void cvt_hilo(const float* __restrict__ src, uint2* __restrict__ hi,
                         uint2* __restrict__ lo, int n4) {
    int i = blockIdx.x * 256 + threadIdx.x;
    if (i < n4) {
        float4 v = ((const float4*)src)[i];
        uint2 h, l; cvt4(v, h, l);
        hi[i] = h; lo[i] = l;
    }
}
__global__ void cvt_mem_pad(const float* __restrict__ mem) {
    int i = blockIdx.x * 256 + threadIdx.x;
    if (i >= 128 * FLAT / 4) return;
    int row = i >> 10;
    uint2 h = make_uint2(0u, 0u), l = make_uint2(0u, 0u);
    if (row < CAP) {
        float4 v = ((const float4*)mem)[i];
        cvt4(v, h, l);
    }
    ((uint2*)g_memh)[i] = h; ((uint2*)g_meml)[i] = l;
}

// ================= prep kernels =================
__global__ void prep_adj(const float* __restrict__ edge_w, const float* __restrict__ mask) {
    __shared__ float t[64 * 64];
    int r = threadIdx.x;
    float sum = 0.f;
    for (int c = 0; c < 64; c++) {
        float v = sigmoidf_(edge_w[r * 64 + c] * 1.5f) * mask[r * 64 + c];
        t[r * 64 + c] = v; sum += v;
    }
    float inv = 1.f / fmaxf(sum, 1e-6f);
    for (int c = 0; c < 64; c++) g_adj[r * 64 + c] = t[r * 64 + c] * inv;
}

__global__ void __launch_bounds__(256) fold_w2(const float* __restrict__ W2) {
    int kt = blockIdx.x;
    int d  = blockIdx.y;
    __shared__ float tile[64][128];
    __shared__ float adjT[64 * 64];
    int tid = threadIdx.x;
    for (int i = tid; i < 4096; i += 256) {
        int m = i >> 6, n = i & 63;
        adjT[i] = g_adj[n * 64 + m];
    }
    for (int i = tid; i < 64 * 32; i += 256) {
        int m = i >> 5, c4 = (i & 31) << 2;
        *(float4*)&tile[m][c4] = *(const float4*)(W2 + (size_t)(m * 64 + d) * Hdim + kt * 128 + c4);
    }
    __syncthreads();
    int n = tid & 63;
    int kq = tid >> 6;
    float4 acc[8];
#pragma unroll
    for (int q = 0; q < 8; q++) acc[q] = make_float4(0.f, 0.f, 0.f, 0.f);
    for (int m = 0; m < 64; m++) {
        float s = adjT[m * 64 + n];
        const float4* trow = (const float4*)&tile[m][kq * 32];
#pragma unroll
        for (int q = 0; q < 8; q++) {
            float4 t4 = trow[q];
            acc[q].x += s * t4.x; acc[q].y += s * t4.y;
            acc[q].z += s * t4.z; acc[q].w += s * t4.w;
        }
    }
    size_t off4 = ((size_t)(n * 64 + d) * Hdim + kt * 128 + kq * 32) >> 2;
#pragma unroll
    for (int q = 0; q < 8; q++) {
        uint2 h, l; cvt4(acc[q], h, l);
        ((uint2*)g_W2h)[off4 + q] = h;
        ((uint2*)g_W2l)[off4 + q] = l;
    }
}
__global__ void prep_b2a(const float* __restrict__ b2) {
    int nd = blockIdx.x * 64 + threadIdx.x;
    int n = nd >> 6, d = nd & 63;
    float acc = 0.f;
    for (int m = 0; m < 64; m++) acc += g_adj[n * 64 + m] * b2[m * 64 + d];
    g_b2a[nd] = acc;
}

__global__ void prep_node(const float* __restrict__ Wslow, const float* __restrict__ u,
                          const float* __restrict__ Wfast, const float* __restrict__ Wf,
                          const float* __restrict__ bf, const float* __restrict__ hprev) {
    int n = blockIdx.x;
    int t = threadIdx.x;
    __shared__ float us[64], v[64], red[64];
    const float* Ws = Wslow + (size_t)n * 4096;
    us[t] = u[n * 64 + t];
    __syncthreads();
    float acc = 0.f;
    for (int o = 0; o < 64; o++) acc += Ws[o * 64 + t] * us[o];
    v[t] = acc;
    __syncthreads();
    float wv = 0.f;
    for (int i = 0; i < 64; i++) wv += Ws[t * 64 + i] * v[i];
    red[t] = us[t] * wv;
    __syncthreads();
    for (int off = 32; off > 0; off >>= 1) {
        if (t < off) red[t] += red[t + off];
        __syncthreads();
    }
    float inv = 1.f / (red[0] + 1e-8f);
    const float* Wfa = Wfast + (size_t)n * 4096;
    float* out = g_WcT + (size_t)n * 4096;
    for (int idx = t; idx < 4096; idx += 64) {
        int i = idx >> 6, o = idx & 63;
        out[idx] = Ws[o * 64 + i] * inv + Wfa[o * 64 + i];
    }
    float c = bf[n * 64 + t];
    const float* Wf2 = Wf + (size_t)n * 8192 + 4096;
    for (int i = 0; i < 64; i++) c += hprev[n * 64 + i] * Wf2[i * 64 + t];
    g_cf[n * 64 + t] = c;
}

__global__ void prep_whm_bf(const float* __restrict__ Wh) {
    int i = blockIdx.x * 256 + threadIdx.x;
    if (i >= (1024 * FLAT) / 4) return;
    int row = i >> 10;
    uint2 h, l;
    if (row < Ccls) {
        const size_t CF4 = (size_t)Ccls * FLAT / 4;
        const float4* W4 = (const float4*)Wh;
        float4 a = W4[i], b = W4[i + CF4], c = W4[i + 2 * CF4];
        float4 m = make_float4((a.x + b.x + c.x) * (1.f / 3.f), (a.y + b.y + c.y) * (1.f / 3.f),
                               (a.z + b.z + c.z) * (1.f / 3.f), (a.w + b.w + c.w) * (1.f / 3.f));
        cvt4(m, h, l);
    } else {
        h = make_uint2(0u, 0u); l = make_uint2(0u, 0u);
    }
    ((uint2*)g_Whmh)[i] = h; ((uint2*)g_Whml)[i] = l;
}
__global__ void prep_bhm(const float* __restrict__ bh) {
    int i = blockIdx.x * 256 + threadIdx.x;
    if (i < 1024) g_bhm[i] = (i < Ccls) ? (bh[i] + bh[i + Ccls] + bh[i + 2 * Ccls]) * (1.f / 3.f) : 0.f;
}
__global__ void zero_sim() {
    g_sim[blockIdx.x * 256 + threadIdx.x] = 0.f;
}

// ================= split-fp16 HMMA GEMM =================
// PASSES: 3 = Ah*Bh + Ah*Bl + Al*Bh; 2 = Ah*Bh + Ah*Bl; 1 = Ah*Bh only.
#define TSTRIDE 40
#define ROWB (TSTRIDE * 2)
#define TILE_B (128 * ROWB)
#define STAGE_B (4 * TILE_B)
#define GSMEM_TOTAL (2 * STAGE_B)

template <int NI, int PASSES>
__global__ void __launch_bounds__(256, 2) gemm_mma(
    const __half* __restrict__ Ahi, const __half* __restrict__ Alo,
    const __half* __restrict__ Bhi, const __half* __restrict__ Blo,
    const float* __restrict__ bias, float* __restrict__ C,
    int K, int lda, int Nstore, int act, int atomicOut) {
    extern __shared__ char smem[];
    const int tid = threadIdx.x;
    const int wid = tid >> 5;
    const int lane = tid & 31;
    const int grp = lane >> 2;
    const int qp = lane & 3;
    const int wm = (wid >> 2) * 64;
    const int wn = (wid & 3) * (NI * 8);
    const int bm = blockIdx.y * 128;
    const int bn = blockIdx.x * 128;
    const int kbase = blockIdx.z * K;
    const uint32_t sb = smem_u32(smem);

    const int row = tid >> 2;
    const int c16 = tid & 3;

    const int aRowL = wm + (lane & 7) + ((lane >> 3) & 1) * 8;
    const int aKL = (lane >> 4) * 8;
    const int bRowL = wn + (lane & 7) + (lane >> 4) * 8;
    const int bKL = ((lane >> 3) & 1) * 8;

    float acc[4][NI][4];
#pragma unroll
    for (int mi = 0; mi < 4; mi++)
#pragma unroll
        for (int ni = 0; ni < NI; ni++)
#pragma unroll
            for (int j = 0; j < 4; j++) acc[mi][ni][j] = 0.f;

    const int nc = K >> 5;

    auto issue = [&](int c, int s) {
        const uint32_t ss = sb + s * STAGE_B;
        const int k0 = c << 5;
#pragma unroll
        for (int t = 0; t < 2; t++) {
            const int r = row + t * 64;
            const uint32_t so = (uint32_t)r * ROWB + c16 * 16;
            const size_t gAoff = ((size_t)(bm + r) * lda + kbase + k0) * 2 + c16 * 16;
            const size_t gBoff = ((size_t)(bn + r) * lda + kbase + k0) * 2 + c16 * 16;
            cp16(ss + 0 * TILE_B + so, (const char*)Ahi + gAoff);
            if (PASSES == 3) cp16(ss + 1 * TILE_B + so, (const char*)Alo + gAoff);
            cp16(ss + 2 * TILE_B + so, (const char*)Bhi + gBoff);
            if (PASSES >= 2) cp16(ss + 3 * TILE_B + so, (const char*)Blo + gBoff);
        }
    };

    issue(0, 0); CP_COMMIT();
    if (nc > 1) issue(1, 1);
    CP_COMMIT();

    for (int c = 0; c < nc; c++) {
        const int s = c & 1;
        CP_WAIT1();
        __syncthreads();
        const uint32_t st = sb + s * STAGE_B;
#pragma unroll
        for (int ks = 0; ks < 2; ks++) {
            const int k0 = ks * 16;
            uint32_t ah[4][4], al[4][4];
#pragma unroll
            for (int mi = 0; mi < 4; mi++) {
                const uint32_t ad = st + (uint32_t)(aRowL + mi * 16) * ROWB + (k0 + aKL) * 2;
                ldsm_x4(ah[mi][0], ah[mi][1], ah[mi][2], ah[mi][3], ad);
                if (PASSES == 3) ldsm_x4(al[mi][0], al[mi][1], al[mi][2], al[mi][3], ad + TILE_B);
            }
            uint32_t bh[NI][2], bl[NI][2];
#pragma unroll
            for (int p = 0; p < NI / 2; p++) {
                const uint32_t bd = st + 2 * TILE_B + (uint32_t)(bRowL + p * 16) * ROWB + (k0 + bKL) * 2;
                uint32_t r0, r1, r2, r3;
                ldsm_x4(r0, r1, r2, r3, bd);
                bh[2 * p][0] = r0; bh[2 * p][1] = r1; bh[2 * p + 1][0] = r2; bh[2 * p + 1][1] = r3;
                if (PASSES >= 2) {
                    ldsm_x4(r0, r1, r2, r3, bd + TILE_B);
                    bl[2 * p][0] = r0; bl[2 * p][1] = r1; bl[2 * p + 1][0] = r2; bl[2 * p + 1][1] = r3;
                }
            }
#pragma unroll
            for (int ni = 0; ni < NI; ni++) {
#pragma unroll
                for (int mi = 0; mi < 4; mi++) {
                    mma16816(acc[mi][ni], ah[mi], bh[ni][0], bh[ni][1]);
                    if (PASSES >= 2) mma16816(acc[mi][ni], ah[mi], bl[ni][0], bl[ni][1]);
                    if (PASSES == 3) mma16816(acc[mi][ni], al[mi], bh[ni][0], bh[ni][1]);
                }
            }
        }
        __syncthreads();
        if (c + 2 < nc) issue(c + 2, s);
        CP_COMMIT();
    }

    // epilogue
#pragma unroll
    for (int mi = 0; mi < 4; mi++) {
#pragma unroll
        for (int ni = 0; ni < NI; ni++) {
            const int r0 = bm + wm + mi * 16 + grp;
            const int col = bn + wn + ni * 8 + qp * 2;
            float* a4 = acc[mi][ni];
            if (atomicOut) {
                if (col < Nstore) {
                    atomicAdd(&C[(size_t)r0 * Nstore + col], a4[0]);
                    atomicAdd(&C[(size_t)(r0 + 8) * Nstore + col], a4[2]);
                    if (col + 1 < Nstore) {
                        atomicAdd(&C[(size_t)r0 * Nstore + col + 1], a4[1]);
                        atomicAdd(&C[(size_t)(r0 + 8) * Nstore + col + 1], a4[3]);
                    }
                }
            } else if (col + 1 < Nstore) {
                float2 v0, v1;
                float bb0 = bias ? bias[col] : 0.f;
                float bb1 = bias ? bias[col + 1] : 0.f;
                v0.x = a4[0] + bb0; v0.y = a4[1] + bb1;
                v1.x = a4[2] + bb0; v1.y = a4[3] + bb1;
                if (act == 1) {
                    v0.x = fmaxf(v0.x, 0.f); v0.y = fmaxf(v0.y, 0.f);
                    v1.x = fmaxf(v1.x, 0.f); v1.y = fmaxf(v1.y, 0.f);
                }
                *(float2*)(C + (size_t)r0 * Nstore + col) = v0;
                *(float2*)(C + (size_t)(r0 + 8) * Nstore + col) = v1;
            } else if (col < Nstore) {
                float bb0 = bias ? bias[col] : 0.f;
                float v0 = a4[0] + bb0, v1 = a4[2] + bb0;
                if (act == 1) { v0 = fmaxf(v0, 0.f); v1 = fmaxf(v1, 0.f); }
                C[(size_t)r0 * Nstore + col] = v0;
                C[(size_t)(r0 + 8) * Nstore + col] = v1;
            }
        }
    }
}

// ================= LayerNorm(H=1024) + GELU -> fp16 hi/lo =================
__global__ void __launch_bounds__(256) ln_gelu_kernel(const float* __restrict__ h,
                                                      const float* __restrict__ g,
                                                      const float* __restrict__ beta,
                                                      uint2* __restrict__ hi,
                                                      uint2* __restrict__ lo) {
    int row = blockIdx.x;
    const float* hr = h + (size_t)row * Hdim;
    int tid = threadIdx.x;
    float4 v = *(const float4*)(hr + tid * 4);
    float s = v.x + v.y + v.z + v.w;
    float ss = v.x * v.x + v.y * v.y + v.z * v.z + v.w * v.w;
    __shared__ float rs[8], rss[8];
    for (int o = 16; o > 0; o >>= 1) {
        s += __shfl_down_sync(0xffffffffu, s, o);
        ss += __shfl_down_sync(0xffffffffu, ss, o);
    }
    if ((tid & 31) == 0) { rs[tid >> 5] = s; rss[tid >> 5] = ss; }
    __syncthreads();
    if (tid < 32) {
        float a = tid < 8 ? rs[tid] : 0.f;
        float b = tid < 8 ? rss[tid] : 0.f;
        for (int o = 4; o > 0; o >>= 1) {
            a += __shfl_down_sync(0xffffffffu, a, o);
            b += __shfl_down_sync(0xffffffffu, b, o);
        }
        if (tid == 0) { rs[0] = a; rss[0] = b; }
    }
    __syncthreads();
    float mu = rs[0] * (1.f / Hdim);
    float var = rss[0] * (1.f / Hdim) - mu * mu;
    float inv = rsqrtf(var + 1e-5f);
    float4 gg = *(const float4*)(g + tid * 4);
    float4 bb = *(const float4*)(beta + tid * 4);
    float y;
    y = (v.x - mu) * inv * gg.x + bb.x; v.x = 0.5f * y * (1.f + erff(y * 0.70710678118654752f));
    y = (v.y - mu) * inv * gg.y + bb.y; v.y = 0.5f * y * (1.f + erff(y * 0.70710678118654752f));
    y = (v.z - mu) * inv * gg.z + bb.z; v.z = 0.5f * y * (1.f + erff(y * 0.70710678118654752f));
    y = (v.w - mu) * inv * gg.w + bb.w; v.w = 0.5f * y * (1.f + erff(y * 0.70710678118654752f));
    uint2 hh, ll; cvt4(v, hh, ll);
    hi[(size_t)row * 256 + tid] = hh;
    lo[(size_t)row * 256 + tid] = ll;
}

// ================= fused cell kernel (packed f32x2 FMA; emits fp16 hi/lo of xflat) =================
#define CELL_SMEM ((64 * 68 * 2 + 4096 * 4 + 7 * 64) * sizeof(float))
__global__ void __launch_bounds__(256) cell_kernel(const float* __restrict__ Wi,
                                                   const float* __restrict__ Wf,
                                                   const float* __restrict__ Wo,
                                                   const float* __restrict__ bi_g,
                                                   const float* __restrict__ bslow_g,
                                                   const float* __restrict__ bo_g,
                                                   const float* __restrict__ hprev_g,
                                                   const float* __restrict__ gln_g,
                                                   const float* __restrict__ bln_g,
                                                   float* __restrict__ xflat_out,
                                                   uint32_t* __restrict__ xfh,
                                                   uint32_t* __restrict__ xfl) {
    extern __shared__ float sf[];
    float* xs = sf;
    float* wi = xs + 64 * 68;
    float* wf = wi + 4096;
    float* wc = wf + 4096;
    float* wo = wc + 4096;
    float* hr = wo + 4096;
    float* vecs = hr + 64 * 68;

    int n = blockIdx.x;
    int b0 = blockIdx.y * 64;
    int tid = threadIdx.x;

#pragma unroll
    for (int j = 0; j < 4; j++) {
        int idx = tid + j * 256;
        int row = idx >> 4, c4 = (idx & 15) << 2;
        *(float4*)(xs + row * 68 + c4) =
            *(const float4*)(g_xagg + (((size_t)(b0 + row) * 64 + n) << 6) + c4);
        ((float4*)wi)[idx] = ((const float4*)(Wi + (size_t)n * 4096))[idx];
        ((float4*)wf)[idx] = ((const float4*)(Wf + (size_t)n * 8192))[idx];
        ((float4*)wc)[idx] = ((const float4*)(g_WcT + (size_t)n * 4096))[idx];
        ((float4*)wo)[idx] = ((const float4*)(Wo + (size_t)n * 4096))[idx];
    }
    if (tid < 64) {
        vecs[0 * 64 + tid] = bi_g[n * 64 + tid];
        vecs[1 * 64 + tid] = g_cf[n * 64 + tid];
        vecs[2 * 64 + tid] = bslow_g[n * 64 + tid];
        vecs[3 * 64 + tid] = bo_g[n * 64 + tid];
        vecs[4 * 64 + tid] = hprev_g[n * 64 + tid];
        vecs[5 * 64 + tid] = gln_g[n * 64 + tid];
        vecs[6 * 64 + tid] = bln_g[n * 64 + tid];
    }
    __syncthreads();

    const int r0 = (tid >> 4) * 4;
    const int c0 = (tid & 15) * 4;

    // packed accumulators: [r][pair], pair 0 = cols {c0,c0+1}, pair 1 = {c0+2,c0+3}
    unsigned long long ai2[4][2], af2[4][2], ac2[4][2];
#pragma unroll
    for (int r = 0; r < 4; r++)
#pragma unroll
        for (int p = 0; p < 2; p++) { ai2[r][p] = 0ull; af2[r][p] = 0ull; ac2[r][p] = 0ull; }

    for (int i = 0; i < 64; i++) {
        unsigned long long xp[4];
#pragma unroll
        for (int r = 0; r < 4; r++) {
            float xv = xs[(r0 + r) * 68 + i];
            PACKF2(xp[r], xv, xv);
        }
        float4 w1 = *(const float4*)(wi + i * 64 + c0);
        float4 w2 = *(const float4*)(wf + i * 64 + c0);
        float4 w3 = *(const float4*)(wc + i * 64 + c0);
        unsigned long long w1p[2], w2p[2], w3p[2];
        PACKF2(w1p[0], w1.x, w1.y); PACKF2(w1p[1], w1.z, w1.w);
        PACKF2(w2p[0], w2.x, w2.y); PACKF2(w2p[1], w2.z, w2.w);
        PACKF2(w3p[0], w3.x, w3.y); PACKF2(w3p[1], w3.z, w3.w);
#pragma unroll
        for (int r = 0; r < 4; r++) {
            FMA_F32X2(ai2[r][0], xp[r], w1p[0]); FMA_F32X2(ai2[r][1], xp[r], w1p[1]);
            FMA_F32X2(af2[r][0], xp[r], w2p[0]); FMA_F32X2(af2[r][1], xp[r], w2p[1]);
            FMA_F32X2(ac2[r][0], xp[r], w3p[0]); FMA_F32X2(ac2[r][1], xp[r], w3p[1]);
        }
    }
#pragma unroll
    for (int r = 0; r < 4; r++)
#pragma unroll
        for (int p = 0; p < 2; p++) {
            float aiv0, aiv1, afv0, afv1, acv0, acv1;
            UNPACKF2(aiv0, aiv1, ai2[r][p]);
            UNPACKF2(afv0, afv1, af2[r][p]);
            UNPACKF2(acv0, acv1, ac2[r][p]);
            int o = c0 + 2 * p;
            float it0 = sigmoidf_(aiv0 + vecs[0 * 64 + o]);
            float ft0 = sigmoidf_(afv0 + vecs[1 * 64 + o]);
            float hs0 = acv0 + vecs[2 * 64 + o];
            hr[(r0 + r) * 68 + o] = it0 * hs0 + ft0 * vecs[4 * 64 + o];
            float it1 = sigmoidf_(aiv1 + vecs[0 * 64 + o + 1]);
            float ft1 = sigmoidf_(afv1 + vecs[1 * 64 + o + 1]);
            float hs1 = acv1 + vecs[2 * 64 + o + 1];
            hr[(r0 + r) * 68 + o + 1] = it1 * hs1 + ft1 * vecs[4 * 64 + o + 1];
        }
    __syncthreads();

    unsigned long long ao2[4][2];
#pragma unroll
    for (int r = 0; r < 4; r++)
#pragma unroll
        for (int p = 0; p < 2; p++) ao2[r][p] = 0ull;
    for (int i = 0; i < 64; i++) {
        unsigned long long xp[4];
#pragma unroll
        for (int r = 0; r < 4; r++) {
            float xv = hr[(r0 + r) * 68 + i];
            PACKF2(xp[r], xv, xv);
        }
        float4 w = *(const float4*)(wo + i * 64 + c0);
        unsigned long long wp[2];
        PACKF2(wp[0], w.x, w.y); PACKF2(wp[1], w.z, w.w);
#pragma unroll
        for (int r = 0; r < 4; r++) {
            FMA_F32X2(ao2[r][0], xp[r], wp[0]);
            FMA_F32X2(ao2[r][1], xp[r], wp[1]);
        }
    }
    float* ys = xs;
#pragma unroll
    for (int r = 0; r < 4; r++)
#pragma unroll
        for (int p = 0; p < 2; p++) {
            float a0, a1;
            UNPACKF2(a0, a1, ao2[r][p]);
            int o = c0 + 2 * p;
            float ot0 = sigmoidf_(a0 + vecs[3 * 64 + o]);
            float ot1 = sigmoidf_(a1 + vecs[3 * 64 + o + 1]);
            ys[(r0 + r) * 68 + o] = ot0 * tanhf(hr[(r0 + r) * 68 + o]);
            ys[(r0 + r) * 68 + o + 1] = ot1 * tanhf(hr[(r0 + r) * 68 + o + 1]);
        }
    __syncthreads();

    int w = tid >> 5, lane = tid & 31;
    for (int rr = 0; rr < 8; rr++) {
        int row = w * 8 + rr;
        float v0 = ys[row * 68 + 2 * lane];
        float v1 = ys[row * 68 + 2 * lane + 1];
        float s = v0 + v1;
        float ss = v0 * v0 + v1 * v1;
        for (int o = 16; o > 0; o >>= 1) {
            s += __shfl_xor_sync(0xffffffffu, s, o);
            ss += __shfl_xor_sync(0xffffffffu, ss, o);
        }
        float mu = s * (1.f / 64.f);
        float var = ss * (1.f / 64.f) - mu * mu;
        float inv = rsqrtf(var + 1e-5f);
        float y0 = (v0 - mu) * inv * vecs[5 * 64 + 2 * lane] + vecs[6 * 64 + 2 * lane];
        float y1 = (v1 - mu) * inv * vecs[5 * 64 + 2 * lane + 1] + vecs[6 * 64 + 2 * lane + 1];
        size_t base = (size_t)(b0 + row) * 4096 + n * 64;
        *(float2*)(xflat_out + base + 2 * lane) = make_float2(y0, y1);
        uint32_t hh, ll; cvt2(y0, y1, hh, ll);
        xfh[(base >> 1) + lane] = hh;
        xfl[(base >> 1) + lane] = ll;
    }
}

// ================= top-5 retrieval + update + fp16 re-emit =================
__global__ void __launch_bounds__(256) retrieve_kernel(const float* __restrict__ mem,
                                                       float* __restrict__ xflat,
                                                       uint2* __restrict__ xfh,
                                                       uint2* __restrict__ xfl) {
    int b = blockIdx.x;
    __shared__ float s[64];
    __shared__ int top[5];
    int tid = threadIdx.x;
    if (tid < 64) s[tid] = g_sim[b * 64 + tid];
    __syncthreads();
    if (tid < 32) {
        for (int k = 0; k < 5; k++) {
            float v = s[tid]; int idx = tid;
            float v2 = s[tid + 32];
            if (v2 > v) { v = v2; idx = tid + 32; }
            for (int o = 16; o > 0; o >>= 1) {
                float ov = __shfl_down_sync(0xffffffffu, v, o);
                int oi = __shfl_down_sync(0xffffffffu, idx, o);
                if (ov > v || (ov == v && oi < idx)) { v = ov; idx = oi; }
            }
            idx = __shfl_sync(0xffffffffu, idx, 0);
            if (tid == 0) top[k] = idx;
            if (tid == 0) s[idx] = -INFINITY;
            __syncwarp();
        }
    }
    __syncthreads();
    const float4* m4 = (const float4*)mem;
    float4* x4 = (float4*)(xflat + (size_t)b * 4096);
    int t0 = top[0] * 1024, t1 = top[1] * 1024, t2 = top[2] * 1024, t3 = top[3] * 1024, t4 = top[4] * 1024;
#pragma unroll
    for (int j = 0; j < 4; j++) {
        int idx = tid + j * 256;
        float4 xv = x4[idx];
        float4 a = m4[t0 + idx], bb = m4[t1 + idx], c = m4[t2 + idx], d = m4[t3 + idx], e = m4[t4 + idx];
        xv.x += 0.02f * (a.x + bb.x + c.x + d.x + e.x);
        xv.y += 0.02f * (a.y + bb.y + c.y + d.y + e.y);
        xv.z += 0.02f * (a.z + bb.z + c.z + d.z + e.z);
        xv.w += 0.02f * (a.w + bb.w + c.w + d.w + e.w);
        x4[idx] = xv;
        uint2 h, l; cvt4(xv, h, l);
        xfh[(size_t)b * 1024 + idx] = h;
        xfl[(size_t)b * 1024 + idx] = l;
    }
}

// ================= proj2: proj[b, 0:8] = relu_s1[b,:] @ Ws2^T + bs2 =================
__global__ void __launch_bounds__(256) proj2_kernel(const float* __restrict__ s1,
                                                    const float* __restrict__ Ws2,
                                                    const float* __restrict__ bs2,
                                                    float* __restrict__ proj) {
    __shared__ float w2s[8 * 1024];
    __shared__ float bss[8];
    int tid = threadIdx.x;
    for (int i = tid; i < 8192; i += 256) w2s[i] = Ws2[i];
    if (tid < 8) bss[tid] = bs2[tid];
    __syncthreads();
    int w = tid >> 5, lane = tid & 31;
    int b = blockIdx.x * 8 + w;
    const float4* row = (const float4*)(s1 + (size_t)b * 1024);
    float4 xv[8];
#pragma unroll
    for (int j = 0; j < 8; j++) xv[j] = row[lane + j * 32];
#pragma unroll
    for (int p = 0; p < 8; p++) {
        const float4* wr = (const float4*)(w2s + p * 1024);
        float acc = 0.f;
#pragma unroll
        for (int j = 0; j < 8; j++) {
            float4 wv = wr[lane + j * 32];
            acc += xv[j].x * wv.x + xv[j].y * wv.y + xv[j].z * wv.z + xv[j].w * wv.w;
        }
        for (int o = 16; o > 0; o >>= 1) acc += __shfl_xor_sync(0xffffffffu, acc, o);
        if (lane == 0) proj[(size_t)b * 8 + p] = acc + bss[p];
    }
}

// ================= launch =================
extern "C" void kernel_launch(void* const* d_in, const int* in_sizes, int n_in,
                              void* d_out, int out_size) {
    const float* x      = (const float*)d_in[0];
    const float* W1     = (const float*)d_in[1];
    const float* b1     = (const float*)d_in[2];
    const float* g1     = (const float*)d_in[3];
    const float* beta1  = (const float*)d_in[4];
    const float* W2     = (const float*)d_in[5];
    const float* b2     = (const float*)d_in[6];
    const float* edge_w = (const float*)d_in[7];
    const float* mask   = (const float*)d_in[8];
    const float* Wi     = (const float*)d_in[9];
    const float* bi     = (const float*)d_in[10];
    const float* Wf     = (const float*)d_in[11];
    const float* bf     = (const float*)d_in[12];
    const float* Wslow  = (const float*)d_in[13];
    const float* bslow  = (const float*)d_in[14];
    const float* u      = (const float*)d_in[15];
    const float* Wfast  = (const float*)d_in[16];
    const float* Wo     = (const float*)d_in[17];
    const float* bo     = (const float*)d_in[18];
    const float* gln    = (const float*)d_in[19];
    const float* bln    = (const float*)d_in[20];
    const float* h_prev = (const float*)d_in[21];
    const float* memory = (const float*)d_in[22];
    const float* Wh     = (const float*)d_in[23];
    const float* bh     = (const float*)d_in[24];
    const float* Ws1    = (const float*)d_in[25];
    const float* bs1    = (const float*)d_in[26];
    const float* Ws2    = (const float*)d_in[27];
    const float* bs2    = (const float*)d_in[28];

    float* out    = (float*)d_out;
    float* logits = out;
    float* proj   = out + (size_t)Bn * Ccls;
    float* xflat  = proj + (size_t)Bn * Pp;

    float *p_h1, *p_b2a, *p_xagg, *p_sim, *p_s1, *p_bhm;
    cudaGetSymbolAddress((void**)&p_h1, g_h1);
    cudaGetSymbolAddress((void**)&p_b2a, g_b2a);
    cudaGetSymbolAddress((void**)&p_xagg, g_xagg);
    cudaGetSymbolAddress((void**)&p_sim, g_sim);
    cudaGetSymbolAddress((void**)&p_s1, g_s1);
    cudaGetSymbolAddress((void**)&p_bhm, g_bhm);
    void *p_xh, *p_xl, *p_W1h, *p_W1l, *p_h1h, *p_h1l, *p_W2h, *p_W2l;
    void *p_xfh, *p_xfl, *p_Whmh, *p_Whml, *p_Ws1h, *p_Ws1l, *p_memh, *p_meml;
    cudaGetSymbolAddress(&p_xh, g_xh);   cudaGetSymbolAddress(&p_xl, g_xl);
    cudaGetSymbolAddress(&p_W1h, g_W1h); cudaGetSymbolAddress(&p_W1l, g_W1l);
    cudaGetSymbolAddress(&p_h1h, g_h1h); cudaGetSymbolAddress(&p_h1l, g_h1l);
    cudaGetSymbolAddress(&p_W2h, g_W2h); cudaGetSymbolAddress(&p_W2l, g_W2l);
    cudaGetSymbolAddress(&p_xfh, g_xfh); cudaGetSymbolAddress(&p_xfl, g_xfl);
    cudaGetSymbolAddress(&p_Whmh, g_Whmh); cudaGetSymbolAddress(&p_Whml, g_Whml);
    cudaGetSymbolAddress(&p_Ws1h, g_Ws1h); cudaGetSymbolAddress(&p_Ws1l, g_Ws1l);
    cudaGetSymbolAddress(&p_memh, g_memh); cudaGetSymbolAddress(&p_meml, g_meml);

    cudaFuncSetAttribute(cell_kernel, cudaFuncAttributeMaxDynamicSharedMemorySize, CELL_SMEM);
    cudaFuncSetAttribute(gemm_mma<4, 3>, cudaFuncAttributeMaxDynamicSharedMemorySize, GSMEM_TOTAL);
    cudaFuncSetAttribute(gemm_mma<4, 2>, cudaFuncAttributeMaxDynamicSharedMemorySize, GSMEM_TOTAL);
    cudaFuncSetAttribute(gemm_mma<4, 1>, cudaFuncAttributeMaxDynamicSharedMemorySize, GSMEM_TOTAL);
    cudaFuncSetAttribute(gemm_mma<2, 3>, cudaFuncAttributeMaxDynamicSharedMemorySize, GSMEM_TOTAL);

    // prep + conversions
    prep_adj<<<1, 64>>>(edge_w, mask);
    fold_w2<<<dim3(8, 64), 256>>>(W2);
    prep_b2a<<<64, 64>>>(b2);
    prep_node<<<64, 64>>>(Wslow, u, Wfast, Wf, bf, h_prev);
    prep_whm_bf<<<(1024 * FLAT / 4 + 255) / 256, 256>>>(Wh);
    prep_bhm<<<4, 256>>>(bh);
    cvt_hilo<<<(Bn * Fdim / 4 + 255) / 256, 256>>>(x, (uint2*)p_xh, (uint2*)p_xl, Bn * Fdim / 4);
    cvt_hilo<<<(Hdim * Fdim / 4 + 255) / 256, 256>>>(W1, (uint2*)p_W1h, (uint2*)p_W1l, Hdim * Fdim / 4);
    cvt_hilo<<<(Hdim * FLAT / 4 + 255) / 256, 256>>>(Ws1, (uint2*)p_Ws1h, (uint2*)p_Ws1l, Hdim * FLAT / 4);
    cvt_mem_pad<<<(128 * FLAT / 4 + 255) / 256, 256>>>(memory);

    // stage 1: input projection (3-pass); G2 -> x_agg (2-pass)
    gemm_mma<4, 3><<<dim3(Hdim / 128, Bn / 128), 256, GSMEM_TOTAL>>>(
        (const __half*)p_xh, (const __half*)p_xl,
        (const __half*)p_W1h, (const __half*)p_W1l, b1, p_h1,
        Fdim, Fdim, Hdim, 0, 0);
    ln_gelu_kernel<<<Bn, 256>>>(p_h1, g1, beta1, (uint2*)p_h1h, (uint2*)p_h1l);
    gemm_mma<4, 2><<<dim3(FLAT / 128, Bn / 128), 256, GSMEM_TOTAL>>>(
        (const __half*)p_h1h, nullptr,
        (const __half*)p_W2h, (const __half*)p_W2l, p_b2a, p_xagg,
        Hdim, Hdim, FLAT, 0, 0);

    // stage 2: cells (packed f32x2 FMA; bit-identical results)
    cell_kernel<<<dim3(Nn, Bn / 64), 256, CELL_SMEM>>>(Wi, Wf, Wo, bi, bslow, bo,
                                                       h_prev, gln, bln, xflat,
                                                       (uint32_t*)p_xfh, (uint32_t*)p_xfl);

    // stage 3: retrieval (split-K sim GEMM, atomic accumulate; 3-pass keeps top-k tight)
    zero_sim<<<Bn * CAP / 256, 256>>>();
    gemm_mma<2, 3><<<dim3(1, Bn / 128, 4), 256, GSMEM_TOTAL>>>(
        (const __half*)p_xfh, (const __half*)p_xfl,
        (const __half*)p_memh, (const __half*)p_meml, nullptr, p_sim,
        FLAT / 4, FLAT, CAP, 0, 1);
    retrieve_kernel<<<Bn, 256>>>(memory, xflat, (uint2*)p_xfh, (uint2*)p_xfl);

    // stage 4: heads (1-pass fp16: smooth error, no top-k dependence)
    gemm_mma<4, 1><<<dim3(1024 / 128, Bn / 128), 256, GSMEM_TOTAL>>>(
        (const __half*)p_xfh, nullptr,
        (const __half*)p_Whmh, nullptr, p_bhm, logits,
        FLAT, FLAT, Ccls, 0, 0);
    gemm_mma<4, 1><<<dim3(Hdim / 128, Bn / 128), 256, GSMEM_TOTAL>>>(
        (const __half*)p_xfh, nullptr,
        (const __half*)p_Ws1h, nullptr, bs1, p_s1,
        FLAT, FLAT, Hdim, 1, 0);
    proj2_kernel<<<Bn / 8, 256>>>(p_s1, Ws2, bs2, proj);
}

// round 14
// speedup vs baseline: 1.4872x; 1.0013x over previous
#include <cuda_runtime.h>
#include <cuda_fp16.h>
#include <math.h>
#include <stdint.h>

#define Bn 4096
#define Fdim 512
#define Hdim 1024
#define Nn 64
#define Dd 64
#define FLAT 4096
#define Ccls 1000
#define CAP 64
#define Pp 8

// ================= scratch (device globals) =================
__device__ float g_h1[Bn * Hdim];
__device__ float g_b2a[FLAT];
__device__ float g_xagg[(size_t)Bn * FLAT];
__device__ float g_sim[Bn * CAP];
__device__ float g_s1[Bn * Hdim];
__device__ float g_bhm[1024];
__device__ float g_adj[Nn * Nn];
__device__ float g_WcT[Nn * Dd * Dd];
__device__ float g_cf[Nn * Dd];
// fp16 hi/lo operand buffers
__device__ __half g_xh[Bn * Fdim],    g_xl[Bn * Fdim];
__device__ __half g_W1h[Hdim * Fdim], g_W1l[Hdim * Fdim];
__device__ __half g_h1h[Bn * Hdim],   g_h1l[Bn * Hdim];
__device__ __half g_W2h[FLAT * Hdim], g_W2l[FLAT * Hdim];
__device__ __half g_xfh[(size_t)Bn * FLAT], g_xfl[(size_t)Bn * FLAT];
__device__ __half g_Whmh[1024 * FLAT], g_Whml[1024 * FLAT];
__device__ __half g_Ws1h[Hdim * FLAT], g_Ws1l[Hdim * FLAT];
__device__ __half g_memh[128 * FLAT], g_meml[128 * FLAT];

__device__ __forceinline__ float sigmoidf_(float x) { return 1.f / (1.f + expf(-x)); }

__device__ __forceinline__ uint32_t pack2h(__half a, __half b) {
    return (uint32_t)__half_as_ushort(a) | ((uint32_t)__half_as_ushort(b) << 16);
}
__device__ __forceinline__ void cvt4(float4 v, uint2& hi, uint2& lo) {
    __half h0 = __float2half_rn(v.x), h1 = __float2half_rn(v.y);
    __half h2 = __float2half_rn(v.z), h3 = __float2half_rn(v.w);
    __half l0 = __float2half_rn(v.x - __half2float(h0));
    __half l1 = __float2half_rn(v.y - __half2float(h1));
    __half l2 = __float2half_rn(v.z - __half2float(h2));
    __half l3 = __float2half_rn(v.w - __half2float(h3));
    hi.x = pack2h(h0, h1); hi.y = pack2h(h2, h3);
    lo.x = pack2h(l0, l1); lo.y = pack2h(l2, l3);
}
__device__ __forceinline__ void cvt2(float a, float b, uint32_t& hi, uint32_t& lo) {
    __half h0 = __float2half_rn(a), h1 = __float2half_rn(b);
    __half l0 = __float2half_rn(a - __half2float(h0));
    __half l1 = __float2half_rn(b - __half2float(h1));
    hi = pack2h(h0, h1); lo = pack2h(l0, l1);
}

// ================= packed f32x2 FMA (Blackwell) =================
#define FMA_F32X2(d, a, b) \
    asm("fma.rn.f32x2 %0, %1, %2, %0;" : "+l"(d) : "l"(a), "l"(b))
#define PACKF2(out, a, b) \
    asm("mov.b64 %0, {%1, %2};" : "=l"(out) : "f"(a), "f"(b))
#define UNPACKF2(a, b, in) \
    asm("mov.b64 {%0, %1}, %2;" : "=f"(a), "=f"(b) : "l"(in))

// ================= mma / cp.async / ldmatrix primitives =================
__device__ __forceinline__ uint32_t smem_u32(const void* p) {
    uint32_t a;
    asm("{ .reg .u64 t; cvta.to.shared.u64 t, %1; cvt.u32.u64 %0, t; }" : "=r"(a) : "l"(p));
    return a;
}
__device__ __forceinline__ void cp16(uint32_t s, const void* g) {
    asm volatile("cp.async.cg.shared.global [%0], [%1], 16;" :: "r"(s), "l"(g));
}
#define CP_COMMIT() asm volatile("cp.async.commit_group;")
#define CP_WAIT1() asm volatile("cp.async.wait_group 1;")

__device__ __forceinline__ void mma16816(float* d, const uint32_t* a, uint32_t b0, uint32_t b1) {
    asm volatile(
        "mma.sync.aligned.m16n8k16.row.col.f32.f16.f16.f32 "
        "{%0,%1,%2,%3}, {%4,%5,%6,%7}, {%8,%9}, {%0,%1,%2,%3};"
        : "+f"(d[0]), "+f"(d[1]), "+f"(d[2]), "+f"(d[3])
        : "r"(a[0]), "r"(a[1]), "r"(a[2]), "r"(a[3]), "r"(b0), "r"(b1));
}
__device__ __forceinline__ void ldsm_x4(uint32_t& r0, uint32_t& r1, uint32_t& r2, uint32_t& r3,
                                        uint32_t addr) {
    asm volatile("ldmatrix.sync.aligned.m8n8.x4.shared.b16 {%0,%1,%2,%3}, [%4];"
                 : "=r"(r0), "=r"(r1), "=r"(r2), "=r"(r3) : "r"(addr));
}

// ================= conversion kernels =================
__global__ void cvt_hilo(const float* __restrict__ src, uint2* __restrict__ hi,
                         uint2* __restrict__ lo, int n4) {
    int i = blockIdx.x * 256 + threadIdx.x;
    if (i < n4) {
        float4 v = ((const float4*)src)[i];
        uint2 h, l; cvt4(v, h, l);
        hi[i] = h; lo[i] = l;
    }
}
__global__ void cvt_mem_pad(const float* __restrict__ mem) {
    int i = blockIdx.x * 256 + threadIdx.x;
    if (i >= 128 * FLAT / 4) return;
    int row = i >> 10;
    uint2 h = make_uint2(0u, 0u), l = make_uint2(0u, 0u);
    if (row < CAP) {
        float4 v = ((const float4*)mem)[i];
        cvt4(v, h, l);
    }
    ((uint2*)g_memh)[i] = h; ((uint2*)g_meml)[i] = l;
}

// ================= prep kernels =================
__global__ void prep_adj(const float* __restrict__ edge_w, const float* __restrict__ mask) {
    __shared__ float t[64 * 64];
    int r = threadIdx.x;
    float sum = 0.f;
    for (int c = 0; c < 64; c++) {
        float v = sigmoidf_(edge_w[r * 64 + c] * 1.5f) * mask[r * 64 + c];
        t[r * 64 + c] = v; sum += v;
    }
    float inv = 1.f / fmaxf(sum, 1e-6f);
    for (int c = 0; c < 64; c++) g_adj[r * 64 + c] = t[r * 64 + c] * inv;
}

__global__ void __launch_bounds__(256) fold_w2(const float* __restrict__ W2) {
    int kt = blockIdx.x;
    int d  = blockIdx.y;
    __shared__ float tile[64][128];
    __shared__ float adjT[64 * 64];
    int tid = threadIdx.x;
    for (int i = tid; i < 4096; i += 256) {
        int m = i >> 6, n = i & 63;
        adjT[i] = g_adj[n * 64 + m];
    }
    for (int i = tid; i < 64 * 32; i += 256) {
        int m = i >> 5, c4 = (i & 31) << 2;
        *(float4*)&tile[m][c4] = *(const float4*)(W2 + (size_t)(m * 64 + d) * Hdim + kt * 128 + c4);
    }
    __syncthreads();
    int n = tid & 63;
    int kq = tid >> 6;
    float4 acc[8];
#pragma unroll
    for (int q = 0; q < 8; q++) acc[q] = make_float4(0.f, 0.f, 0.f, 0.f);
    for (int m = 0; m < 64; m++) {
        float s = adjT[m * 64 + n];
        const float4* trow = (const float4*)&tile[m][kq * 32];
#pragma unroll
        for (int q = 0; q < 8; q++) {
            float4 t4 = trow[q];
            acc[q].x += s * t4.x; acc[q].y += s * t4.y;
            acc[q].z += s * t4.z; acc[q].w += s * t4.w;
        }
    }
    size_t off4 = ((size_t)(n * 64 + d) * Hdim + kt * 128 + kq * 32) >> 2;
#pragma unroll
    for (int q = 0; q < 8; q++) {
        uint2 h, l; cvt4(acc[q], h, l);
        ((uint2*)g_W2h)[off4 + q] = h;
        ((uint2*)g_W2l)[off4 + q] = l;
    }
}
__global__ void prep_b2a(const float* __restrict__ b2) {
    int nd = blockIdx.x * 64 + threadIdx.x;
    int n = nd >> 6, d = nd & 63;
    float acc = 0.f;
    for (int m = 0; m < 64; m++) acc += g_adj[n * 64 + m] * b2[m * 64 + d];
    g_b2a[nd] = acc;
}

// 256 threads: t<64 computes sigma/cf; all threads stream the weight combine
__global__ void __launch_bounds__(256) prep_node(const float* __restrict__ Wslow,
                                                 const float* __restrict__ u,
                                                 const float* __restrict__ Wfast,
                                                 const float* __restrict__ Wf,
                                                 const float* __restrict__ bf,
                                                 const float* __restrict__ hprev) {
    int n = blockIdx.x;
    int t = threadIdx.x;
    __shared__ float us[64], v[64], red[64];
    const float* Ws = Wslow + (size_t)n * 4096;
    if (t < 64) us[t] = u[n * 64 + t];
    __syncthreads();
    if (t < 64) {
        float acc = 0.f;
        for (int o = 0; o < 64; o++) acc += Ws[o * 64 + t] * us[o];
        v[t] = acc;
    }
    __syncthreads();
    if (t < 64) {
        float wv = 0.f;
        for (int i = 0; i < 64; i++) wv += Ws[t * 64 + i] * v[i];
        red[t] = us[t] * wv;
    }
    __syncthreads();
    for (int off = 32; off > 0; off >>= 1) {
        if (t < off) red[t] += red[t + off];
        __syncthreads();
    }
    float inv = 1.f / (red[0] + 1e-8f);
    const float* Wfa = Wfast + (size_t)n * 4096;
    float* out = g_WcT + (size_t)n * 4096;
    for (int idx = t; idx < 4096; idx += 256) {
        int i = idx >> 6, o = idx & 63;
        out[idx] = Ws[o * 64 + i] * inv + Wfa[o * 64 + i];
    }
    if (t < 64) {
        float c = bf[n * 64 + t];
        const float* Wf2 = Wf + (size_t)n * 8192 + 4096;
        for (int i = 0; i < 64; i++) c += hprev[n * 64 + i] * Wf2[i * 64 + t];
        g_cf[n * 64 + t] = c;
    }
}

__global__ void prep_whm_bf(const float* __restrict__ Wh) {
    int i = blockIdx.x * 256 + threadIdx.x;
    if (i >= (1024 * FLAT) / 4) return;
    int row = i >> 10;
    uint2 h, l;
    if (row < Ccls) {
        const size_t CF4 = (size_t)Ccls * FLAT / 4;
        const float4* W4 = (const float4*)Wh;
        float4 a = W4[i], b = W4[i + CF4], c = W4[i + 2 * CF4];
        float4 m = make_float4((a.x + b.x + c.x) * (1.f / 3.f), (a.y + b.y + c.y) * (1.f / 3.f),
                               (a.z + b.z + c.z) * (1.f / 3.f), (a.w + b.w + c.w) * (1.f / 3.f));
        cvt4(m, h, l);
    } else {
        h = make_uint2(0u, 0u); l = make_uint2(0u, 0u);
    }
    ((uint2*)g_Whmh)[i] = h; ((uint2*)g_Whml)[i] = l;
}
__global__ void prep_bhm(const float* __restrict__ bh) {
    int i = blockIdx.x * 256 + threadIdx.x;
    if (i < 1024) g_bhm[i] = (i < Ccls) ? (bh[i] + bh[i + Ccls] + bh[i + 2 * Ccls]) * (1.f / 3.f) : 0.f;
}
__global__ void zero_sim() {
    g_sim[blockIdx.x * 256 + threadIdx.x] = 0.f;
}

// ================= split-fp16 HMMA GEMM (persistent tile loop) =================
// PASSES: 3 = Ah*Bh + Ah*Bl + Al*Bh; 2 = Ah*Bh + Ah*Bl; 1 = Ah*Bh only.
// Tiles indexed t in [0, tilesTotal): bm = (t/tilesX)*128, bn = (t%tilesX)*128.
// Launch grid.x <= tilesTotal; each CTA strides. grid.z splits K (atomic mode).
#define TSTRIDE 40
#define ROWB (TSTRIDE * 2)
#define TILE_B (128 * ROWB)
#define STAGE_B (4 * TILE_B)
#define GSMEM_TOTAL (2 * STAGE_B)

template <int NI, int PASSES>
__global__ void __launch_bounds__(256, 2) gemm_mma(
    const __half* __restrict__ Ahi, const __half* __restrict__ Alo,
    const __half* __restrict__ Bhi, const __half* __restrict__ Blo,
    const float* __restrict__ bias, float* __restrict__ C,
    int K, int lda, int Nstore, int act, int atomicOut,
    int tilesX, int tilesTotal) {
    extern __shared__ char smem[];
    const int tid = threadIdx.x;
    const int wid = tid >> 5;
    const int lane = tid & 31;
    const int grp = lane >> 2;
    const int qp = lane & 3;
    const int wm = (wid >> 2) * 64;
    const int wn = (wid & 3) * (NI * 8);
    const int kbase = blockIdx.z * K;
    const uint32_t sb = smem_u32(smem);

    const int row = tid >> 2;
    const int c16 = tid & 3;

    const int aRowL = wm + (lane & 7) + ((lane >> 3) & 1) * 8;
    const int aKL = (lane >> 4) * 8;
    const int bRowL = wn + (lane & 7) + (lane >> 4) * 8;
    const int bKL = ((lane >> 3) & 1) * 8;

    const int nc = K >> 5;

    for (int t = blockIdx.x; t < tilesTotal; t += gridDim.x) {
        const int bm = (t / tilesX) * 128;
        const int bn = (t % tilesX) * 128;
        __syncthreads();   // all warps done reading smem from previous tile

        float acc[4][NI][4];
#pragma unroll
        for (int mi = 0; mi < 4; mi++)
#pragma unroll
            for (int ni = 0; ni < NI; ni++)
#pragma unroll
                for (int j = 0; j < 4; j++) acc[mi][ni][j] = 0.f;

        auto issue = [&](int c, int s) {
            const uint32_t ss = sb + s * STAGE_B;
            const int k0 = c << 5;
#pragma unroll
            for (int tt = 0; tt < 2; tt++) {
                const int r = row + tt * 64;
                const uint32_t so = (uint32_t)r * ROWB + c16 * 16;
                const size_t gAoff = ((size_t)(bm + r) * lda + kbase + k0) * 2 + c16 * 16;
                const size_t gBoff = ((size_t)(bn + r) * lda + kbase + k0) * 2 + c16 * 16;
                cp16(ss + 0 * TILE_B + so, (const char*)Ahi + gAoff);
                if (PASSES == 3) cp16(ss + 1 * TILE_B + so, (const char*)Alo + gAoff);
                cp16(ss + 2 * TILE_B + so, (const char*)Bhi + gBoff);
                if (PASSES >= 2) cp16(ss + 3 * TILE_B + so, (const char*)Blo + gBoff);
            }
        };

        issue(0, 0); CP_COMMIT();
        if (nc > 1) issue(1, 1);
        CP_COMMIT();

        for (int c = 0; c < nc; c++) {
            const int s = c & 1;
            CP_WAIT1();
            __syncthreads();
            const uint32_t st = sb + s * STAGE_B;
#pragma unroll
            for (int ks = 0; ks < 2; ks++) {
                const int k0 = ks * 16;
                uint32_t ah[4][4], al[4][4];
#pragma unroll
                for (int mi = 0; mi < 4; mi++) {
                    const uint32_t ad = st + (uint32_t)(aRowL + mi * 16) * ROWB + (k0 + aKL) * 2;
                    ldsm_x4(ah[mi][0], ah[mi][1], ah[mi][2], ah[mi][3], ad);
                    if (PASSES == 3) ldsm_x4(al[mi][0], al[mi][1], al[mi][2], al[mi][3], ad + TILE_B);
                }
                uint32_t bh[NI][2], bl[NI][2];
#pragma unroll
                for (int p = 0; p < NI / 2; p++) {
                    const uint32_t bd = st + 2 * TILE_B + (uint32_t)(bRowL + p * 16) * ROWB + (k0 + bKL) * 2;
                    uint32_t r0, r1, r2, r3;
                    ldsm_x4(r0, r1, r2, r3, bd);
                    bh[2 * p][0] = r0; bh[2 * p][1] = r1; bh[2 * p + 1][0] = r2; bh[2 * p + 1][1] = r3;
                    if (PASSES >= 2) {
                        ldsm_x4(r0, r1, r2, r3, bd + TILE_B);
                        bl[2 * p][0] = r0; bl[2 * p][1] = r1; bl[2 * p + 1][0] = r2; bl[2 * p + 1][1] = r3;
                    }
                }
#pragma unroll
                for (int ni = 0; ni < NI; ni++) {
#pragma unroll
                    for (int mi = 0; mi < 4; mi++) {
                        mma16816(acc[mi][ni], ah[mi], bh[ni][0], bh[ni][1]);
                        if (PASSES >= 2) mma16816(acc[mi][ni], ah[mi], bl[ni][0], bl[ni][1]);
                        if (PASSES == 3) mma16816(acc[mi][ni], al[mi], bh[ni][0], bh[ni][1]);
                    }
                }
            }
            __syncthreads();
            if (c + 2 < nc) issue(c + 2, s);
            CP_COMMIT();
        }

        // epilogue
#pragma unroll
        for (int mi = 0; mi < 4; mi++) {
#pragma unroll
            for (int ni = 0; ni < NI; ni++) {
                const int r0 = bm + wm + mi * 16 + grp;
                const int col = bn + wn + ni * 8 + qp * 2;
                float* a4 = acc[mi][ni];
                if (atomicOut) {
                    if (col < Nstore) {
                        atomicAdd(&C[(size_t)r0 * Nstore + col], a4[0]);
                        atomicAdd(&C[(size_t)(r0 + 8) * Nstore + col], a4[2]);
                        if (col + 1 < Nstore) {
                            atomicAdd(&C[(size_t)r0 * Nstore + col + 1], a4[1]);
                            atomicAdd(&C[(size_t)(r0 + 8) * Nstore + col + 1], a4[3]);
                        }
                    }
                } else if (col + 1 < Nstore) {
                    float2 v0, v1;
                    float bb0 = bias ? bias[col] : 0.f;
                    float bb1 = bias ? bias[col + 1] : 0.f;
                    v0.x = a4[0] + bb0; v0.y = a4[1] + bb1;
                    v1.x = a4[2] + bb0; v1.y = a4[3] + bb1;
                    if (act == 1) {
                        v0.x = fmaxf(v0.x, 0.f); v0.y = fmaxf(v0.y, 0.f);
                        v1.x = fmaxf(v1.x, 0.f); v1.y = fmaxf(v1.y, 0.f);
                    }
                    *(float2*)(C + (size_t)r0 * Nstore + col) = v0;
                    *(float2*)(C + (size_t)(r0 + 8) * Nstore + col) = v1;
                } else if (col < Nstore) {
                    float bb0 = bias ? bias[col] : 0.f;
                    float v0 = a4[0] + bb0, v1 = a4[2] + bb0;
                    if (act == 1) { v0 = fmaxf(v0, 0.f); v1 = fmaxf(v1, 0.f); }
                    C[(size_t)r0 * Nstore + col] = v0;
                    C[(size_t)(r0 + 8) * Nstore + col] = v1;
                }
            }
        }
    }
}

// ================= LayerNorm(H=1024) + GELU -> fp16 hi/lo =================
__global__ void __launch_bounds__(256) ln_gelu_kernel(const float* __restrict__ h,
                                                      const float* __restrict__ g,
                                                      const float* __restrict__ beta,
                                                      uint2* __restrict__ hi,
                                                      uint2* __restrict__ lo) {
    int row = blockIdx.x;
    const float* hr = h + (size_t)row * Hdim;
    int tid = threadIdx.x;
    float4 v = *(const float4*)(hr + tid * 4);
    float s = v.x + v.y + v.z + v.w;
    float ss = v.x * v.x + v.y * v.y + v.z * v.z + v.w * v.w;
    __shared__ float rs[8], rss[8];
    for (int o = 16; o > 0; o >>= 1) {
        s += __shfl_down_sync(0xffffffffu, s, o);
        ss += __shfl_down_sync(0xffffffffu, ss, o);
    }
    if ((tid & 31) == 0) { rs[tid >> 5] = s; rss[tid >> 5] = ss; }
    __syncthreads();
    if (tid < 32) {
        float a = tid < 8 ? rs[tid] : 0.f;
        float b = tid < 8 ? rss[tid] : 0.f;
        for (int o = 4; o > 0; o >>= 1) {
            a += __shfl_down_sync(0xffffffffu, a, o);
            b += __shfl_down_sync(0xffffffffu, b, o);
        }
        if (tid == 0) { rs[0] = a; rss[0] = b; }
    }
    __syncthreads();
    float mu = rs[0] * (1.f / Hdim);
    float var = rss[0] * (1.f / Hdim) - mu * mu;
    float inv = rsqrtf(var + 1e-5f);
    float4 gg = *(const float4*)(g + tid * 4);
    float4 bb = *(const float4*)(beta + tid * 4);
    float y;
    y = (v.x - mu) * inv * gg.x + bb.x; v.x = 0.5f * y * (1.f + erff(y * 0.70710678118654752f));
    y = (v.y - mu) * inv * gg.y + bb.y; v.y = 0.5f * y * (1.f + erff(y * 0.70710678118654752f));
    y = (v.z - mu) * inv * gg.z + bb.z; v.z = 0.5f * y * (1.f + erff(y * 0.70710678118654752f));
    y = (v.w - mu) * inv * gg.w + bb.w; v.w = 0.5f * y * (1.f + erff(y * 0.70710678118654752f));
    uint2 hh, ll; cvt4(v, hh, ll);
    hi[(size_t)row * 256 + tid] = hh;
    lo[(size_t)row * 256 + tid] = ll;
}

// ================= fused cell kernel (packed f32x2 FMA; emits fp16 hi/lo of xflat) =================
#define CELL_SMEM ((64 * 68 * 2 + 4096 * 4 + 7 * 64) * sizeof(float))
__global__ void __launch_bounds__(256) cell_kernel(const float* __restrict__ Wi,
                                                   const float* __restrict__ Wf,
                                                   const float* __restrict__ Wo,
                                                   const float* __restrict__ bi_g,
                                                   const float* __restrict__ bslow_g,
                                                   const float* __restrict__ bo_g,
                                                   const float* __restrict__ hprev_g,
                                                   const float* __restrict__ gln_g,
                                                   const float* __restrict__ bln_g,
                                                   float* __restrict__ xflat_out,
                                                   uint32_t* __restrict__ xfh,
                                                   uint32_t* __restrict__ xfl) {
    extern __shared__ float sf[];
    float* xs = sf;
    float* wi = xs + 64 * 68;
    float* wf = wi + 4096;
    float* wc = wf + 4096;
    float* wo = wc + 4096;
    float* hr = wo + 4096;
    float* vecs = hr + 64 * 68;

    int n = blockIdx.x;
    int b0 = blockIdx.y * 64;
    int tid = threadIdx.x;

#pragma unroll
    for (int j = 0; j < 4; j++) {
        int idx = tid + j * 256;
        int row = idx >> 4, c4 = (idx & 15) << 2;
        *(float4*)(xs + row * 68 + c4) =
            *(const float4*)(g_xagg + (((size_t)(b0 + row) * 64 + n) << 6) + c4);
        ((float4*)wi)[idx] = ((const float4*)(Wi + (size_t)n * 4096))[idx];
        ((float4*)wf)[idx] = ((const float4*)(Wf + (size_t)n * 8192))[idx];
        ((float4*)wc)[idx] = ((const float4*)(g_WcT + (size_t)n * 4096))[idx];
        ((float4*)wo)[idx] = ((const float4*)(Wo + (size_t)n * 4096))[idx];
    }
    if (tid < 64) {
        vecs[0 * 64 + tid] = bi_g[n * 64 + tid];
        vecs[1 * 64 + tid] = g_cf[n * 64 + tid];
        vecs[2 * 64 + tid] = bslow_g[n * 64 + tid];
        vecs[3 * 64 + tid] = bo_g[n * 64 + tid];
        vecs[4 * 64 + tid] = hprev_g[n * 64 + tid];
        vecs[5 * 64 + tid] = gln_g[n * 64 + tid];
        vecs[6 * 64 + tid] = bln_g[n * 64 + tid];
    }
    __syncthreads();

    const int r0 = (tid >> 4) * 4;
    const int c0 = (tid & 15) * 4;

    unsigned long long ai2[4][2], af2[4][2], ac2[4][2];
#pragma unroll
    for (int r = 0; r < 4; r++)
#pragma unroll
        for (int p = 0; p < 2; p++) { ai2[r][p] = 0ull; af2[r][p] = 0ull; ac2[r][p] = 0ull; }

    for (int i = 0; i < 64; i++) {
        unsigned long long xp[4];
#pragma unroll
        for (int r = 0; r < 4; r++) {
            float xv = xs[(r0 + r) * 68 + i];
            PACKF2(xp[r], xv, xv);
        }
        float4 w1 = *(const float4*)(wi + i * 64 + c0);
        float4 w2 = *(const float4*)(wf + i * 64 + c0);
        float4 w3 = *(const float4*)(wc + i * 64 + c0);
        unsigned long long w1p[2], w2p[2], w3p[2];
        PACKF2(w1p[0], w1.x, w1.y); PACKF2(w1p[1], w1.z, w1.w);
        PACKF2(w2p[0], w2.x, w2.y); PACKF2(w2p[1], w2.z, w2.w);
        PACKF2(w3p[0], w3.x, w3.y); PACKF2(w3p[1], w3.z, w3.w);
#pragma unroll
        for (int r = 0; r < 4; r++) {
            FMA_F32X2(ai2[r][0], xp[r], w1p[0]); FMA_F32X2(ai2[r][1], xp[r], w1p[1]);
            FMA_F32X2(af2[r][0], xp[r], w2p[0]); FMA_F32X2(af2[r][1], xp[r], w2p[1]);
            FMA_F32X2(ac2[r][0], xp[r], w3p[0]); FMA_F32X2(ac2[r][1], xp[r], w3p[1]);
        }
    }
#pragma unroll
    for (int r = 0; r < 4; r++)
#pragma unroll
        for (int p = 0; p < 2; p++) {
            float aiv0, aiv1, afv0, afv1, acv0, acv1;
            UNPACKF2(aiv0, aiv1, ai2[r][p]);
            UNPACKF2(afv0, afv1, af2[r][p]);
            UNPACKF2(acv0, acv1, ac2[r][p]);
            int o = c0 + 2 * p;
            float it0 = sigmoidf_(aiv0 + vecs[0 * 64 + o]);
            float ft0 = sigmoidf_(afv0 + vecs[1 * 64 + o]);
            float hs0 = acv0 + vecs[2 * 64 + o];
            hr[(r0 + r) * 68 + o] = it0 * hs0 + ft0 * vecs[4 * 64 + o];
            float it1 = sigmoidf_(aiv1 + vecs[0 * 64 + o + 1]);
            float ft1 = sigmoidf_(afv1 + vecs[1 * 64 + o + 1]);
            float hs1 = acv1 + vecs[2 * 64 + o + 1];
            hr[(r0 + r) * 68 + o + 1] = it1 * hs1 + ft1 * vecs[4 * 64 + o + 1];
        }
    __syncthreads();

    unsigned long long ao2[4][2];
#pragma unroll
    for (int r = 0; r < 4; r++)
#pragma unroll
        for (int p = 0; p < 2; p++) ao2[r][p] = 0ull;
    for (int i = 0; i < 64; i++) {
        unsigned long long xp[4];
#pragma unroll
        for (int r = 0; r < 4; r++) {
            float xv = hr[(r0 + r) * 68 + i];
            PACKF2(xp[r], xv, xv);
        }
        float4 w = *(const float4*)(wo + i * 64 + c0);
        unsigned long long wp[2];
        PACKF2(wp[0], w.x, w.y); PACKF2(wp[1], w.z, w.w);
#pragma unroll
        for (int r = 0; r < 4; r++) {
            FMA_F32X2(ao2[r][0], xp[r], wp[0]);
            FMA_F32X2(ao2[r][1], xp[r], wp[1]);
        }
    }
    float* ys = xs;
#pragma unroll
    for (int r = 0; r < 4; r++)
#pragma unroll
        for (int p = 0; p < 2; p++) {
            float a0, a1;
            UNPACKF2(a0, a1, ao2[r][p]);
            int o = c0 + 2 * p;
            float ot0 = sigmoidf_(a0 + vecs[3 * 64 + o]);
            float ot1 = sigmoidf_(a1 + vecs[3 * 64 + o + 1]);
            ys[(r0 + r) * 68 + o] = ot0 * tanhf(hr[(r0 + r) * 68 + o]);
            ys[(r0 + r) * 68 + o + 1] = ot1 * tanhf(hr[(r0 + r) * 68 + o + 1]);
        }
    __syncthreads();

    int w = tid >> 5, lane = tid & 31;
    for (int rr = 0; rr < 8; rr++) {
        int row = w * 8 + rr;
        float v0 = ys[row * 68 + 2 * lane];
        float v1 = ys[row * 68 + 2 * lane + 1];
        float s = v0 + v1;
        float ss = v0 * v0 + v1 * v1;
        for (int o = 16; o > 0; o >>= 1) {
            s += __shfl_xor_sync(0xffffffffu, s, o);
            ss += __shfl_xor_sync(0xffffffffu, ss, o);
        }
        float mu = s * (1.f / 64.f);
        float var = ss * (1.f / 64.f) - mu * mu;
        float inv = rsqrtf(var + 1e-5f);
        float y0 = (v0 - mu) * inv * vecs[5 * 64 + 2 * lane] + vecs[6 * 64 + 2 * lane];
        float y1 = (v1 - mu) * inv * vecs[5 * 64 + 2 * lane + 1] + vecs[6 * 64 + 2 * lane + 1];
        size_t base = (size_t)(b0 + row) * 4096 + n * 64;
        *(float2*)(xflat_out + base + 2 * lane) = make_float2(y0, y1);
        uint32_t hh, ll; cvt2(y0, y1, hh, ll);
        xfh[(base >> 1) + lane] = hh;
        xfl[(base >> 1) + lane] = ll;
    }
}

// ================= top-5 retrieval + update + fp16 re-emit =================
__global__ void __launch_bounds__(256) retrieve_kernel(const float* __restrict__ mem,
                                                       float* __restrict__ xflat,
                                                       uint2* __restrict__ xfh,
                                                       uint2* __restrict__ xfl) {
    int b = blockIdx.x;
    __shared__ float s[64];
    __shared__ int top[5];
    int tid = threadIdx.x;
    if (tid < 64) s[tid] = g_sim[b * 64 + tid];
    __syncthreads();
    if (tid < 32) {
        for (int k = 0; k < 5; k++) {
            float v = s[tid]; int idx = tid;
            float v2 = s[tid + 32];
            if (v2 > v) { v = v2; idx = tid + 32; }
            for (int o = 16; o > 0; o >>= 1) {
                float ov = __shfl_down_sync(0xffffffffu, v, o);
                int oi = __shfl_down_sync(0xffffffffu, idx, o);
                if (ov > v || (ov == v && oi < idx)) { v = ov; idx = oi; }
            }
            idx = __shfl_sync(0xffffffffu, idx, 0);
            if (tid == 0) top[k] = idx;
            if (tid == 0) s[idx] = -INFINITY;
            __syncwarp();
        }
    }
    __syncthreads();
    const float4* m4 = (const float4*)mem;
    float4* x4 = (float4*)(xflat + (size_t)b * 4096);
    int t0 = top[0] * 1024, t1 = top[1] * 1024, t2 = top[2] * 1024, t3 = top[3] * 1024, t4 = top[4] * 1024;
#pragma unroll
    for (int j = 0; j < 4; j++) {
        int idx = tid + j * 256;
        float4 xv = x4[idx];
        float4 a = m4[t0 + idx], bb = m4[t1 + idx], c = m4[t2 + idx], d = m4[t3 + idx], e = m4[t4 + idx];
        xv.x += 0.02f * (a.x + bb.x + c.x + d.x + e.x);
        xv.y += 0.02f * (a.y + bb.y + c.y + d.y + e.y);
        xv.z += 0.02f * (a.z + bb.z + c.z + d.z + e.z);
        xv.w += 0.02f * (a.w + bb.w + c.w + d.w + e.w);
        x4[idx] = xv;
        uint2 h, l; cvt4(xv, h, l);
        xfh[(size_t)b * 1024 + idx] = h;
        xfl[(size_t)b * 1024 + idx] = l;
    }
}

// ================= proj2 =================
__global__ void __launch_bounds__(256) proj2_kernel(const float* __restrict__ s1,
                                                    const float* __restrict__ Ws2,
                                                    const float* __restrict__ bs2,
                                                    float* __restrict__ proj) {
    __shared__ float w2s[8 * 1024];
    __shared__ float bss[8];
    int tid = threadIdx.x;
    for (int i = tid; i < 8192; i += 256) w2s[i] = Ws2[i];
    if (tid < 8) bss[tid] = bs2[tid];
    __syncthreads();
    int w = tid >> 5, lane = tid & 31;
    int b = blockIdx.x * 8 + w;
    const float4* row = (const float4*)(s1 + (size_t)b * 1024);
    float4 xv[8];
#pragma unroll
    for (int j = 0; j < 8; j++) xv[j] = row[lane + j * 32];
#pragma unroll
    for (int p = 0; p < 8; p++) {
        const float4* wr = (const float4*)(w2s + p * 1024);
        float acc = 0.f;
#pragma unroll
        for (int j = 0; j < 8; j++) {
            float4 wv = wr[lane + j * 32];
            acc += xv[j].x * wv.x + xv[j].y * wv.y + xv[j].z * wv.z + xv[j].w * wv.w;
        }
        for (int o = 16; o > 0; o >>= 1) acc += __shfl_xor_sync(0xffffffffu, acc, o);
        if (lane == 0) proj[(size_t)b * 8 + p] = acc + bss[p];
    }
}

// ================= launch =================
extern "C" void kernel_launch(void* const* d_in, const int* in_sizes, int n_in,
                              void* d_out, int out_size) {
    const float* x      = (const float*)d_in[0];
    const float* W1     = (const float*)d_in[1];
    const float* b1     = (const float*)d_in[2];
    const float* g1     = (const float*)d_in[3];
    const float* beta1  = (const float*)d_in[4];
    const float* W2     = (const float*)d_in[5];
    const float* b2     = (const float*)d_in[6];
    const float* edge_w = (const float*)d_in[7];
    const float* mask   = (const float*)d_in[8];
    const float* Wi     = (const float*)d_in[9];
    const float* bi     = (const float*)d_in[10];
    const float* Wf     = (const float*)d_in[11];
    const float* bf     = (const float*)d_in[12];
    const float* Wslow  = (const float*)d_in[13];
    const float* bslow  = (const float*)d_in[14];
    const float* u      = (const float*)d_in[15];
    const float* Wfast  = (const float*)d_in[16];
    const float* Wo     = (const float*)d_in[17];
    const float* bo     = (const float*)d_in[18];
    const float* gln    = (const float*)d_in[19];
    const float* bln    = (const float*)d_in[20];
    const float* h_prev = (const float*)d_in[21];
    const float* memory = (const float*)d_in[22];
    const float* Wh     = (const float*)d_in[23];
    const float* bh     = (const float*)d_in[24];
    const float* Ws1    = (const float*)d_in[25];
    const float* bs1    = (const float*)d_in[26];
    const float* Ws2    = (const float*)d_in[27];
    const float* bs2    = (const float*)d_in[28];

    float* out    = (float*)d_out;
    float* logits = out;
    float* proj   = out + (size_t)Bn * Ccls;
    float* xflat  = proj + (size_t)Bn * Pp;

    float *p_h1, *p_b2a, *p_xagg, *p_sim, *p_s1, *p_bhm;
    cudaGetSymbolAddress((void**)&p_h1, g_h1);
    cudaGetSymbolAddress((void**)&p_b2a, g_b2a);
    cudaGetSymbolAddress((void**)&p_xagg, g_xagg);
    cudaGetSymbolAddress((void**)&p_sim, g_sim);
    cudaGetSymbolAddress((void**)&p_s1, g_s1);
    cudaGetSymbolAddress((void**)&p_bhm, g_bhm);
    void *p_xh, *p_xl, *p_W1h, *p_W1l, *p_h1h, *p_h1l, *p_W2h, *p_W2l;
    void *p_xfh, *p_xfl, *p_Whmh, *p_Whml, *p_Ws1h, *p_Ws1l, *p_memh, *p_meml;
    cudaGetSymbolAddress(&p_xh, g_xh);   cudaGetSymbolAddress(&p_xl, g_xl);
    cudaGetSymbolAddress(&p_W1h, g_W1h); cudaGetSymbolAddress(&p_W1l, g_W1l);
    cudaGetSymbolAddress(&p_h1h, g_h1h); cudaGetSymbolAddress(&p_h1l, g_h1l);
    cudaGetSymbolAddress(&p_W2h, g_W2h); cudaGetSymbolAddress(&p_W2l, g_W2l);
    cudaGetSymbolAddress(&p_xfh, g_xfh); cudaGetSymbolAddress(&p_xfl, g_xfl);
    cudaGetSymbolAddress(&p_Whmh, g_Whmh); cudaGetSymbolAddress(&p_Whml, g_Whml);
    cudaGetSymbolAddress(&p_Ws1h, g_Ws1h); cudaGetSymbolAddress(&p_Ws1l, g_Ws1l);
    cudaGetSymbolAddress(&p_memh, g_memh); cudaGetSymbolAddress(&p_meml, g_meml);

    int nsm = 148;
    cudaDeviceGetAttribute(&nsm, cudaDevAttrMultiProcessorCount, 0);
    int persist = 2 * nsm;
    if (persist > 1024) persist = 1024;

    cudaFuncSetAttribute(cell_kernel, cudaFuncAttributeMaxDynamicSharedMemorySize, CELL_SMEM);
    cudaFuncSetAttribute(gemm_mma<4, 3>, cudaFuncAttributeMaxDynamicSharedMemorySize, GSMEM_TOTAL);
    cudaFuncSetAttribute(gemm_mma<4, 2>, cudaFuncAttributeMaxDynamicSharedMemorySize, GSMEM_TOTAL);
    cudaFuncSetAttribute(gemm_mma<4, 1>, cudaFuncAttributeMaxDynamicSharedMemorySize, GSMEM_TOTAL);
    cudaFuncSetAttribute(gemm_mma<2, 3>, cudaFuncAttributeMaxDynamicSharedMemorySize, GSMEM_TOTAL);

    // prep + conversions
    prep_adj<<<1, 64>>>(edge_w, mask);
    fold_w2<<<dim3(8, 64), 256>>>(W2);
    prep_b2a<<<64, 64>>>(b2);
    prep_node<<<64, 256>>>(Wslow, u, Wfast, Wf, bf, h_prev);
    prep_whm_bf<<<(1024 * FLAT / 4 + 255) / 256, 256>>>(Wh);
    prep_bhm<<<4, 256>>>(bh);
    cvt_hilo<<<(Bn * Fdim / 4 + 255) / 256, 256>>>(x, (uint2*)p_xh, (uint2*)p_xl, Bn * Fdim / 4);
    cvt_hilo<<<(Hdim * Fdim / 4 + 255) / 256, 256>>>(W1, (uint2*)p_W1h, (uint2*)p_W1l, Hdim * Fdim / 4);
    cvt_hilo<<<(Hdim * FLAT / 4 + 255) / 256, 256>>>(Ws1, (uint2*)p_Ws1h, (uint2*)p_Ws1l, Hdim * FLAT / 4);
    cvt_mem_pad<<<(128 * FLAT / 4 + 255) / 256, 256>>>(memory);

    // stage 1: input projection (3-pass); G2 -> x_agg (2-pass, persistent tiles)
    gemm_mma<4, 3><<<256, 256, GSMEM_TOTAL>>>(
        (const __half*)p_xh, (const __half*)p_xl,
        (const __half*)p_W1h, (const __half*)p_W1l, b1, p_h1,
        Fdim, Fdim, Hdim, 0, 0, Hdim / 128, (Hdim / 128) * (Bn / 128));
    ln_gelu_kernel<<<Bn, 256>>>(p_h1, g1, beta1, (uint2*)p_h1h, (uint2*)p_h1l);
    gemm_mma<4, 2><<<persist, 256, GSMEM_TOTAL>>>(
        (const __half*)p_h1h, nullptr,
        (const __half*)p_W2h, (const __half*)p_W2l, p_b2a, p_xagg,
        Hdim, Hdim, FLAT, 0, 0, FLAT / 128, (FLAT / 128) * (Bn / 128));

    // stage 2: cells
    cell_kernel<<<dim3(Nn, Bn / 64), 256, CELL_SMEM>>>(Wi, Wf, Wo, bi, bslow, bo,
                                                       h_prev, gln, bln, xflat,
                                                       (uint32_t*)p_xfh, (uint32_t*)p_xfl);

    // stage 3: retrieval (split-K sim GEMM, atomic accumulate; 3-pass keeps top-k tight)
    zero_sim<<<Bn * CAP / 256, 256>>>();
    gemm_mma<2, 3><<<dim3(Bn / 128, 1, 4), 256, GSMEM_TOTAL>>>(
        (const __half*)p_xfh, (const __half*)p_xfl,
        (const __half*)p_memh, (const __half*)p_meml, nullptr, p_sim,
        FLAT / 4, FLAT, CAP, 0, 1, 1, Bn / 128);
    retrieve_kernel<<<Bn, 256>>>(memory, xflat, (uint2*)p_xfh, (uint2*)p_xfl);

    // stage 4: heads (1-pass fp16)
    gemm_mma<4, 1><<<256, 256, GSMEM_TOTAL>>>(
        (const __half*)p_xfh, nullptr,
        (const __half*)p_Whmh, nullptr, p_bhm, logits,
        FLAT, FLAT, Ccls, 0, 0, 1024 / 128, (1024 / 128) * (Bn / 128));
    gemm_mma<4, 1><<<256, 256, GSMEM_TOTAL>>>(
        (const __half*)p_xfh, nullptr,
        (const __half*)p_Ws1h, nullptr, bs1, p_s1,
        FLAT, FLAT, Hdim, 1, 0, Hdim / 128, (Hdim / 128) * (Bn / 128));
    proj2_kernel<<<Bn / 8, 256>>>(p_s1, Ws2, bs2, proj);
}

// round 15
// speedup vs baseline: 1.5013x; 1.0095x over previous
#include <cuda_runtime.h>
#include <cuda_fp16.h>
#include <math.h>
#include <stdint.h>

#define Bn 4096
#define Fdim 512
#define Hdim 1024
#define Nn 64
#define Dd 64
#define FLAT 4096
#define Ccls 1000
#define CAP 64
#define Pp 8

// ================= scratch (device globals) =================
__device__ float g_h1[Bn * Hdim];
__device__ float g_b2a[FLAT];
__device__ float g_xagg[(size_t)Bn * FLAT];
__device__ float g_sim[Bn * CAP];
__device__ float g_s1[Bn * Hdim];
__device__ float g_bhm[1024];
__device__ float g_WcT[Nn * Dd * Dd];
__device__ float g_cf[Nn * Dd];
// fp16 hi/lo operand buffers
__device__ __half g_xh[Bn * Fdim],    g_xl[Bn * Fdim];
__device__ __half g_W1h[Hdim * Fdim], g_W1l[Hdim * Fdim];
__device__ __half g_h1h[Bn * Hdim],   g_h1l[Bn * Hdim];
__device__ __half g_W2h[FLAT * Hdim], g_W2l[FLAT * Hdim];
__device__ __half g_xfh[(size_t)Bn * FLAT], g_xfl[(size_t)Bn * FLAT];
__device__ __half g_Whmh[1024 * FLAT], g_Whml[1024 * FLAT];
__device__ __half g_Ws1h[Hdim * FLAT], g_Ws1l[Hdim * FLAT];
__device__ __half g_memh[128 * FLAT], g_meml[128 * FLAT];

__device__ __forceinline__ float sigmoidf_(float x) { return 1.f / (1.f + expf(-x)); }

__device__ __forceinline__ uint32_t pack2h(__half a, __half b) {
    return (uint32_t)__half_as_ushort(a) | ((uint32_t)__half_as_ushort(b) << 16);
}
__device__ __forceinline__ void cvt4(float4 v, uint2& hi, uint2& lo) {
    __half h0 = __float2half_rn(v.x), h1 = __float2half_rn(v.y);
    __half h2 = __float2half_rn(v.z), h3 = __float2half_rn(v.w);
    __half l0 = __float2half_rn(v.x - __half2float(h0));
    __half l1 = __float2half_rn(v.y - __half2float(h1));
    __half l2 = __float2half_rn(v.z - __half2float(h2));
    __half l3 = __float2half_rn(v.w - __half2float(h3));
    hi.x = pack2h(h0, h1); hi.y = pack2h(h2, h3);
    lo.x = pack2h(l0, l1); lo.y = pack2h(l2, l3);
}
__device__ __forceinline__ void cvt2(float a, float b, uint32_t& hi, uint32_t& lo) {
    __half h0 = __float2half_rn(a), h1 = __float2half_rn(b);
    __half l0 = __float2half_rn(a - __half2float(h0));
    __half l1 = __float2half_rn(b - __half2float(h1));
    hi = pack2h(h0, h1); lo = pack2h(l0, l1);
}

// ================= packed f32x2 FMA (Blackwell) =================
#define FMA_F32X2(d, a, b) \
    asm("fma.rn.f32x2 %0, %1, %2, %0;" : "+l"(d) : "l"(a), "l"(b))
#define PACKF2(out, a, b) \
    asm("mov.b64 %0, {%1, %2};" : "=l"(out) : "f"(a), "f"(b))
#define UNPACKF2(a, b, in) \
    asm("mov.b64 {%0, %1}, %2;" : "=f"(a), "=f"(b) : "l"(in))

// ================= mma / cp.async / ldmatrix primitives =================
__device__ __forceinline__ uint32_t smem_u32(const void* p) {
    uint32_t a;
    asm("{ .reg .u64 t; cvta.to.shared.u64 t, %1; cvt.u32.u64 %0, t; }" : "=r"(a) : "l"(p));
    return a;
}
__device__ __forceinline__ void cp16(uint32_t s, const void* g) {
    asm volatile("cp.async.cg.shared.global [%0], [%1], 16;" :: "r"(s), "l"(g));
}
#define CP_COMMIT() asm volatile("cp.async.commit_group;")
#define CP_WAIT1() asm volatile("cp.async.wait_group 1;")

__device__ __forceinline__ void mma16816(float* d, const uint32_t* a, uint32_t b0, uint32_t b1) {
    asm volatile(
        "mma.sync.aligned.m16n8k16.row.col.f32.f16.f16.f32 "
        "{%0,%1,%2,%3}, {%4,%5,%6,%7}, {%8,%9}, {%0,%1,%2,%3};"
        : "+f"(d[0]), "+f"(d[1]), "+f"(d[2]), "+f"(d[3])
        : "r"(a[0]), "r"(a[1]), "r"(a[2]), "r"(a[3]), "r"(b0), "r"(b1));
}
__device__ __forceinline__ void ldsm_x4(uint32_t& r0, uint32_t& r1, uint32_t& r2, uint32_t& r3,
                                        uint32_t addr) {
    asm volatile("ldmatrix.sync.aligned.m8n8.x4.shared.b16 {%0,%1,%2,%3}, [%4];"
                 : "=r"(r0), "=r"(r1), "=r"(r2), "=r"(r3) : "r"(addr));
}

// ================= fused prep mega-kernel =================
// block ranges (256 threads each):
//  [0, 2048)            cvt_hilo x        (Bn*Fdim/4   = 524288 f4)
//  [2048, 2560)         cvt_hilo W1       (Hdim*Fdim/4 = 131072 f4)
//  [2560, 6656)         cvt_hilo Ws1      (Hdim*FLAT/4 = 1048576 f4)
//  [6656, 7168)         cvt_mem_pad       (128*FLAT/4  = 131072 f4)
//  [7168, 11264)        prep_whm          (1024*FLAT/4 = 1048576 f4)
//  [11264, 11268)       prep_bhm
//  [11268, 12292)       zero_sim
//  [12292, 12356)       prep_b2a (in-branch adj row, bit-exact)
//  [12356, 12420)       prep_node
#define MISC_BLOCKS 12420

__global__ void __launch_bounds__(256) misc_prep(
    const float* __restrict__ x, const float* __restrict__ W1,
    const float* __restrict__ Ws1, const float* __restrict__ mem,
    const float* __restrict__ Wh, const float* __restrict__ bh,
    const float* __restrict__ b2,
    const float* __restrict__ edge_w, const float* __restrict__ mask,
    const float* __restrict__ Wslow, const float* __restrict__ u,
    const float* __restrict__ Wfast, const float* __restrict__ Wf,
    const float* __restrict__ bf, const float* __restrict__ hprev) {
    const int bid = blockIdx.x;
    const int tid = threadIdx.x;

    if (bid < 2048) {                                    // cvt x
        int i = bid * 256 + tid;
        float4 v = ((const float4*)x)[i];
        uint2 h, l; cvt4(v, h, l);
        ((uint2*)g_xh)[i] = h; ((uint2*)g_xl)[i] = l;
    } else if (bid < 2560) {                             // cvt W1
        int i = (bid - 2048) * 256 + tid;
        float4 v = ((const float4*)W1)[i];
        uint2 h, l; cvt4(v, h, l);
        ((uint2*)g_W1h)[i] = h; ((uint2*)g_W1l)[i] = l;
    } else if (bid < 6656) {                             // cvt Ws1
        int i = (bid - 2560) * 256 + tid;
        float4 v = ((const float4*)Ws1)[i];
        uint2 h, l; cvt4(v, h, l);
        ((uint2*)g_Ws1h)[i] = h; ((uint2*)g_Ws1l)[i] = l;
    } else if (bid < 7168) {                             // mem pad -> 128 rows
        int i = (bid - 6656) * 256 + tid;
        int row = i >> 10;
        uint2 h = make_uint2(0u, 0u), l = make_uint2(0u, 0u);
        if (row < CAP) {
            float4 v = ((const float4*)mem)[i];
            cvt4(v, h, l);
        }
        ((uint2*)g_memh)[i] = h; ((uint2*)g_meml)[i] = l;
    } else if (bid < 11264) {                            // whm mean -> fp16 hi/lo, padded
        int i = (bid - 7168) * 256 + tid;
        int row = i >> 10;
        uint2 h, l;
        if (row < Ccls) {
            const size_t CF4 = (size_t)Ccls * FLAT / 4;
            const float4* W4 = (const float4*)Wh;
            float4 a = W4[i], b = W4[i + CF4], c = W4[i + 2 * CF4];
            float4 m = make_float4((a.x + b.x + c.x) * (1.f / 3.f), (a.y + b.y + c.y) * (1.f / 3.f),
                                   (a.z + b.z + c.z) * (1.f / 3.f), (a.w + b.w + c.w) * (1.f / 3.f));
            cvt4(m, h, l);
        } else {
            h = make_uint2(0u, 0u); l = make_uint2(0u, 0u);
        }
        ((uint2*)g_Whmh)[i] = h; ((uint2*)g_Whml)[i] = l;
    } else if (bid < 11268) {                            // bhm
        int i = (bid - 11264) * 256 + tid;
        if (i < 1024)
            g_bhm[i] = (i < Ccls) ? (bh[i] + bh[i + Ccls] + bh[i + 2 * Ccls]) * (1.f / 3.f) : 0.f;
    } else if (bid < 12292) {                            // zero_sim
        g_sim[(bid - 11268) * 256 + tid] = 0.f;
    } else if (bid < 12356) {                            // b2a (row n = local bid)
        __shared__ float rowv[64];
        int n = bid - 12292;
        if (tid == 0) {
            float sum = 0.f;
            for (int c = 0; c < 64; c++) {
                float v = sigmoidf_(edge_w[n * 64 + c] * 1.5f) * mask[n * 64 + c];
                rowv[c] = v; sum += v;
            }
            float inv = 1.f / fmaxf(sum, 1e-6f);
            for (int c = 0; c < 64; c++) rowv[c] = rowv[c] * inv;
        }
        __syncthreads();
        if (tid < 64) {
            int d = tid;
            float acc = 0.f;
            for (int m = 0; m < 64; m++) acc += rowv[m] * b2[m * 64 + d];
            g_b2a[n * 64 + d] = acc;
        }
    } else {                                             // prep_node (n = local bid)
        __shared__ float us[64], v[64], red[64];
        int n = bid - 12356;
        int t = tid;
        const float* Ws = Wslow + (size_t)n * 4096;
        if (t < 64) us[t] = u[n * 64 + t];
        __syncthreads();
        if (t < 64) {
            float acc = 0.f;
            for (int o = 0; o < 64; o++) acc += Ws[o * 64 + t] * us[o];
            v[t] = acc;
        }
        __syncthreads();
        if (t < 64) {
            float wv = 0.f;
            for (int i = 0; i < 64; i++) wv += Ws[t * 64 + i] * v[i];
            red[t] = us[t] * wv;
        }
        __syncthreads();
        for (int off = 32; off > 0; off >>= 1) {
            if (t < off) red[t] += red[t + off];
            __syncthreads();
        }
        float inv = 1.f / (red[0] + 1e-8f);
        const float* Wfa = Wfast + (size_t)n * 4096;
        float* outp = g_WcT + (size_t)n * 4096;
        for (int idx = t; idx < 4096; idx += 256) {
            int i = idx >> 6, o = idx & 63;
            outp[idx] = Ws[o * 64 + i] * inv + Wfa[o * 64 + i];
        }
        if (t < 64) {
            float c = bf[n * 64 + t];
            const float* Wf2 = Wf + (size_t)n * 8192 + 4096;
            for (int i = 0; i < 64; i++) c += hprev[n * 64 + i] * Wf2[i * 64 + t];
            g_cf[n * 64 + t] = c;
        }
    }
}

// ================= fold W2 (computes adjacency in-kernel, bit-exact) =================
__global__ void __launch_bounds__(256) fold_w2(const float* __restrict__ W2,
                                               const float* __restrict__ edge_w,
                                               const float* __restrict__ mask) {
    int kt = blockIdx.x;
    int d  = blockIdx.y;
    __shared__ float tile[64][128];
    __shared__ float adjT[64 * 64];   // adjT[m*64+n] = adj[n][m]
    int tid = threadIdx.x;
    if (tid < 64) {                   // replay prep_adj row `tid` exactly
        int r = tid;
        float sum = 0.f;
        for (int c = 0; c < 64; c++) {
            float v = sigmoidf_(edge_w[r * 64 + c] * 1.5f) * mask[r * 64 + c];
            adjT[c * 64 + r] = v; sum += v;
        }
        float inv = 1.f / fmaxf(sum, 1e-6f);
        for (int c = 0; c < 64; c++) adjT[c * 64 + r] = adjT[c * 64 + r] * inv;
    }
    for (int i = tid; i < 64 * 32; i += 256) {
        int m = i >> 5, c4 = (i & 31) << 2;
        *(float4*)&tile[m][c4] = *(const float4*)(W2 + (size_t)(m * 64 + d) * Hdim + kt * 128 + c4);
    }
    __syncthreads();
    int n = tid & 63;
    int kq = tid >> 6;
    float4 acc[8];
#pragma unroll
    for (int q = 0; q < 8; q++) acc[q] = make_float4(0.f, 0.f, 0.f, 0.f);
    for (int m = 0; m < 64; m++) {
        float s = adjT[m * 64 + n];
        const float4* trow = (const float4*)&tile[m][kq * 32];
#pragma unroll
        for (int q = 0; q < 8; q++) {
            float4 t4 = trow[q];
            acc[q].x += s * t4.x; acc[q].y += s * t4.y;
            acc[q].z += s * t4.z; acc[q].w += s * t4.w;
        }
    }
    size_t off4 = ((size_t)(n * 64 + d) * Hdim + kt * 128 + kq * 32) >> 2;
#pragma unroll
    for (int q = 0; q < 8; q++) {
        uint2 h, l; cvt4(acc[q], h, l);
        ((uint2*)g_W2h)[off4 + q] = h;
        ((uint2*)g_W2l)[off4 + q] = l;
    }
}

// ================= split-fp16 HMMA GEMM (persistent tile loop) =================
#define TSTRIDE 40
#define ROWB (TSTRIDE * 2)
#define TILE_B (128 * ROWB)
#define STAGE_B (4 * TILE_B)
#define GSMEM_TOTAL (2 * STAGE_B)

template <int NI, int PASSES>
__global__ void __launch_bounds__(256, 2) gemm_mma(
    const __half* __restrict__ Ahi, const __half* __restrict__ Alo,
    const __half* __restrict__ Bhi, const __half* __restrict__ Blo,
    const float* __restrict__ bias, float* __restrict__ C,
    int K, int lda, int Nstore, int act, int atomicOut,
    int tilesX, int tilesTotal) {
    extern __shared__ char smem[];
    const int tid = threadIdx.x;
    const int wid = tid >> 5;
    const int lane = tid & 31;
    const int grp = lane >> 2;
    const int qp = lane & 3;
    const int wm = (wid >> 2) * 64;
    const int wn = (wid & 3) * (NI * 8);
    const int kbase = blockIdx.z * K;
    const uint32_t sb = smem_u32(smem);

    const int row = tid >> 2;
    const int c16 = tid & 3;

    const int aRowL = wm + (lane & 7) + ((lane >> 3) & 1) * 8;
    const int aKL = (lane >> 4) * 8;
    const int bRowL = wn + (lane & 7) + (lane >> 4) * 8;
    const int bKL = ((lane >> 3) & 1) * 8;

    const int nc = K >> 5;

    for (int t = blockIdx.x; t < tilesTotal; t += gridDim.x) {
        const int bm = (t / tilesX) * 128;
        const int bn = (t % tilesX) * 128;
        __syncthreads();

        float acc[4][NI][4];
#pragma unroll
        for (int mi = 0; mi < 4; mi++)
#pragma unroll
            for (int ni = 0; ni < NI; ni++)
#pragma unroll
                for (int j = 0; j < 4; j++) acc[mi][ni][j] = 0.f;

        auto issue = [&](int c, int s) {
            const uint32_t ss = sb + s * STAGE_B;
            const int k0 = c << 5;
#pragma unroll
            for (int tt = 0; tt < 2; tt++) {
                const int r = row + tt * 64;
                const uint32_t so = (uint32_t)r * ROWB + c16 * 16;
                const size_t gAoff = ((size_t)(bm + r) * lda + kbase + k0) * 2 + c16 * 16;
                const size_t gBoff = ((size_t)(bn + r) * lda + kbase + k0) * 2 + c16 * 16;
                cp16(ss + 0 * TILE_B + so, (const char*)Ahi + gAoff);
                if (PASSES == 3) cp16(ss + 1 * TILE_B + so, (const char*)Alo + gAoff);
                cp16(ss + 2 * TILE_B + so, (const char*)Bhi + gBoff);
                if (PASSES >= 2) cp16(ss + 3 * TILE_B + so, (const char*)Blo + gBoff);
            }
        };

        issue(0, 0); CP_COMMIT();
        if (nc > 1) issue(1, 1);
        CP_COMMIT();

        for (int c = 0; c < nc; c++) {
            const int s = c & 1;
            CP_WAIT1();
            __syncthreads();
            const uint32_t st = sb + s * STAGE_B;
#pragma unroll
            for (int ks = 0; ks < 2; ks++) {
                const int k0 = ks * 16;
                uint32_t ah[4][4], al[4][4];
#pragma unroll
                for (int mi = 0; mi < 4; mi++) {
                    const uint32_t ad = st + (uint32_t)(aRowL + mi * 16) * ROWB + (k0 + aKL) * 2;
                    ldsm_x4(ah[mi][0], ah[mi][1], ah[mi][2], ah[mi][3], ad);
                    if (PASSES == 3) ldsm_x4(al[mi][0], al[mi][1], al[mi][2], al[mi][3], ad + TILE_B);
                }
                uint32_t bh[NI][2], bl[NI][2];
#pragma unroll
                for (int p = 0; p < NI / 2; p++) {
                    const uint32_t bd = st + 2 * TILE_B + (uint32_t)(bRowL + p * 16) * ROWB + (k0 + bKL) * 2;
                    uint32_t r0, r1, r2, r3;
                    ldsm_x4(r0, r1, r2, r3, bd);
                    bh[2 * p][0] = r0; bh[2 * p][1] = r1; bh[2 * p + 1][0] = r2; bh[2 * p + 1][1] = r3;
                    if (PASSES >= 2) {
                        ldsm_x4(r0, r1, r2, r3, bd + TILE_B);
                        bl[2 * p][0] = r0; bl[2 * p][1] = r1; bl[2 * p + 1][0] = r2; bl[2 * p + 1][1] = r3;
                    }
                }
#pragma unroll
                for (int ni = 0; ni < NI; ni++) {
#pragma unroll
                    for (int mi = 0; mi < 4; mi++) {
                        mma16816(acc[mi][ni], ah[mi], bh[ni][0], bh[ni][1]);
                        if (PASSES >= 2) mma16816(acc[mi][ni], ah[mi], bl[ni][0], bl[ni][1]);
                        if (PASSES == 3) mma16816(acc[mi][ni], al[mi], bh[ni][0], bh[ni][1]);
                    }
                }
            }
            __syncthreads();
            if (c + 2 < nc) issue(c + 2, s);
            CP_COMMIT();
        }

        // epilogue
#pragma unroll
        for (int mi = 0; mi < 4; mi++) {
#pragma unroll
            for (int ni = 0; ni < NI; ni++) {
                const int r0 = bm + wm + mi * 16 + grp;
                const int col = bn + wn + ni * 8 + qp * 2;
                float* a4 = acc[mi][ni];
                if (atomicOut) {
                    if (col < Nstore) {
                        atomicAdd(&C[(size_t)r0 * Nstore + col], a4[0]);
                        atomicAdd(&C[(size_t)(r0 + 8) * Nstore + col], a4[2]);
                        if (col + 1 < Nstore) {
                            atomicAdd(&C[(size_t)r0 * Nstore + col + 1], a4[1]);
                            atomicAdd(&C[(size_t)(r0 + 8) * Nstore + col + 1], a4[3]);
                        }
                    }
                } else if (col + 1 < Nstore) {
                    float2 v0, v1;
                    float bb0 = bias ? bias[col] : 0.f;
                    float bb1 = bias ? bias[col + 1] : 0.f;
                    v0.x = a4[0] + bb0; v0.y = a4[1] + bb1;
                    v1.x = a4[2] + bb0; v1.y = a4[3] + bb1;
                    if (act == 1) {
                        v0.x = fmaxf(v0.x, 0.f); v0.y = fmaxf(v0.y, 0.f);
                        v1.x = fmaxf(v1.x, 0.f); v1.y = fmaxf(v1.y, 0.f);
                    }
                    *(float2*)(C + (size_t)r0 * Nstore + col) = v0;
                    *(float2*)(C + (size_t)(r0 + 8) * Nstore + col) = v1;
                } else if (col < Nstore) {
                    float bb0 = bias ? bias[col] : 0.f;
                    float v0 = a4[0] + bb0, v1 = a4[2] + bb0;
                    if (act == 1) { v0 = fmaxf(v0, 0.f); v1 = fmaxf(v1, 0.f); }
                    C[(size_t)r0 * Nstore + col] = v0;
                    C[(size_t)(r0 + 8) * Nstore + col] = v1;
                }
            }
        }
    }
}

// ================= LayerNorm(H=1024) + GELU -> fp16 hi/lo =================
__global__ void __launch_bounds__(256) ln_gelu_kernel(const float* __restrict__ h,
                                                      const float* __restrict__ g,
                                                      const float* __restrict__ beta,
                                                      uint2* __restrict__ hi,
                                                      uint2* __restrict__ lo) {
    int row = blockIdx.x;
    const float* hr = h + (size_t)row * Hdim;
    int tid = threadIdx.x;
    float4 v = *(const float4*)(hr + tid * 4);
    float s = v.x + v.y + v.z + v.w;
    float ss = v.x * v.x + v.y * v.y + v.z * v.z + v.w * v.w;
    __shared__ float rs[8], rss[8];
    for (int o = 16; o > 0; o >>= 1) {
        s += __shfl_down_sync(0xffffffffu, s, o);
        ss += __shfl_down_sync(0xffffffffu, ss, o);
    }
    if ((tid & 31) == 0) { rs[tid >> 5] = s; rss[tid >> 5] = ss; }
    __syncthreads();
    if (tid < 32) {
        float a = tid < 8 ? rs[tid] : 0.f;
        float b = tid < 8 ? rss[tid] : 0.f;
        for (int o = 4; o > 0; o >>= 1) {
            a += __shfl_down_sync(0xffffffffu, a, o);
            b += __shfl_down_sync(0xffffffffu, b, o);
        }
        if (tid == 0) { rs[0] = a; rss[0] = b; }
    }
    __syncthreads();
    float mu = rs[0] * (1.f / Hdim);
    float var = rss[0] * (1.f / Hdim) - mu * mu;
    float inv = rsqrtf(var + 1e-5f);
    float4 gg = *(const float4*)(g + tid * 4);
    float4 bb = *(const float4*)(beta + tid * 4);
    float y;
    y = (v.x - mu) * inv * gg.x + bb.x; v.x = 0.5f * y * (1.f + erff(y * 0.70710678118654752f));
    y = (v.y - mu) * inv * gg.y + bb.y; v.y = 0.5f * y * (1.f + erff(y * 0.70710678118654752f));
    y = (v.z - mu) * inv * gg.z + bb.z; v.z = 0.5f * y * (1.f + erff(y * 0.70710678118654752f));
    y = (v.w - mu) * inv * gg.w + bb.w; v.w = 0.5f * y * (1.f + erff(y * 0.70710678118654752f));
    uint2 hh, ll; cvt4(v, hh, ll);
    hi[(size_t)row * 256 + tid] = hh;
    lo[(size_t)row * 256 + tid] = ll;
}

// ================= fused cell kernel (packed f32x2 FMA) =================
#define CELL_SMEM ((64 * 68 * 2 + 4096 * 4 + 7 * 64) * sizeof(float))
__global__ void __launch_bounds__(256) cell_kernel(const float* __restrict__ Wi,
                                                   const float* __restrict__ Wf,
                                                   const float* __restrict__ Wo,
                                                   const float* __restrict__ bi_g,
                                                   const float* __restrict__ bslow_g,
                                                   const float* __restrict__ bo_g,
                                                   const float* __restrict__ hprev_g,
                                                   const float* __restrict__ gln_g,
                                                   const float* __restrict__ bln_g,
                                                   float* __restrict__ xflat_out,
                                                   uint32_t* __restrict__ xfh,
                                                   uint32_t* __restrict__ xfl) {
    extern __shared__ float sf[];
    float* xs = sf;
    float* wi = xs + 64 * 68;
    float* wf = wi + 4096;
    float* wc = wf + 4096;
    float* wo = wc + 4096;
    float* hr = wo + 4096;
    float* vecs = hr + 64 * 68;

    int n = blockIdx.x;
    int b0 = blockIdx.y * 64;
    int tid = threadIdx.x;

#pragma unroll
    for (int j = 0; j < 4; j++) {
        int idx = tid + j * 256;
        int row = idx >> 4, c4 = (idx & 15) << 2;
        *(float4*)(xs + row * 68 + c4) =
            *(const float4*)(g_xagg + (((size_t)(b0 + row) * 64 + n) << 6) + c4);
        ((float4*)wi)[idx] = ((const float4*)(Wi + (size_t)n * 4096))[idx];
        ((float4*)wf)[idx] = ((const float4*)(Wf + (size_t)n * 8192))[idx];
        ((float4*)wc)[idx] = ((const float4*)(g_WcT + (size_t)n * 4096))[idx];
        ((float4*)wo)[idx] = ((const float4*)(Wo + (size_t)n * 4096))[idx];
    }
    if (tid < 64) {
        vecs[0 * 64 + tid] = bi_g[n * 64 + tid];
        vecs[1 * 64 + tid] = g_cf[n * 64 + tid];
        vecs[2 * 64 + tid] = bslow_g[n * 64 + tid];
        vecs[3 * 64 + tid] = bo_g[n * 64 + tid];
        vecs[4 * 64 + tid] = hprev_g[n * 64 + tid];
        vecs[5 * 64 + tid] = gln_g[n * 64 + tid];
        vecs[6 * 64 + tid] = bln_g[n * 64 + tid];
    }
    __syncthreads();

    const int r0 = (tid >> 4) * 4;
    const int c0 = (tid & 15) * 4;

    unsigned long long ai2[4][2], af2[4][2], ac2[4][2];
#pragma unroll
    for (int r = 0; r < 4; r++)
#pragma unroll
        for (int p = 0; p < 2; p++) { ai2[r][p] = 0ull; af2[r][p] = 0ull; ac2[r][p] = 0ull; }

    for (int i = 0; i < 64; i++) {
        unsigned long long xp[4];
#pragma unroll
        for (int r = 0; r < 4; r++) {
            float xv = xs[(r0 + r) * 68 + i];
            PACKF2(xp[r], xv, xv);
        }
        float4 w1 = *(const float4*)(wi + i * 64 + c0);
        float4 w2 = *(const float4*)(wf + i * 64 + c0);
        float4 w3 = *(const float4*)(wc + i * 64 + c0);
        unsigned long long w1p[2], w2p[2], w3p[2];
        PACKF2(w1p[0], w1.x, w1.y); PACKF2(w1p[1], w1.z, w1.w);
        PACKF2(w2p[0], w2.x, w2.y); PACKF2(w2p[1], w2.z, w2.w);
        PACKF2(w3p[0], w3.x, w3.y); PACKF2(w3p[1], w3.z, w3.w);
#pragma unroll
        for (int r = 0; r < 4; r++) {
            FMA_F32X2(ai2[r][0], xp[r], w1p[0]); FMA_F32X2(ai2[r][1], xp[r], w1p[1]);
            FMA_F32X2(af2[r][0], xp[r], w2p[0]); FMA_F32X2(af2[r][1], xp[r], w2p[1]);
            FMA_F32X2(ac2[r][0], xp[r], w3p[0]); FMA_F32X2(ac2[r][1], xp[r], w3p[1]);
        }
    }
#pragma unroll
    for (int r = 0; r < 4; r++)
#pragma unroll
        for (int p = 0; p < 2; p++) {
            float aiv0, aiv1, afv0, afv1, acv0, acv1;
            UNPACKF2(aiv0, aiv1, ai2[r][p]);
            UNPACKF2(afv0, afv1, af2[r][p]);
            UNPACKF2(acv0, acv1, ac2[r][p]);
            int o = c0 + 2 * p;
            float it0 = sigmoidf_(aiv0 + vecs[0 * 64 + o]);
            float ft0 = sigmoidf_(afv0 + vecs[1 * 64 + o]);
            float hs0 = acv0 + vecs[2 * 64 + o];
            hr[(r0 + r) * 68 + o] = it0 * hs0 + ft0 * vecs[4 * 64 + o];
            float it1 = sigmoidf_(aiv1 + vecs[0 * 64 + o + 1]);
            float ft1 = sigmoidf_(afv1 + vecs[1 * 64 + o + 1]);
            float hs1 = acv1 + vecs[2 * 64 + o + 1];
            hr[(r0 + r) * 68 + o + 1] = it1 * hs1 + ft1 * vecs[4 * 64 + o + 1];
        }
    __syncthreads();

    unsigned long long ao2[4][2];
#pragma unroll
    for (int r = 0; r < 4; r++)
#pragma unroll
        for (int p = 0; p < 2; p++) ao2[r][p] = 0ull;
    for (int i = 0; i < 64; i++) {
        unsigned long long xp[4];
#pragma unroll
        for (int r = 0; r < 4; r++) {
            float xv = hr[(r0 + r) * 68 + i];
            PACKF2(xp[r], xv, xv);
        }
        float4 w = *(const float4*)(wo + i * 64 + c0);
        unsigned long long wp[2];
        PACKF2(wp[0], w.x, w.y); PACKF2(wp[1], w.z, w.w);
#pragma unroll
        for (int r = 0; r < 4; r++) {
            FMA_F32X2(ao2[r][0], xp[r], wp[0]);
            FMA_F32X2(ao2[r][1], xp[r], wp[1]);
        }
    }
    float* ys = xs;
#pragma unroll
    for (int r = 0; r < 4; r++)
#pragma unroll
        for (int p = 0; p < 2; p++) {
            float a0, a1;
            UNPACKF2(a0, a1, ao2[r][p]);
            int o = c0 + 2 * p;
            float ot0 = sigmoidf_(a0 + vecs[3 * 64 + o]);
            float ot1 = sigmoidf_(a1 + vecs[3 * 64 + o + 1]);
            ys[(r0 + r) * 68 + o] = ot0 * tanhf(hr[(r0 + r) * 68 + o]);
            ys[(r0 + r) * 68 + o + 1] = ot1 * tanhf(hr[(r0 + r) * 68 + o + 1]);
        }
    __syncthreads();

    int w = tid >> 5, lane = tid & 31;
    for (int rr = 0; rr < 8; rr++) {
        int row = w * 8 + rr;
        float v0 = ys[row * 68 + 2 * lane];
        float v1 = ys[row * 68 + 2 * lane + 1];
        float s = v0 + v1;
        float ss = v0 * v0 + v1 * v1;
        for (int o = 16; o > 0; o >>= 1) {
            s += __shfl_xor_sync(0xffffffffu, s, o);
            ss += __shfl_xor_sync(0xffffffffu, ss, o);
        }
        float mu = s * (1.f / 64.f);
        float var = ss * (1.f / 64.f) - mu * mu;
        float inv = rsqrtf(var + 1e-5f);
        float y0 = (v0 - mu) * inv * vecs[5 * 64 + 2 * lane] + vecs[6 * 64 + 2 * lane];
        float y1 = (v1 - mu) * inv * vecs[5 * 64 + 2 * lane + 1] + vecs[6 * 64 + 2 * lane + 1];
        size_t base = (size_t)(b0 + row) * 4096 + n * 64;
        *(float2*)(xflat_out + base + 2 * lane) = make_float2(y0, y1);
        uint32_t hh, ll; cvt2(y0, y1, hh, ll);
        xfh[(base >> 1) + lane] = hh;
        xfl[(base >> 1) + lane] = ll;
    }
}

// ================= top-5 retrieval + update + fp16 re-emit =================
__global__ void __launch_bounds__(256) retrieve_kernel(const float* __restrict__ mem,
                                                       float* __restrict__ xflat,
                                                       uint2* __restrict__ xfh,
                                                       uint2* __restrict__ xfl) {
    int b = blockIdx.x;
    __shared__ float s[64];
    __shared__ int top[5];
    int tid = threadIdx.x;
    if (tid < 64) s[tid] = g_sim[b * 64 + tid];
    __syncthreads();
    if (tid < 32) {
        for (int k = 0; k < 5; k++) {
            float v = s[tid]; int idx = tid;
            float v2 = s[tid + 32];
            if (v2 > v) { v = v2; idx = tid + 32; }
            for (int o = 16; o > 0; o >>= 1) {
                float ov = __shfl_down_sync(0xffffffffu, v, o);
                int oi = __shfl_down_sync(0xffffffffu, idx, o);
                if (ov > v || (ov == v && oi < idx)) { v = ov; idx = oi; }
            }
            idx = __shfl_sync(0xffffffffu, idx, 0);
            if (tid == 0) top[k] = idx;
            if (tid == 0) s[idx] = -INFINITY;
            __syncwarp();
        }
    }
    __syncthreads();
    const float4* m4 = (const float4*)mem;
    float4* x4 = (float4*)(xflat + (size_t)b * 4096);
    int t0 = top[0] * 1024, t1 = top[1] * 1024, t2 = top[2] * 1024, t3 = top[3] * 1024, t4 = top[4] * 1024;
#pragma unroll
    for (int j = 0; j < 4; j++) {
        int idx = tid + j * 256;
        float4 xv = x4[idx];
        float4 a = m4[t0 + idx], bb = m4[t1 + idx], c = m4[t2 + idx], d = m4[t3 + idx], e = m4[t4 + idx];
        xv.x += 0.02f * (a.x + bb.x + c.x + d.x + e.x);
        xv.y += 0.02f * (a.y + bb.y + c.y + d.y + e.y);
        xv.z += 0.02f * (a.z + bb.z + c.z + d.z + e.z);
        xv.w += 0.02f * (a.w + bb.w + c.w + d.w + e.w);
        x4[idx] = xv;
        uint2 h, l; cvt4(xv, h, l);
        xfh[(size_t)b * 1024 + idx] = h;
        xfl[(size_t)b * 1024 + idx] = l;
    }
}

// ================= proj2 =================
__global__ void __launch_bounds__(256) proj2_kernel(const float* __restrict__ s1,
                                                    const float* __restrict__ Ws2,
                                                    const float* __restrict__ bs2,
                                                    float* __restrict__ proj) {
    __shared__ float w2s[8 * 1024];
    __shared__ float bss[8];
    int tid = threadIdx.x;
    for (int i = tid; i < 8192; i += 256) w2s[i] = Ws2[i];
    if (tid < 8) bss[tid] = bs2[tid];
    __syncthreads();
    int w = tid >> 5, lane = tid & 31;
    int b = blockIdx.x * 8 + w;
    const float4* row = (const float4*)(s1 + (size_t)b * 1024);
    float4 xv[8];
#pragma unroll
    for (int j = 0; j < 8; j++) xv[j] = row[lane + j * 32];
#pragma unroll
    for (int p = 0; p < 8; p++) {
        const float4* wr = (const float4*)(w2s + p * 1024);
        float acc = 0.f;
#pragma unroll
        for (int j = 0; j < 8; j++) {
            float4 wv = wr[lane + j * 32];
            acc += xv[j].x * wv.x + xv[j].y * wv.y + xv[j].z * wv.z + xv[j].w * wv.w;
        }
        for (int o = 16; o > 0; o >>= 1) acc += __shfl_xor_sync(0xffffffffu, acc, o);
        if (lane == 0) proj[(size_t)b * 8 + p] = acc + bss[p];
    }
}

// ================= launch =================
extern "C" void kernel_launch(void* const* d_in, const int* in_sizes, int n_in,
                              void* d_out, int out_size) {
    const float* x      = (const float*)d_in[0];
    const float* W1     = (const float*)d_in[1];
    const float* b1     = (const float*)d_in[2];
    const float* g1     = (const float*)d_in[3];
    const float* beta1  = (const float*)d_in[4];
    const float* W2     = (const float*)d_in[5];
    const float* b2     = (const float*)d_in[6];
    const float* edge_w = (const float*)d_in[7];
    const float* mask   = (const float*)d_in[8];
    const float* Wi     = (const float*)d_in[9];
    const float* bi     = (const float*)d_in[10];
    const float* Wf     = (const float*)d_in[11];
    const float* bf     = (const float*)d_in[12];
    const float* Wslow  = (const float*)d_in[13];
    const float* bslow  = (const float*)d_in[14];
    const float* u      = (const float*)d_in[15];
    const float* Wfast  = (const float*)d_in[16];
    const float* Wo     = (const float*)d_in[17];
    const float* bo     = (const float*)d_in[18];
    const float* gln    = (const float*)d_in[19];
    const float* bln    = (const float*)d_in[20];
    const float* h_prev = (const float*)d_in[21];
    const float* memory = (const float*)d_in[22];
    const float* Wh     = (const float*)d_in[23];
    const float* bh     = (const float*)d_in[24];
    const float* Ws1    = (const float*)d_in[25];
    const float* bs1    = (const float*)d_in[26];
    const float* Ws2    = (const float*)d_in[27];
    const float* bs2    = (const float*)d_in[28];

    float* out    = (float*)d_out;
    float* logits = out;
    float* proj   = out + (size_t)Bn * Ccls;
    float* xflat  = proj + (size_t)Bn * Pp;

    float *p_h1, *p_b2a, *p_xagg, *p_sim, *p_s1, *p_bhm;
    cudaGetSymbolAddress((void**)&p_h1, g_h1);
    cudaGetSymbolAddress((void**)&p_b2a, g_b2a);
    cudaGetSymbolAddress((void**)&p_xagg, g_xagg);
    cudaGetSymbolAddress((void**)&p_sim, g_sim);
    cudaGetSymbolAddress((void**)&p_s1, g_s1);
    cudaGetSymbolAddress((void**)&p_bhm, g_bhm);
    void *p_xh, *p_xl, *p_W1h, *p_W1l, *p_h1h, *p_h1l, *p_W2h, *p_W2l;
    void *p_xfh, *p_xfl, *p_Whmh, *p_Whml, *p_Ws1h, *p_Ws1l, *p_memh, *p_meml;
    cudaGetSymbolAddress(&p_xh, g_xh);   cudaGetSymbolAddress(&p_xl, g_xl);
    cudaGetSymbolAddress(&p_W1h, g_W1h); cudaGetSymbolAddress(&p_W1l, g_W1l);
    cudaGetSymbolAddress(&p_h1h, g_h1h); cudaGetSymbolAddress(&p_h1l, g_h1l);
    cudaGetSymbolAddress(&p_W2h, g_W2h); cudaGetSymbolAddress(&p_W2l, g_W2l);
    cudaGetSymbolAddress(&p_xfh, g_xfh); cudaGetSymbolAddress(&p_xfl, g_xfl);
    cudaGetSymbolAddress(&p_Whmh, g_Whmh); cudaGetSymbolAddress(&p_Whml, g_Whml);
    cudaGetSymbolAddress(&p_Ws1h, g_Ws1h); cudaGetSymbolAddress(&p_Ws1l, g_Ws1l);
    cudaGetSymbolAddress(&p_memh, g_memh); cudaGetSymbolAddress(&p_meml, g_meml);

    int nsm = 148;
    cudaDeviceGetAttribute(&nsm, cudaDevAttrMultiProcessorCount, 0);
    int persist = 2 * nsm;
    if (persist > 1024) persist = 1024;

    cudaFuncSetAttribute(cell_kernel, cudaFuncAttributeMaxDynamicSharedMemorySize, CELL_SMEM);
    cudaFuncSetAttribute(gemm_mma<4, 3>, cudaFuncAttributeMaxDynamicSharedMemorySize, GSMEM_TOTAL);
    cudaFuncSetAttribute(gemm_mma<4, 2>, cudaFuncAttributeMaxDynamicSharedMemorySize, GSMEM_TOTAL);
    cudaFuncSetAttribute(gemm_mma<4, 1>, cudaFuncAttributeMaxDynamicSharedMemorySize, GSMEM_TOTAL);
    cudaFuncSetAttribute(gemm_mma<2, 3>, cudaFuncAttributeMaxDynamicSharedMemorySize, GSMEM_TOTAL);

    // fused prep (cvt x/W1/Ws1, mem pad, whm, bhm, zero_sim, b2a, prep_node)
    misc_prep<<<MISC_BLOCKS, 256>>>(x, W1, Ws1, memory, Wh, bh, b2, edge_w, mask,
                                    Wslow, u, Wfast, Wf, bf, h_prev);
    fold_w2<<<dim3(8, 64), 256>>>(W2, edge_w, mask);

    // stage 1: input projection (3-pass); G2 -> x_agg (2-pass, persistent tiles)
    gemm_mma<4, 3><<<256, 256, GSMEM_TOTAL>>>(
        (const __half*)p_xh, (const __half*)p_xl,
        (const __half*)p_W1h, (const __half*)p_W1l, b1, p_h1,
        Fdim, Fdim, Hdim, 0, 0, Hdim / 128, (Hdim / 128) * (Bn / 128));
    ln_gelu_kernel<<<Bn, 256>>>(p_h1, g1, beta1, (uint2*)p_h1h, (uint2*)p_h1l);
    gemm_mma<4, 2><<<persist, 256, GSMEM_TOTAL>>>(
        (const __half*)p_h1h, nullptr,
        (const __half*)p_W2h, (const __half*)p_W2l, p_b2a, p_xagg,
        Hdim, Hdim, FLAT, 0, 0, FLAT / 128, (FLAT / 128) * (Bn / 128));

    // stage 2: cells
    cell_kernel<<<dim3(Nn, Bn / 64), 256, CELL_SMEM>>>(Wi, Wf, Wo, bi, bslow, bo,
                                                       h_prev, gln, bln, xflat,
                                                       (uint32_t*)p_xfh, (uint32_t*)p_xfl);

    // stage 3: retrieval (split-K sim GEMM, atomic accumulate; 3-pass keeps top-k tight)
    gemm_mma<2, 3><<<dim3(Bn / 128, 1, 4), 256, GSMEM_TOTAL>>>(
        (const __half*)p_xfh, (const __half*)p_xfl,
        (const __half*)p_memh, (const __half*)p_meml, nullptr, p_sim,
        FLAT / 4, FLAT, CAP, 0, 1, 1, Bn / 128);
    retrieve_kernel<<<Bn, 256>>>(memory, xflat, (uint2*)p_xfh, (uint2*)p_xfl);

    // stage 4: heads (1-pass fp16)
    gemm_mma<4, 1><<<256, 256, GSMEM_TOTAL>>>(
        (const __half*)p_xfh, nullptr,
        (const __half*)p_Whmh, nullptr, p_bhm, logits,
        FLAT, FLAT, Ccls, 0, 0, 1024 / 128, (1024 / 128) * (Bn / 128));
    gemm_mma<4, 1><<<256, 256, GSMEM_TOTAL>>>(
        (const __half*)p_xfh, nullptr,
        (const __half*)p_Ws1h, nullptr, bs1, p_s1,
        FLAT, FLAT, Hdim, 1, 0, Hdim / 128, (Hdim / 128) * (Bn / 128));
    proj2_kernel<<<Bn / 8, 256>>>(p_s1, Ws2, bs2, proj);
}

// round 16
// speedup vs baseline: 1.5314x; 1.0201x over previous
#include <cuda_runtime.h>
#include <cuda_fp16.h>
#include <math.h>
#include <stdint.h>

#define Bn 4096
#define Fdim 512
#define Hdim 1024
#define Nn 64
#define Dd 64
#define FLAT 4096
#define Ccls 1000
#define CAP 64
#define Pp 8

// ================= scratch (device globals) =================
__device__ float g_h1[Bn * Hdim];
__device__ float g_b2a[FLAT];
__device__ float g_xagg[(size_t)Bn * FLAT];
__device__ float g_sim[Bn * CAP];
__device__ float g_s1[Bn * Hdim];
__device__ float g_bcat[2048];
__device__ float g_WcT[Nn * Dd * Dd];
__device__ float g_cf[Nn * Dd];
// fp16 hi/lo operand buffers
__device__ __half g_xh[Bn * Fdim],    g_xl[Bn * Fdim];
__device__ __half g_W1h[Hdim * Fdim], g_W1l[Hdim * Fdim];
__device__ __half g_h1h[Bn * Hdim],   g_h1l[Bn * Hdim];
__device__ __half g_W2h[FLAT * Hdim], g_W2l[FLAT * Hdim];
__device__ __half g_xfh[(size_t)Bn * FLAT], g_xfl[(size_t)Bn * FLAT];
__device__ __half g_Wcath[(size_t)2048 * FLAT];   // rows 0-1023: mean(Wh) padded; 1024-2047: Ws1
__device__ __half g_memh[128 * FLAT], g_meml[128 * FLAT];

__device__ __forceinline__ float sigmoidf_(float x) { return 1.f / (1.f + expf(-x)); }

__device__ __forceinline__ uint32_t pack2h(__half a, __half b) {
    return (uint32_t)__half_as_ushort(a) | ((uint32_t)__half_as_ushort(b) << 16);
}
__device__ __forceinline__ void cvt4(float4 v, uint2& hi, uint2& lo) {
    __half h0 = __float2half_rn(v.x), h1 = __float2half_rn(v.y);
    __half h2 = __float2half_rn(v.z), h3 = __float2half_rn(v.w);
    __half l0 = __float2half_rn(v.x - __half2float(h0));
    __half l1 = __float2half_rn(v.y - __half2float(h1));
    __half l2 = __float2half_rn(v.z - __half2float(h2));
    __half l3 = __float2half_rn(v.w - __half2float(h3));
    hi.x = pack2h(h0, h1); hi.y = pack2h(h2, h3);
    lo.x = pack2h(l0, l1); lo.y = pack2h(l2, l3);
}
__device__ __forceinline__ uint2 cvt4hi(float4 v) {
    __half h0 = __float2half_rn(v.x), h1 = __float2half_rn(v.y);
    __half h2 = __float2half_rn(v.z), h3 = __float2half_rn(v.w);
    uint2 hi; hi.x = pack2h(h0, h1); hi.y = pack2h(h2, h3);
    return hi;
}
__device__ __forceinline__ void cvt2(float a, float b, uint32_t& hi, uint32_t& lo) {
    __half h0 = __float2half_rn(a), h1 = __float2half_rn(b);
    __half l0 = __float2half_rn(a - __half2float(h0));
    __half l1 = __float2half_rn(b - __half2float(h1));
    hi = pack2h(h0, h1); lo = pack2h(l0, l1);
}

// ================= packed f32x2 FMA (Blackwell) =================
#define FMA_F32X2(d, a, b) \
    asm("fma.rn.f32x2 %0, %1, %2, %0;" : "+l"(d) : "l"(a), "l"(b))
#define PACKF2(out, a, b) \
    asm("mov.b64 %0, {%1, %2};" : "=l"(out) : "f"(a), "f"(b))
#define UNPACKF2(a, b, in) \
    asm("mov.b64 {%0, %1}, %2;" : "=f"(a), "=f"(b) : "l"(in))

// ================= mma / cp.async / ldmatrix primitives =================
__device__ __forceinline__ uint32_t smem_u32(const void* p) {
    uint32_t a;
    asm("{ .reg .u64 t; cvta.to.shared.u64 t, %1; cvt.u32.u64 %0, t; }" : "=r"(a) : "l"(p));
    return a;
}
__device__ __forceinline__ void cp16(uint32_t s, const void* g) {
    asm volatile("cp.async.cg.shared.global [%0], [%1], 16;" :: "r"(s), "l"(g));
}
#define CP_COMMIT() asm volatile("cp.async.commit_group;")
#define CP_WAIT1() asm volatile("cp.async.wait_group 1;")

__device__ __forceinline__ void mma16816(float* d, const uint32_t* a, uint32_t b0, uint32_t b1) {
    asm volatile(
        "mma.sync.aligned.m16n8k16.row.col.f32.f16.f16.f32 "
        "{%0,%1,%2,%3}, {%4,%5,%6,%7}, {%8,%9}, {%0,%1,%2,%3};"
        : "+f"(d[0]), "+f"(d[1]), "+f"(d[2]), "+f"(d[3])
        : "r"(a[0]), "r"(a[1]), "r"(a[2]), "r"(a[3]), "r"(b0), "r"(b1));
}
__device__ __forceinline__ void ldsm_x4(uint32_t& r0, uint32_t& r1, uint32_t& r2, uint32_t& r3,
                                        uint32_t addr) {
    asm volatile("ldmatrix.sync.aligned.m8n8.x4.shared.b16 {%0,%1,%2,%3}, [%4];"
                 : "=r"(r0), "=r"(r1), "=r"(r2), "=r"(r3) : "r"(addr));
}

// ================= fused prep mega-kernel =================
// block ranges (256 threads each):
//  [0, 2048)            cvt_hilo x
//  [2048, 2560)         cvt_hilo W1
//  [2560, 6656)         cvt Ws1 (hi only) -> Wcat rows 1024..2047
//  [6656, 7168)         cvt_mem_pad
//  [7168, 11264)        whm mean (hi only) -> Wcat rows 0..1023
//  [11264, 11272)       bcat (2048: bhm mean ++ bs1)
//  [11272, 12296)       zero_sim
//  [12296, 12360)       b2a (in-branch adj row)
//  [12360, 12424)       prep_node
#define MISC_BLOCKS 12424

__global__ void __launch_bounds__(256) misc_prep(
    const float* __restrict__ x, const float* __restrict__ W1,
    const float* __restrict__ Ws1, const float* __restrict__ mem,
    const float* __restrict__ Wh, const float* __restrict__ bh,
    const float* __restrict__ bs1, const float* __restrict__ b2,
    const float* __restrict__ edge_w, const float* __restrict__ mask,
    const float* __restrict__ Wslow, const float* __restrict__ u,
    const float* __restrict__ Wfast, const float* __restrict__ Wf,
    const float* __restrict__ bf, const float* __restrict__ hprev) {
    const int bid = blockIdx.x;
    const int tid = threadIdx.x;

    if (bid < 2048) {                                    // cvt x
        int i = bid * 256 + tid;
        float4 v = ((const float4*)x)[i];
        uint2 h, l; cvt4(v, h, l);
        ((uint2*)g_xh)[i] = h; ((uint2*)g_xl)[i] = l;
    } else if (bid < 2560) {                             // cvt W1
        int i = (bid - 2048) * 256 + tid;
        float4 v = ((const float4*)W1)[i];
        uint2 h, l; cvt4(v, h, l);
        ((uint2*)g_W1h)[i] = h; ((uint2*)g_W1l)[i] = l;
    } else if (bid < 6656) {                             // Ws1 hi -> Wcat upper
        int i = (bid - 2560) * 256 + tid;
        float4 v = ((const float4*)Ws1)[i];
        ((uint2*)g_Wcath)[(1024 * FLAT / 4) + i] = cvt4hi(v);
    } else if (bid < 7168) {                             // mem pad -> 128 rows
        int i = (bid - 6656) * 256 + tid;
        int row = i >> 10;
        uint2 h = make_uint2(0u, 0u), l = make_uint2(0u, 0u);
        if (row < CAP) {
            float4 v = ((const float4*)mem)[i];
            cvt4(v, h, l);
        }
        ((uint2*)g_memh)[i] = h; ((uint2*)g_meml)[i] = l;
    } else if (bid < 11264) {                            // whm mean hi -> Wcat lower
        int i = (bid - 7168) * 256 + tid;
        int row = i >> 10;
        uint2 h = make_uint2(0u, 0u);
        if (row < Ccls) {
            const size_t CF4 = (size_t)Ccls * FLAT / 4;
            const float4* W4 = (const float4*)Wh;
            float4 a = W4[i], b = W4[i + CF4], c = W4[i + 2 * CF4];
            float4 m = make_float4((a.x + b.x + c.x) * (1.f / 3.f), (a.y + b.y + c.y) * (1.f / 3.f),
                                   (a.z + b.z + c.z) * (1.f / 3.f), (a.w + b.w + c.w) * (1.f / 3.f));
            h = cvt4hi(m);
        }
        ((uint2*)g_Wcath)[i] = h;
    } else if (bid < 11272) {                            // bcat
        int i = (bid - 11264) * 256 + tid;
        if (i < 2048) {
            float v;
            if (i < Ccls) v = (bh[i] + bh[i + Ccls] + bh[i + 2 * Ccls]) * (1.f / 3.f);
            else if (i < 1024) v = 0.f;
            else v = bs1[i - 1024];
            g_bcat[i] = v;
        }
    } else if (bid < 12296) {                            // zero_sim
        g_sim[(bid - 11272) * 256 + tid] = 0.f;
    } else if (bid < 12360) {                            // b2a
        __shared__ float rowv[64];
        int n = bid - 12296;
        if (tid == 0) {
            float sum = 0.f;
            for (int c = 0; c < 64; c++) {
                float v = sigmoidf_(edge_w[n * 64 + c] * 1.5f) * mask[n * 64 + c];
                rowv[c] = v; sum += v;
            }
            float inv = 1.f / fmaxf(sum, 1e-6f);
            for (int c = 0; c < 64; c++) rowv[c] = rowv[c] * inv;
        }
        __syncthreads();
        if (tid < 64) {
            int d = tid;
            float acc = 0.f;
            for (int m = 0; m < 64; m++) acc += rowv[m] * b2[m * 64 + d];
            g_b2a[n * 64 + d] = acc;
        }
    } else {                                             // prep_node
        __shared__ float us[64], v[64], red[64];
        int n = bid - 12360;
        int t = tid;
        const float* Ws = Wslow + (size_t)n * 4096;
        if (t < 64) us[t] = u[n * 64 + t];
        __syncthreads();
        if (t < 64) {
            float acc = 0.f;
            for (int o = 0; o < 64; o++) acc += Ws[o * 64 + t] * us[o];
            v[t] = acc;
        }
        __syncthreads();
        if (t < 64) {
            float wv = 0.f;
            for (int i = 0; i < 64; i++) wv += Ws[t * 64 + i] * v[i];
            red[t] = us[t] * wv;
        }
        __syncthreads();
        for (int off = 32; off > 0; off >>= 1) {
            if (t < off) red[t] += red[t + off];
            __syncthreads();
        }
        float inv = 1.f / (red[0] + 1e-8f);
        const float* Wfa = Wfast + (size_t)n * 4096;
        float* outp = g_WcT + (size_t)n * 4096;
        for (int idx = t; idx < 4096; idx += 256) {
            int i = idx >> 6, o = idx & 63;
            outp[idx] = Ws[o * 64 + i] * inv + Wfa[o * 64 + i];
        }
        if (t < 64) {
            float c = bf[n * 64 + t];
            const float* Wf2 = Wf + (size_t)n * 8192 + 4096;
            for (int i = 0; i < 64; i++) c += hprev[n * 64 + i] * Wf2[i * 64 + t];
            g_cf[n * 64 + t] = c;
        }
    }
}

// ================= fold W2 (in-kernel adjacency, bit-exact) =================
__global__ void __launch_bounds__(256) fold_w2(const float* __restrict__ W2,
                                               const float* __restrict__ edge_w,
                                               const float* __restrict__ mask) {
    int kt = blockIdx.x;
    int d  = blockIdx.y;
    __shared__ float tile[64][128];
    __shared__ float adjT[64 * 64];
    int tid = threadIdx.x;
    if (tid < 64) {
        int r = tid;
        float sum = 0.f;
        for (int c = 0; c < 64; c++) {
            float v = sigmoidf_(edge_w[r * 64 + c] * 1.5f) * mask[r * 64 + c];
            adjT[c * 64 + r] = v; sum += v;
        }
        float inv = 1.f / fmaxf(sum, 1e-6f);
        for (int c = 0; c < 64; c++) adjT[c * 64 + r] = adjT[c * 64 + r] * inv;
    }
    for (int i = tid; i < 64 * 32; i += 256) {
        int m = i >> 5, c4 = (i & 31) << 2;
        *(float4*)&tile[m][c4] = *(const float4*)(W2 + (size_t)(m * 64 + d) * Hdim + kt * 128 + c4);
    }
    __syncthreads();
    int n = tid & 63;
    int kq = tid >> 6;
    float4 acc[8];
#pragma unroll
    for (int q = 0; q < 8; q++) acc[q] = make_float4(0.f, 0.f, 0.f, 0.f);
    for (int m = 0; m < 64; m++) {
        float s = adjT[m * 64 + n];
        const float4* trow = (const float4*)&tile[m][kq * 32];
#pragma unroll
        for (int q = 0; q < 8; q++) {
            float4 t4 = trow[q];
            acc[q].x += s * t4.x; acc[q].y += s * t4.y;
            acc[q].z += s * t4.z; acc[q].w += s * t4.w;
        }
    }
    size_t off4 = ((size_t)(n * 64 + d) * Hdim + kt * 128 + kq * 32) >> 2;
#pragma unroll
    for (int q = 0; q < 8; q++) {
        uint2 h, l; cvt4(acc[q], h, l);
        ((uint2*)g_W2h)[off4 + q] = h;
        ((uint2*)g_W2l)[off4 + q] = l;
    }
}

// ================= split-fp16 HMMA GEMM (persistent tiles; act==2 dual output) =================
#define TSTRIDE 40
#define ROWB (TSTRIDE * 2)
#define TILE_B (128 * ROWB)
#define STAGE_B (4 * TILE_B)
#define GSMEM_TOTAL (2 * STAGE_B)

template <int NI, int PASSES>
__global__ void __launch_bounds__(256, 2) gemm_mma(
    const __half* __restrict__ Ahi, const __half* __restrict__ Alo,
    const __half* __restrict__ Bhi, const __half* __restrict__ Blo,
    const float* __restrict__ bias, float* __restrict__ C, float* __restrict__ C2,
    int K, int lda, int Nstore, int act, int atomicOut,
    int tilesX, int tilesTotal) {
    extern __shared__ char smem[];
    const int tid = threadIdx.x;
    const int wid = tid >> 5;
    const int lane = tid & 31;
    const int grp = lane >> 2;
    const int qp = lane & 3;
    const int wm = (wid >> 2) * 64;
    const int wn = (wid & 3) * (NI * 8);
    const int kbase = blockIdx.z * K;
    const uint32_t sb = smem_u32(smem);

    const int row = tid >> 2;
    const int c16 = tid & 3;

    const int aRowL = wm + (lane & 7) + ((lane >> 3) & 1) * 8;
    const int aKL = (lane >> 4) * 8;
    const int bRowL = wn + (lane & 7) + (lane >> 4) * 8;
    const int bKL = ((lane >> 3) & 1) * 8;

    const int nc = K >> 5;

    for (int t = blockIdx.x; t < tilesTotal; t += gridDim.x) {
        const int bm = (t / tilesX) * 128;
        const int bn = (t % tilesX) * 128;
        __syncthreads();

        float acc[4][NI][4];
#pragma unroll
        for (int mi = 0; mi < 4; mi++)
#pragma unroll
            for (int ni = 0; ni < NI; ni++)
#pragma unroll
                for (int j = 0; j < 4; j++) acc[mi][ni][j] = 0.f;

        auto issue = [&](int c, int s) {
            const uint32_t ss = sb + s * STAGE_B;
            const int k0 = c << 5;
#pragma unroll
            for (int tt = 0; tt < 2; tt++) {
                const int r = row + tt * 64;
                const uint32_t so = (uint32_t)r * ROWB + c16 * 16;
                const size_t gAoff = ((size_t)(bm + r) * lda + kbase + k0) * 2 + c16 * 16;
                const size_t gBoff = ((size_t)(bn + r) * lda + kbase + k0) * 2 + c16 * 16;
                cp16(ss + 0 * TILE_B + so, (const char*)Ahi + gAoff);
                if (PASSES == 3) cp16(ss + 1 * TILE_B + so, (const char*)Alo + gAoff);
                cp16(ss + 2 * TILE_B + so, (const char*)Bhi + gBoff);
                if (PASSES >= 2) cp16(ss + 3 * TILE_B + so, (const char*)Blo + gBoff);
            }
        };

        issue(0, 0); CP_COMMIT();
        if (nc > 1) issue(1, 1);
        CP_COMMIT();

        for (int c = 0; c < nc; c++) {
            const int s = c & 1;
            CP_WAIT1();
            __syncthreads();
            const uint32_t st = sb + s * STAGE_B;
#pragma unroll
            for (int ks = 0; ks < 2; ks++) {
                const int k0 = ks * 16;
                uint32_t ah[4][4], al[4][4];
#pragma unroll
                for (int mi = 0; mi < 4; mi++) {
                    const uint32_t ad = st + (uint32_t)(aRowL + mi * 16) * ROWB + (k0 + aKL) * 2;
                    ldsm_x4(ah[mi][0], ah[mi][1], ah[mi][2], ah[mi][3], ad);
                    if (PASSES == 3) ldsm_x4(al[mi][0], al[mi][1], al[mi][2], al[mi][3], ad + TILE_B);
                }
                uint32_t bh[NI][2], bl[NI][2];
#pragma unroll
                for (int p = 0; p < NI / 2; p++) {
                    const uint32_t bd = st + 2 * TILE_B + (uint32_t)(bRowL + p * 16) * ROWB + (k0 + bKL) * 2;
                    uint32_t r0, r1, r2, r3;
                    ldsm_x4(r0, r1, r2, r3, bd);
                    bh[2 * p][0] = r0; bh[2 * p][1] = r1; bh[2 * p + 1][0] = r2; bh[2 * p + 1][1] = r3;
                    if (PASSES >= 2) {
                        ldsm_x4(r0, r1, r2, r3, bd + TILE_B);
                        bl[2 * p][0] = r0; bl[2 * p][1] = r1; bl[2 * p + 1][0] = r2; bl[2 * p + 1][1] = r3;
                    }
                }
#pragma unroll
                for (int ni = 0; ni < NI; ni++) {
#pragma unroll
                    for (int mi = 0; mi < 4; mi++) {
                        mma16816(acc[mi][ni], ah[mi], bh[ni][0], bh[ni][1]);
                        if (PASSES >= 2) mma16816(acc[mi][ni], ah[mi], bl[ni][0], bl[ni][1]);
                        if (PASSES == 3) mma16816(acc[mi][ni], al[mi], bh[ni][0], bh[ni][1]);
                    }
                }
            }
            __syncthreads();
            if (c + 2 < nc) issue(c + 2, s);
            CP_COMMIT();
        }

        // epilogue
#pragma unroll
        for (int mi = 0; mi < 4; mi++) {
#pragma unroll
            for (int ni = 0; ni < NI; ni++) {
                const int r0 = bm + wm + mi * 16 + grp;
                const int col = bn + wn + ni * 8 + qp * 2;
                float* a4 = acc[mi][ni];
                if (atomicOut) {
                    if (col < Nstore) {
                        atomicAdd(&C[(size_t)r0 * Nstore + col], a4[0]);
                        atomicAdd(&C[(size_t)(r0 + 8) * Nstore + col], a4[2]);
                        if (col + 1 < Nstore) {
                            atomicAdd(&C[(size_t)r0 * Nstore + col + 1], a4[1]);
                            atomicAdd(&C[(size_t)(r0 + 8) * Nstore + col + 1], a4[3]);
                        }
                    }
                } else if (act == 2) {
                    // dual head: cols [0,1024) -> logits (Nstore=1000), [1024,2048) -> relu s1
                    float bb0 = bias[col], bb1 = bias[col + 1];
                    if (col < 1024) {
                        if (col < 1000) {   // col even, col+1 <= 999
                            float2 v0 = make_float2(a4[0] + bb0, a4[1] + bb1);
                            float2 v1 = make_float2(a4[2] + bb0, a4[3] + bb1);
                            *(float2*)(C + (size_t)r0 * 1000 + col) = v0;
                            *(float2*)(C + (size_t)(r0 + 8) * 1000 + col) = v1;
                        }
                    } else {
                        int c2 = col - 1024;
                        float2 v0 = make_float2(fmaxf(a4[0] + bb0, 0.f), fmaxf(a4[1] + bb1, 0.f));
                        float2 v1 = make_float2(fmaxf(a4[2] + bb0, 0.f), fmaxf(a4[3] + bb1, 0.f));
                        *(float2*)(C2 + (size_t)r0 * 1024 + c2) = v0;
                        *(float2*)(C2 + (size_t)(r0 + 8) * 1024 + c2) = v1;
                    }
                } else if (col + 1 < Nstore) {
                    float2 v0, v1;
                    float bb0 = bias ? bias[col] : 0.f;
                    float bb1 = bias ? bias[col + 1] : 0.f;
                    v0.x = a4[0] + bb0; v0.y = a4[1] + bb1;
                    v1.x = a4[2] + bb0; v1.y = a4[3] + bb1;
                    if (act == 1) {
                        v0.x = fmaxf(v0.x, 0.f); v0.y = fmaxf(v0.y, 0.f);
                        v1.x = fmaxf(v1.x, 0.f); v1.y = fmaxf(v1.y, 0.f);
                    }
                    *(float2*)(C + (size_t)r0 * Nstore + col) = v0;
                    *(float2*)(C + (size_t)(r0 + 8) * Nstore + col) = v1;
                } else if (col < Nstore) {
                    float bb0 = bias ? bias[col] : 0.f;
                    float v0 = a4[0] + bb0, v1 = a4[2] + bb0;
                    if (act == 1) { v0 = fmaxf(v0, 0.f); v1 = fmaxf(v1, 0.f); }
                    C[(size_t)r0 * Nstore + col] = v0;
                    C[(size_t)(r0 + 8) * Nstore + col] = v1;
                }
            }
        }
    }
}

// ================= LayerNorm(H=1024) + GELU -> fp16 hi/lo =================
__global__ void __launch_bounds__(256) ln_gelu_kernel(const float* __restrict__ h,
                                                      const float* __restrict__ g,
                                                      const float* __restrict__ beta,
                                                      uint2* __restrict__ hi,
                                                      uint2* __restrict__ lo) {
    int row = blockIdx.x;
    const float* hr = h + (size_t)row * Hdim;
    int tid = threadIdx.x;
    float4 v = *(const float4*)(hr + tid * 4);
    float s = v.x + v.y + v.z + v.w;
    float ss = v.x * v.x + v.y * v.y + v.z * v.z + v.w * v.w;
    __shared__ float rs[8], rss[8];
    for (int o = 16; o > 0; o >>= 1) {
        s += __shfl_down_sync(0xffffffffu, s, o);
        ss += __shfl_down_sync(0xffffffffu, ss, o);
    }
    if ((tid & 31) == 0) { rs[tid >> 5] = s; rss[tid >> 5] = ss; }
    __syncthreads();
    if (tid < 32) {
        float a = tid < 8 ? rs[tid] : 0.f;
        float b = tid < 8 ? rss[tid] : 0.f;
        for (int o = 4; o > 0; o >>= 1) {
            a += __shfl_down_sync(0xffffffffu, a, o);
            b += __shfl_down_sync(0xffffffffu, b, o);
        }
        if (tid == 0) { rs[0] = a; rss[0] = b; }
    }
    __syncthreads();
    float mu = rs[0] * (1.f / Hdim);
    float var = rss[0] * (1.f / Hdim) - mu * mu;
    float inv = rsqrtf(var + 1e-5f);
    float4 gg = *(const float4*)(g + tid * 4);
    float4 bb = *(const float4*)(beta + tid * 4);
    float y;
    y = (v.x - mu) * inv * gg.x + bb.x; v.x = 0.5f * y * (1.f + erff(y * 0.70710678118654752f));
    y = (v.y - mu) * inv * gg.y + bb.y; v.y = 0.5f * y * (1.f + erff(y * 0.70710678118654752f));
    y = (v.z - mu) * inv * gg.z + bb.z; v.z = 0.5f * y * (1.f + erff(y * 0.70710678118654752f));
    y = (v.w - mu) * inv * gg.w + bb.w; v.w = 0.5f * y * (1.f + erff(y * 0.70710678118654752f));
    uint2 hh, ll; cvt4(v, hh, ll);
    hi[(size_t)row * 256 + tid] = hh;
    lo[(size_t)row * 256 + tid] = ll;
}

// ================= fused cell kernel (packed f32x2 FMA) =================
#define CELL_SMEM ((64 * 68 * 2 + 4096 * 4 + 7 * 64) * sizeof(float))
__global__ void __launch_bounds__(256) cell_kernel(const float* __restrict__ Wi,
                                                   const float* __restrict__ Wf,
                                                   const float* __restrict__ Wo,
                                                   const float* __restrict__ bi_g,
                                                   const float* __restrict__ bslow_g,
                                                   const float* __restrict__ bo_g,
                                                   const float* __restrict__ hprev_g,
                                                   const float* __restrict__ gln_g,
                                                   const float* __restrict__ bln_g,
                                                   float* __restrict__ xflat_out,
                                                   uint32_t* __restrict__ xfh,
                                                   uint32_t* __restrict__ xfl) {
    extern __shared__ float sf[];
    float* xs = sf;
    float* wi = xs + 64 * 68;
    float* wf = wi + 4096;
    float* wc = wf + 4096;
    float* wo = wc + 4096;
    float* hr = wo + 4096;
    float* vecs = hr + 64 * 68;

    int n = blockIdx.x;
    int b0 = blockIdx.y * 64;
    int tid = threadIdx.x;

#pragma unroll
    for (int j = 0; j < 4; j++) {
        int idx = tid + j * 256;
        int row = idx >> 4, c4 = (idx & 15) << 2;
        *(float4*)(xs + row * 68 + c4) =
            *(const float4*)(g_xagg + (((size_t)(b0 + row) * 64 + n) << 6) + c4);
        ((float4*)wi)[idx] = ((const float4*)(Wi + (size_t)n * 4096))[idx];
        ((float4*)wf)[idx] = ((const float4*)(Wf + (size_t)n * 8192))[idx];
        ((float4*)wc)[idx] = ((const float4*)(g_WcT + (size_t)n * 4096))[idx];
        ((float4*)wo)[idx] = ((const float4*)(Wo + (size_t)n * 4096))[idx];
    }
    if (tid < 64) {
        vecs[0 * 64 + tid] = bi_g[n * 64 + tid];
        vecs[1 * 64 + tid] = g_cf[n * 64 + tid];
        vecs[2 * 64 + tid] = bslow_g[n * 64 + tid];
        vecs[3 * 64 + tid] = bo_g[n * 64 + tid];
        vecs[4 * 64 + tid] = hprev_g[n * 64 + tid];
        vecs[5 * 64 + tid] = gln_g[n * 64 + tid];
        vecs[6 * 64 + tid] = bln_g[n * 64 + tid];
    }
    __syncthreads();

    const int r0 = (tid >> 4) * 4;
    const int c0 = (tid & 15) * 4;

    unsigned long long ai2[4][2], af2[4][2], ac2[4][2];
#pragma unroll
    for (int r = 0; r < 4; r++)
#pragma unroll
        for (int p = 0; p < 2; p++) { ai2[r][p] = 0ull; af2[r][p] = 0ull; ac2[r][p] = 0ull; }

    for (int i = 0; i < 64; i++) {
        unsigned long long xp[4];
#pragma unroll
        for (int r = 0; r < 4; r++) {
            float xv = xs[(r0 + r) * 68 + i];
            PACKF2(xp[r], xv, xv);
        }
        float4 w1 = *(const float4*)(wi + i * 64 + c0);
        float4 w2 = *(const float4*)(wf + i * 64 + c0);
        float4 w3 = *(const float4*)(wc + i * 64 + c0);
        unsigned long long w1p[2], w2p[2], w3p[2];
        PACKF2(w1p[0], w1.x, w1.y); PACKF2(w1p[1], w1.z, w1.w);
        PACKF2(w2p[0], w2.x, w2.y); PACKF2(w2p[1], w2.z, w2.w);
        PACKF2(w3p[0], w3.x, w3.y); PACKF2(w3p[1], w3.z, w3.w);
#pragma unroll
        for (int r = 0; r < 4; r++) {
            FMA_F32X2(ai2[r][0], xp[r], w1p[0]); FMA_F32X2(ai2[r][1], xp[r], w1p[1]);
            FMA_F32X2(af2[r][0], xp[r], w2p[0]); FMA_F32X2(af2[r][1], xp[r], w2p[1]);
            FMA_F32X2(ac2[r][0], xp[r], w3p[0]); FMA_F32X2(ac2[r][1], xp[r], w3p[1]);
        }
    }
#pragma unroll
    for (int r = 0; r < 4; r++)
#pragma unroll
        for (int p = 0; p < 2; p++) {
            float aiv0, aiv1, afv0, afv1, acv0, acv1;
            UNPACKF2(aiv0, aiv1, ai2[r][p]);
            UNPACKF2(afv0, afv1, af2[r][p]);
            UNPACKF2(acv0, acv1, ac2[r][p]);
            int o = c0 + 2 * p;
            float it0 = sigmoidf_(aiv0 + vecs[0 * 64 + o]);
            float ft0 = sigmoidf_(afv0 + vecs[1 * 64 + o]);
            float hs0 = acv0 + vecs[2 * 64 + o];
            hr[(r0 + r) * 68 + o] = it0 * hs0 + ft0 * vecs[4 * 64 + o];
            float it1 = sigmoidf_(aiv1 + vecs[0 * 64 + o + 1]);
            float ft1 = sigmoidf_(afv1 + vecs[1 * 64 + o + 1]);
            float hs1 = acv1 + vecs[2 * 64 + o + 1];
            hr[(r0 + r) * 68 + o + 1] = it1 * hs1 + ft1 * vecs[4 * 64 + o + 1];
        }
    __syncthreads();

    unsigned long long ao2[4][2];
#pragma unroll
    for (int r = 0; r < 4; r++)
#pragma unroll
        for (int p = 0; p < 2; p++) ao2[r][p] = 0ull;
    for (int i = 0; i < 64; i++) {
        unsigned long long xp[4];
#pragma unroll
        for (int r = 0; r < 4; r++) {
            float xv = hr[(r0 + r) * 68 + i];
            PACKF2(xp[r], xv, xv);
        }
        float4 w = *(const float4*)(wo + i * 64 + c0);
        unsigned long long wp[2];
        PACKF2(wp[0], w.x, w.y); PACKF2(wp[1], w.z, w.w);
#pragma unroll
        for (int r = 0; r < 4; r++) {
            FMA_F32X2(ao2[r][0], xp[r], wp[0]);
            FMA_F32X2(ao2[r][1], xp[r], wp[1]);
        }
    }
    float* ys = xs;
#pragma unroll
    for (int r = 0; r < 4; r++)
#pragma unroll
        for (int p = 0; p < 2; p++) {
            float a0, a1;
            UNPACKF2(a0, a1, ao2[r][p]);
            int o = c0 + 2 * p;
            float ot0 = sigmoidf_(a0 + vecs[3 * 64 + o]);
            float ot1 = sigmoidf_(a1 + vecs[3 * 64 + o + 1]);
            ys[(r0 + r) * 68 + o] = ot0 * tanhf(hr[(r0 + r) * 68 + o]);
            ys[(r0 + r) * 68 + o + 1] = ot1 * tanhf(hr[(r0 + r) * 68 + o + 1]);
        }
    __syncthreads();

    int w = tid >> 5, lane = tid & 31;
    for (int rr = 0; rr < 8; rr++) {
        int row = w * 8 + rr;
        float v0 = ys[row * 68 + 2 * lane];
        float v1 = ys[row * 68 + 2 * lane + 1];
        float s = v0 + v1;
        float ss = v0 * v0 + v1 * v1;
        for (int o = 16; o > 0; o >>= 1) {
            s += __shfl_xor_sync(0xffffffffu, s, o);
            ss += __shfl_xor_sync(0xffffffffu, ss, o);
        }
        float mu = s * (1.f / 64.f);
        float var = ss * (1.f / 64.f) - mu * mu;
        float inv = rsqrtf(var + 1e-5f);
        float y0 = (v0 - mu) * inv * vecs[5 * 64 + 2 * lane] + vecs[6 * 64 + 2 * lane];
        float y1 = (v1 - mu) * inv * vecs[5 * 64 + 2 * lane + 1] + vecs[6 * 64 + 2 * lane + 1];
        size_t base = (size_t)(b0 + row) * 4096 + n * 64;
        *(float2*)(xflat_out + base + 2 * lane) = make_float2(y0, y1);
        uint32_t hh, ll; cvt2(y0, y1, hh, ll);
        xfh[(base >> 1) + lane] = hh;
        xfl[(base >> 1) + lane] = ll;
    }
}

// ================= top-5 retrieval + update + fp16 re-emit =================
__global__ void __launch_bounds__(256) retrieve_kernel(const float* __restrict__ mem,
                                                       float* __restrict__ xflat,
                                                       uint2* __restrict__ xfh,
                                                       uint2* __restrict__ xfl) {
    int b = blockIdx.x;
    __shared__ float s[64];
    __shared__ int top[5];
    int tid = threadIdx.x;
    if (tid < 64) s[tid] = g_sim[b * 64 + tid];
    __syncthreads();
    if (tid < 32) {
        for (int k = 0; k < 5; k++) {
            float v = s[tid]; int idx = tid;
            float v2 = s[tid + 32];
            if (v2 > v) { v = v2; idx = tid + 32; }
            for (int o = 16; o > 0; o >>= 1) {
                float ov = __shfl_down_sync(0xffffffffu, v, o);
                int oi = __shfl_down_sync(0xffffffffu, idx, o);
                if (ov > v || (ov == v && oi < idx)) { v = ov; idx = oi; }
            }
            idx = __shfl_sync(0xffffffffu, idx, 0);
            if (tid == 0) top[k] = idx;
            if (tid == 0) s[idx] = -INFINITY;
            __syncwarp();
        }
    }
    __syncthreads();
    const float4* m4 = (const float4*)mem;
    float4* x4 = (float4*)(xflat + (size_t)b * 4096);
    int t0 = top[0] * 1024, t1 = top[1] * 1024, t2 = top[2] * 1024, t3 = top[3] * 1024, t4 = top[4] * 1024;
#pragma unroll
    for (int j = 0; j < 4; j++) {
        int idx = tid + j * 256;
        float4 xv = x4[idx];
        float4 a = m4[t0 + idx], bb = m4[t1 + idx], c = m4[t2 + idx], d = m4[t3 + idx], e = m4[t4 + idx];
        xv.x += 0.02f * (a.x + bb.x + c.x + d.x + e.x);
        xv.y += 0.02f * (a.y + bb.y + c.y + d.y + e.y);
        xv.z += 0.02f * (a.z + bb.z + c.z + d.z + e.z);
        xv.w += 0.02f * (a.w + bb.w + c.w + d.w + e.w);
        x4[idx] = xv;
        uint2 h, l; cvt4(xv, h, l);
        xfh[(size_t)b * 1024 + idx] = h;
        xfl[(size_t)b * 1024 + idx] = l;
    }
}

// ================= proj2 =================
__global__ void __launch_bounds__(256) proj2_kernel(const float* __restrict__ s1,
                                                    const float* __restrict__ Ws2,
                                                    const float* __restrict__ bs2,
                                                    float* __restrict__ proj) {
    __shared__ float w2s[8 * 1024];
    __shared__ float bss[8];
    int tid = threadIdx.x;
    for (int i = tid; i < 8192; i += 256) w2s[i] = Ws2[i];
    if (tid < 8) bss[tid] = bs2[tid];
    __syncthreads();
    int w = tid >> 5, lane = tid & 31;
    int b = blockIdx.x * 8 + w;
    const float4* row = (const float4*)(s1 + (size_t)b * 1024);
    float4 xv[8];
#pragma unroll
    for (int j = 0; j < 8; j++) xv[j] = row[lane + j * 32];
#pragma unroll
    for (int p = 0; p < 8; p++) {
        const float4* wr = (const float4*)(w2s + p * 1024);
        float acc = 0.f;
#pragma unroll
        for (int j = 0; j < 8; j++) {
            float4 wv = wr[lane + j * 32];
            acc += xv[j].x * wv.x + xv[j].y * wv.y + xv[j].z * wv.z + xv[j].w * wv.w;
        }
        for (int o = 16; o > 0; o >>= 1) acc += __shfl_xor_sync(0xffffffffu, acc, o);
        if (lane == 0) proj[(size_t)b * 8 + p] = acc + bss[p];
    }
}

// ================= launch =================
extern "C" void kernel_launch(void* const* d_in, const int* in_sizes, int n_in,
                              void* d_out, int out_size) {
    const float* x      = (const float*)d_in[0];
    const float* W1     = (const float*)d_in[1];
    const float* b1     = (const float*)d_in[2];
    const float* g1     = (const float*)d_in[3];
    const float* beta1  = (const float*)d_in[4];
    const float* W2     = (const float*)d_in[5];
    const float* b2     = (const float*)d_in[6];
    const float* edge_w = (const float*)d_in[7];
    const float* mask   = (const float*)d_in[8];
    const float* Wi     = (const float*)d_in[9];
    const float* bi     = (const float*)d_in[10];
    const float* Wf     = (const float*)d_in[11];
    const float* bf     = (const float*)d_in[12];
    const float* Wslow  = (const float*)d_in[13];
    const float* bslow  = (const float*)d_in[14];
    const float* u      = (const float*)d_in[15];
    const float* Wfast  = (const float*)d_in[16];
    const float* Wo     = (const float*)d_in[17];
    const float* bo     = (const float*)d_in[18];
    const float* gln    = (const float*)d_in[19];
    const float* bln    = (const float*)d_in[20];
    const float* h_prev = (const float*)d_in[21];
    const float* memory = (const float*)d_in[22];
    const float* Wh     = (const float*)d_in[23];
    const float* bh     = (const float*)d_in[24];
    const float* Ws1    = (const float*)d_in[25];
    const float* bs1    = (const float*)d_in[26];
    const float* Ws2    = (const float*)d_in[27];
    const float* bs2    = (const float*)d_in[28];

    float* out    = (float*)d_out;
    float* logits = out;
    float* proj   = out + (size_t)Bn * Ccls;
    float* xflat  = proj + (size_t)Bn * Pp;

    float *p_h1, *p_b2a, *p_xagg, *p_sim, *p_s1, *p_bcat;
    cudaGetSymbolAddress((void**)&p_h1, g_h1);
    cudaGetSymbolAddress((void**)&p_b2a, g_b2a);
    cudaGetSymbolAddress((void**)&p_xagg, g_xagg);
    cudaGetSymbolAddress((void**)&p_sim, g_sim);
    cudaGetSymbolAddress((void**)&p_s1, g_s1);
    cudaGetSymbolAddress((void**)&p_bcat, g_bcat);
    void *p_xh, *p_xl, *p_W1h, *p_W1l, *p_h1h, *p_h1l, *p_W2h, *p_W2l;
    void *p_xfh, *p_xfl, *p_Wcath, *p_memh, *p_meml;
    cudaGetSymbolAddress(&p_xh, g_xh);   cudaGetSymbolAddress(&p_xl, g_xl);
    cudaGetSymbolAddress(&p_W1h, g_W1h); cudaGetSymbolAddress(&p_W1l, g_W1l);
    cudaGetSymbolAddress(&p_h1h, g_h1h); cudaGetSymbolAddress(&p_h1l, g_h1l);
    cudaGetSymbolAddress(&p_W2h, g_W2h); cudaGetSymbolAddress(&p_W2l, g_W2l);
    cudaGetSymbolAddress(&p_xfh, g_xfh); cudaGetSymbolAddress(&p_xfl, g_xfl);
    cudaGetSymbolAddress(&p_Wcath, g_Wcath);
    cudaGetSymbolAddress(&p_memh, g_memh); cudaGetSymbolAddress(&p_meml, g_meml);

    int nsm = 148;
    cudaDeviceGetAttribute(&nsm, cudaDevAttrMultiProcessorCount, 0);
    int persist = 2 * nsm;
    if (persist > 1024) persist = 1024;

    cudaFuncSetAttribute(cell_kernel, cudaFuncAttributeMaxDynamicSharedMemorySize, CELL_SMEM);
    cudaFuncSetAttribute(gemm_mma<4, 3>, cudaFuncAttributeMaxDynamicSharedMemorySize, GSMEM_TOTAL);
    cudaFuncSetAttribute(gemm_mma<4, 2>, cudaFuncAttributeMaxDynamicSharedMemorySize, GSMEM_TOTAL);
    cudaFuncSetAttribute(gemm_mma<4, 1>, cudaFuncAttributeMaxDynamicSharedMemorySize, GSMEM_TOTAL);
    cudaFuncSetAttribute(gemm_mma<2, 3>, cudaFuncAttributeMaxDynamicSharedMemorySize, GSMEM_TOTAL);

    // fused prep
    misc_prep<<<MISC_BLOCKS, 256>>>(x, W1, Ws1, memory, Wh, bh, bs1, b2, edge_w, mask,
                                    Wslow, u, Wfast, Wf, bf, h_prev);
    fold_w2<<<dim3(8, 64), 256>>>(W2, edge_w, mask);

    // stage 1: input projection (3-pass); G2 -> x_agg (2-pass, persistent tiles)
    gemm_mma<4, 3><<<256, 256, GSMEM_TOTAL>>>(
        (const __half*)p_xh, (const __half*)p_xl,
        (const __half*)p_W1h, (const __half*)p_W1l, b1, p_h1, nullptr,
        Fdim, Fdim, Hdim, 0, 0, Hdim / 128, (Hdim / 128) * (Bn / 128));
    ln_gelu_kernel<<<Bn, 256>>>(p_h1, g1, beta1, (uint2*)p_h1h, (uint2*)p_h1l);
    gemm_mma<4, 2><<<persist, 256, GSMEM_TOTAL>>>(
        (const __half*)p_h1h, nullptr,
        (const __half*)p_W2h, (const __half*)p_W2l, p_b2a, p_xagg, nullptr,
        Hdim, Hdim, FLAT, 0, 0, FLAT / 128, (FLAT / 128) * (Bn / 128));

    // stage 2: cells
    cell_kernel<<<dim3(Nn, Bn / 64), 256, CELL_SMEM>>>(Wi, Wf, Wo, bi, bslow, bo,
                                                       h_prev, gln, bln, xflat,
                                                       (uint32_t*)p_xfh, (uint32_t*)p_xfl);

    // stage 3: retrieval (split-K=8 sim GEMM -> 256 CTAs, atomic accumulate)
    gemm_mma<2, 3><<<dim3(Bn / 128, 1, 8), 256, GSMEM_TOTAL>>>(
        (const __half*)p_xfh, (const __half*)p_xfl,
        (const __half*)p_memh, (const __half*)p_meml, nullptr, p_sim, nullptr,
        FLAT / 8, FLAT, CAP, 0, 1, 1, Bn / 128);
    retrieve_kernel<<<Bn, 256>>>(memory, xflat, (uint2*)p_xfh, (uint2*)p_xfl);

    // stage 4: fused dual head (logits + relu->s1), 1-pass fp16
    gemm_mma<4, 1><<<512, 256, GSMEM_TOTAL>>>(
        (const __half*)p_xfh, nullptr,
        (const __half*)p_Wcath, nullptr, p_bcat, logits, p_s1,
        FLAT, FLAT, 1000, 2, 0, 2048 / 128, (2048 / 128) * (Bn / 128));
    proj2_kernel<<<Bn / 8, 256>>>(p_s1, Ws2, bs2, proj);
}